// round 3
// baseline (speedup 1.0000x reference)
#include <cuda_runtime.h>
#include <cuda_bf16.h>
#include <math.h>

// ---------------- problem constants ----------------
#define BB 4
#define TT 2048
#define DIM 1024
#define HH 16
#define NOPE 128
#define ROPE 64
#define VDIM 128
#define KVR 512
#define QKD 192            // NOPE + ROPE
#define MTOT (BB*TT)       // 8192
#define SCALE_F (0.07216878364870323f)  // 192^-0.5

// ---------------- scratch (device globals, zero-init bss) ----------------
__device__ __align__(16) float g_Q  [(size_t)MTOT * HH * QKD];   // [b,t,h,192] (rope+scale applied)
__device__ __align__(16) float g_KVA[(size_t)MTOT * (KVR+ROPE)]; // [bt,576]
__device__ __align__(16) float g_KVN[(size_t)MTOT * KVR];        // rms-normed latent
__device__ __align__(16) float g_KR [(size_t)MTOT * ROPE];       // k_rope [bt,64]
__device__ __align__(16) float g_KV [(size_t)MTOT * HH * (NOPE+VDIM)]; // [b,t,h,256]
__device__ __align__(16) float g_ATT[(size_t)MTOT * HH * VDIM];  // [b,t,h*128]

// ---------------- SGEMM: C[M,N] = A[M,K] @ B[N,K]^T + bias[N] ----------------
// BM=BN=128, BK=16, 256 threads, 8x8 per thread. M%128==0, K%16==0 assumed; N guarded.
__global__ __launch_bounds__(256) void gemm_nt_bias(
    const float* __restrict__ A, const float* __restrict__ Bw,
    const float* __restrict__ bias, float* __restrict__ C,
    int M, int N, int K)
{
    __shared__ float As[16][128];
    __shared__ float Bs[16][128];
    const int tid  = threadIdx.x;
    const int brow = blockIdx.y * 128;
    const int bcol = blockIdx.x * 128;
    const int trow = (tid >> 4) << 3;   // 0..120
    const int tcol = (tid & 15) << 3;   // 0..120
    const int lr = tid >> 2;            // 0..63
    const int lk = (tid & 3) << 2;      // 0,4,8,12

    float acc[8][8];
#pragma unroll
    for (int i = 0; i < 8; i++)
#pragma unroll
        for (int j = 0; j < 8; j++) acc[i][j] = 0.f;

    const int c0 = bcol + lr;
    const int c1 = bcol + lr + 64;

    for (int k0 = 0; k0 < K; k0 += 16) {
        float4 a0 = *(const float4*)(A + (size_t)(brow + lr)      * K + k0 + lk);
        float4 a1 = *(const float4*)(A + (size_t)(brow + lr + 64) * K + k0 + lk);
        float4 b0 = make_float4(0.f,0.f,0.f,0.f);
        float4 b1 = make_float4(0.f,0.f,0.f,0.f);
        if (c0 < N) b0 = *(const float4*)(Bw + (size_t)c0 * K + k0 + lk);
        if (c1 < N) b1 = *(const float4*)(Bw + (size_t)c1 * K + k0 + lk);

        As[lk+0][lr]    = a0.x; As[lk+1][lr]    = a0.y; As[lk+2][lr]    = a0.z; As[lk+3][lr]    = a0.w;
        As[lk+0][lr+64] = a1.x; As[lk+1][lr+64] = a1.y; As[lk+2][lr+64] = a1.z; As[lk+3][lr+64] = a1.w;
        Bs[lk+0][lr]    = b0.x; Bs[lk+1][lr]    = b0.y; Bs[lk+2][lr]    = b0.z; Bs[lk+3][lr]    = b0.w;
        Bs[lk+0][lr+64] = b1.x; Bs[lk+1][lr+64] = b1.y; Bs[lk+2][lr+64] = b1.z; Bs[lk+3][lr+64] = b1.w;
        __syncthreads();

#pragma unroll
        for (int kk = 0; kk < 16; kk++) {
            float ar[8], br[8];
            *(float4*)&ar[0] = *(const float4*)&As[kk][trow];
            *(float4*)&ar[4] = *(const float4*)&As[kk][trow + 4];
            *(float4*)&br[0] = *(const float4*)&Bs[kk][tcol];
            *(float4*)&br[4] = *(const float4*)&Bs[kk][tcol + 4];
#pragma unroll
            for (int i = 0; i < 8; i++)
#pragma unroll
                for (int j = 0; j < 8; j++) acc[i][j] += ar[i] * br[j];
        }
        __syncthreads();
    }

#pragma unroll
    for (int i = 0; i < 8; i++) {
        int row = brow + trow + i;
#pragma unroll
        for (int j = 0; j < 8; j++) {
            int col = bcol + tcol + j;
            if (col < N) C[(size_t)row * N + col] = acc[i][j] + bias[col];
        }
    }
}

// ---------------- q rope + scale: g_Q in place ----------------
// idx over MTOT*HH*96 "pairs": j<64 -> nope pair (scale only), j>=64 -> rope pair i=j-64
__global__ void rope_q_kernel(const float* __restrict__ cosv, const float* __restrict__ sinv)
{
    int idx = blockIdx.x * blockDim.x + threadIdx.x;
    const int total = MTOT * HH * 96;
    if (idx >= total) return;
    int j   = idx % 96;
    int bth = idx / 96;
    int bt  = bth / HH;
    int t   = bt % TT;
    float* q = g_Q + (size_t)bth * QKD;
    if (j < 64) {
        q[2*j]   *= SCALE_F;
        q[2*j+1] *= SCALE_F;
    } else {
        int i = j - 64;                 // 0..31
        float c = cosv[t*32 + i];
        float s = sinv[t*32 + i];
        float xr = q[NOPE + 2*i];
        float xi = q[NOPE + 2*i + 1];
        q[NOPE + 2*i]     = (xr*c - xi*s) * SCALE_F;
        q[NOPE + 2*i + 1] = (xr*s + xi*c) * SCALE_F;
    }
}

// ---------------- kv_a post: rms_norm(first 512) -> g_KVN, rope(last 64) -> g_KR ----------------
__global__ __launch_bounds__(128) void kva_post_kernel(const float* __restrict__ cosv,
                                                       const float* __restrict__ sinv)
{
    __shared__ float red[4];
    const int bt = blockIdx.x;
    const int t  = bt % TT;
    const float* a = g_KVA + (size_t)bt * (KVR + ROPE);
    const int tid = threadIdx.x;

    float ss = 0.f;
    for (int d = tid; d < KVR; d += 128) { float v = a[d]; ss += v * v; }
#pragma unroll
    for (int off = 16; off; off >>= 1) ss += __shfl_xor_sync(0xffffffffu, ss, off);
    if ((tid & 31) == 0) red[tid >> 5] = ss;
    __syncthreads();
    float total = red[0] + red[1] + red[2] + red[3];
    float r = rsqrtf(total * (1.0f / KVR) + 1e-6f);

    float* o = g_KVN + (size_t)bt * KVR;
    for (int d = tid; d < KVR; d += 128) o[d] = a[d] * r;

    if (tid < 32) {
        int i = tid;
        float c = cosv[t*32 + i];
        float s = sinv[t*32 + i];
        float xr = a[KVR + 2*i];
        float xi = a[KVR + 2*i + 1];
        g_KR[(size_t)bt * ROPE + 2*i]     = xr*c - xi*s;
        g_KR[(size_t)bt * ROPE + 2*i + 1] = xr*s + xi*c;
    }
}

// ---------------- flash attention (causal), 1 warp = 1 query ----------------
#define AQ 8           // queries per CTA
#define AK 64          // keys per tile
#define KSTR 193       // smem row stride for K (conflict-free lane*193+d)
#define ATT_SMEM ((AQ*QKD + AK*KSTR + AK*VDIM) * 4)

__global__ __launch_bounds__(256) void attn_kernel()
{
    extern __shared__ float sm[];
    float* qs = sm;                    // [8][192]
    float* ks = qs + AQ * QKD;         // [64][193]
    float* vs = ks + AK * KSTR;        // [64][128]

    const int b  = blockIdx.z;
    const int h  = blockIdx.y;
    const int t0 = blockIdx.x * AQ;
    const int tid  = threadIdx.x;
    const int w    = tid >> 5;
    const int lane = tid & 31;

    // stage Q tile
    for (int i = tid; i < AQ * QKD; i += 256) {
        int qi = i / QKD, d = i % QKD;
        qs[i] = g_Q[(((size_t)(b*TT + t0 + qi)) * HH + h) * QKD + d];
    }

    const int t = t0 + w;              // this warp's query position
    float m = -1e30f, l = 0.f;
    float o0 = 0.f, o1 = 0.f, o2 = 0.f, o3 = 0.f;

    const int nblocks = t0 / AK + 1;   // causal: key tiles covering [0, t0+7]
    for (int kb = 0; kb < nblocks; kb++) {
        const int sbase = kb * AK;
        __syncthreads();
        // stage K (nope ++ rope) and V
        for (int i = tid; i < AK * QKD; i += 256) {
            int j = i / QKD, d = i % QKD;
            size_t srow = (size_t)(b*TT + sbase + j);
            float v;
            if (d < NOPE) v = g_KV[(srow * HH + h) * (NOPE + VDIM) + d];
            else          v = g_KR[srow * ROPE + (d - NOPE)];
            ks[j * KSTR + d] = v;
        }
        for (int i = tid; i < AK * VDIM; i += 256) {
            int j = i / VDIM, d = i % VDIM;
            vs[i] = g_KV[((size_t)(b*TT + sbase + j) * HH + h) * (NOPE + VDIM) + NOPE + d];
        }
        __syncthreads();

        // scores for keys sbase+lane and sbase+32+lane
        float sA = 0.f, sB = 0.f;
        const float* qrow = qs + w * QKD;
        const float* kA = ks + lane * KSTR;
        const float* kB = ks + (lane + 32) * KSTR;
#pragma unroll 8
        for (int d = 0; d < QKD; d++) {
            float qd = qrow[d];
            sA += qd * kA[d];
            sB += qd * kB[d];
        }
        if (sbase + lane      > t) sA = -1e30f;
        if (sbase + 32 + lane > t) sB = -1e30f;

        // online softmax update
        float bm = fmaxf(sA, sB);
#pragma unroll
        for (int off = 16; off; off >>= 1) bm = fmaxf(bm, __shfl_xor_sync(0xffffffffu, bm, off));
        float mn   = fmaxf(m, bm);
        float corr = __expf(m - mn);
        float pA = __expf(sA - mn);
        float pB = __expf(sB - mn);
        float ps = pA + pB;
#pragma unroll
        for (int off = 16; off; off >>= 1) ps += __shfl_xor_sync(0xffffffffu, ps, off);
        l = l * corr + ps;
        o0 *= corr; o1 *= corr; o2 *= corr; o3 *= corr;
        m = mn;

        // accumulate O += P @ V  (broadcast p across warp)
#pragma unroll 8
        for (int j = 0; j < 32; j++) {
            float pj = __shfl_sync(0xffffffffu, pA, j);
            const float* vr = vs + j * VDIM;
            o0 += pj * vr[lane];
            o1 += pj * vr[lane + 32];
            o2 += pj * vr[lane + 64];
            o3 += pj * vr[lane + 96];
        }
#pragma unroll 8
        for (int j = 0; j < 32; j++) {
            float pj = __shfl_sync(0xffffffffu, pB, j);
            const float* vr = vs + (j + 32) * VDIM;
            o0 += pj * vr[lane];
            o1 += pj * vr[lane + 32];
            o2 += pj * vr[lane + 64];
            o3 += pj * vr[lane + 96];
        }
    }

    float inv = 1.f / l;
    float* op = g_ATT + (((size_t)(b*TT + t)) * HH + h) * VDIM;
    op[lane]      = o0 * inv;
    op[lane + 32] = o1 * inv;
    op[lane + 64] = o2 * inv;
    op[lane + 96] = o3 * inv;
}

// ---------------- launch ----------------
extern "C" void kernel_launch(void* const* d_in, const int* in_sizes, int n_in,
                              void* d_out, int out_size)
{
    const float* x       = (const float*)d_in[0];
    const float* wq_w    = (const float*)d_in[1];
    const float* wq_b    = (const float*)d_in[2];
    const float* wkv_a_w = (const float*)d_in[3];
    const float* wkv_a_b = (const float*)d_in[4];
    const float* wkv_b_w = (const float*)d_in[5];
    const float* wkv_b_b = (const float*)d_in[6];
    const float* wo_w    = (const float*)d_in[7];
    const float* wo_b    = (const float*)d_in[8];
    const float* cosv    = (const float*)d_in[9];
    const float* sinv    = (const float*)d_in[10];
    float* out = (float*)d_out;

    float *Qp, *KVAp, *KVNp, *KVp, *ATTp;
    cudaGetSymbolAddress((void**)&Qp,   g_Q);
    cudaGetSymbolAddress((void**)&KVAp, g_KVA);
    cudaGetSymbolAddress((void**)&KVNp, g_KVN);
    cudaGetSymbolAddress((void**)&KVp,  g_KV);
    cudaGetSymbolAddress((void**)&ATTp, g_ATT);

    // 1) q = x @ wq^T + b      [8192, 3072]
    gemm_nt_bias<<<dim3(3072/128, MTOT/128), 256>>>(x, wq_w, wq_b, Qp, MTOT, HH*QKD, DIM);
    // 2) rope + scale on q
    {
        int total = MTOT * HH * 96;
        rope_q_kernel<<<(total + 255) / 256, 256>>>(cosv, sinv);
    }
    // 3) kv_a = x @ wkv_a^T + b   [8192, 576]
    gemm_nt_bias<<<dim3((KVR+ROPE+127)/128, MTOT/128), 256>>>(x, wkv_a_w, wkv_a_b, KVAp, MTOT, KVR+ROPE, DIM);
    // 4) rms norm + k rope
    kva_post_kernel<<<MTOT, 128>>>(cosv, sinv);
    // 5) kv = norm @ wkv_b^T + b  [8192, 4096]
    gemm_nt_bias<<<dim3(HH*(NOPE+VDIM)/128, MTOT/128), 256>>>(KVNp, wkv_b_w, wkv_b_b, KVp, MTOT, HH*(NOPE+VDIM), KVR);
    // 6) attention
    cudaFuncSetAttribute(attn_kernel, cudaFuncAttributeMaxDynamicSharedMemorySize, ATT_SMEM);
    attn_kernel<<<dim3(TT/AQ, HH, BB), 256, ATT_SMEM>>>();
    // 7) out = att @ wo^T + b     [8192, 1024]
    gemm_nt_bias<<<dim3(DIM/128, MTOT/128), 256>>>(ATTp, wo_w, wo_b, out, MTOT, DIM, HH*VDIM);
}

// round 4
// speedup vs baseline: 1.1336x; 1.1336x over previous
#include <cuda_runtime.h>
#include <cuda_bf16.h>
#include <math.h>
#include <stdint.h>

// ---------------- problem constants ----------------
#define BB 4
#define TT 2048
#define DIM 1024
#define HH 16
#define NOPE 128
#define ROPE 64
#define VDIM 128
#define KVR 512
#define QKD 192            // NOPE + ROPE
#define MTOT (BB*TT)       // 8192
#define SCALE_F (0.07216878364870323f)  // 192^-0.5

// ---------------- fp32 scratch ----------------
__device__ __align__(16) float g_Q  [(size_t)MTOT * HH * QKD];
__device__ __align__(16) float g_KVA[(size_t)MTOT * (KVR+ROPE)];
__device__ __align__(16) float g_KVN[(size_t)MTOT * KVR];
__device__ __align__(16) float g_KR [(size_t)MTOT * ROPE];
__device__ __align__(16) float g_KV [(size_t)MTOT * HH * (NOPE+VDIM)];
__device__ __align__(16) float g_ATT[(size_t)MTOT * HH * VDIM];

// ---------------- bf16 hi/lo planes (plane stride = element count) ----------
__device__ __align__(16) __nv_bfloat16 g_xh   [2 * (size_t)MTOT * DIM];
__device__ __align__(16) __nv_bfloat16 g_wqh  [2 * (size_t)(HH*QKD) * DIM];
__device__ __align__(16) __nv_bfloat16 g_wkvah[2 * (size_t)(KVR+ROPE) * DIM];
__device__ __align__(16) __nv_bfloat16 g_wkvbh[2 * (size_t)(HH*(NOPE+VDIM)) * KVR];
__device__ __align__(16) __nv_bfloat16 g_woh  [2 * (size_t)DIM * (HH*VDIM)];
__device__ __align__(16) __nv_bfloat16 g_kvnh [2 * (size_t)MTOT * KVR];
__device__ __align__(16) __nv_bfloat16 g_atth [2 * (size_t)MTOT * HH * VDIM];

// ---------------- fp32 -> (hi, lo) bf16 planes ----------------
__global__ void conv_hilo(const float* __restrict__ src, __nv_bfloat16* __restrict__ dst, size_t n)
{
    size_t i = (size_t)blockIdx.x * blockDim.x + threadIdx.x;
    if (i >= n) return;
    float v = src[i];
    __nv_bfloat16 h = __float2bfloat16(v);
    dst[i]     = h;
    dst[n + i] = __float2bfloat16(v - __bfloat162float(h));
}

// ---------------- HMMA helpers ----------------
__device__ __forceinline__ void ldsm4(uint32_t* r, uint32_t addr) {
    asm volatile("ldmatrix.sync.aligned.m8n8.x4.shared.b16 {%0,%1,%2,%3},[%4];"
                 : "=r"(r[0]), "=r"(r[1]), "=r"(r[2]), "=r"(r[3]) : "r"(addr));
}
__device__ __forceinline__ void ldsm2(uint32_t* r, uint32_t addr) {
    asm volatile("ldmatrix.sync.aligned.m8n8.x2.shared.b16 {%0,%1},[%2];"
                 : "=r"(r[0]), "=r"(r[1]) : "r"(addr));
}
__device__ __forceinline__ void mma16816(float* c, const uint32_t* a, const uint32_t* b) {
    asm volatile(
        "mma.sync.aligned.m16n8k16.row.col.f32.bf16.bf16.f32 "
        "{%0,%1,%2,%3},{%4,%5,%6,%7},{%8,%9},{%0,%1,%2,%3};"
        : "+f"(c[0]), "+f"(c[1]), "+f"(c[2]), "+f"(c[3])
        : "r"(a[0]), "r"(a[1]), "r"(a[2]), "r"(a[3]), "r"(b[0]), "r"(b[1]));
}

// ---------------- HMMA GEMM: C[M,N] = A@B^T + bias, A/B as hi/lo bf16 planes ----
// BM=BN=128, BK=32, 256 threads, warps 4(m)x2(n), warp tile 32x64.
#define LDPAD 40   // bf16 elems per smem row (80B, conflict-free ldmatrix)

__global__ __launch_bounds__(256, 2) void gemm_hmma(
    const __nv_bfloat16* __restrict__ A, size_t aPlane,
    const __nv_bfloat16* __restrict__ B, size_t bPlane,
    const float* __restrict__ bias, float* __restrict__ C,
    int M, int N, int K)
{
    __shared__ __nv_bfloat16 As[2][128][LDPAD];
    __shared__ __nv_bfloat16 Bs[2][128][LDPAD];

    const int tid  = threadIdx.x;
    const int lane = tid & 31;
    const int wid  = tid >> 5;
    const int brow = blockIdx.y * 128;
    const int bcol = blockIdx.x * 128;

    // loader mapping: 2 rows x 1 k-chunk of 8 bf16 per plane per matrix
    const int lc = tid & 3;        // k-chunk (8 bf16 = 16B)
    const int lr = tid >> 2;       // 0..63 -> rows lr, lr+64

    const int wm = (wid & 3) * 32;
    const int wn = (wid >> 2) * 64;

    float acc[2][8][4];
#pragma unroll
    for (int mi = 0; mi < 2; mi++)
#pragma unroll
        for (int ni = 0; ni < 8; ni++)
#pragma unroll
            for (int e = 0; e < 4; e++) acc[mi][ni][e] = 0.f;

    const uint32_t sAs = (uint32_t)__cvta_generic_to_shared(&As[0][0][0]);
    const uint32_t sBs = (uint32_t)__cvta_generic_to_shared(&Bs[0][0][0]);
    const uint32_t planeOff = 128 * LDPAD * 2;   // bytes between hi and lo planes

    uint4 ra[4], rb[4];   // [plane*2 + rowhalf]

    // prefetch stage 0
    {
        const int k0 = 0;
#pragma unroll
        for (int p = 0; p < 2; p++) {
#pragma unroll
            for (int rh = 0; rh < 2; rh++) {
                int row = lr + rh * 64;
                ra[p*2+rh] = *(const uint4*)(A + p*aPlane + (size_t)(brow + row) * K + k0 + lc*8);
                int n = bcol + row;
                if (n < N) rb[p*2+rh] = *(const uint4*)(B + p*bPlane + (size_t)n * K + k0 + lc*8);
                else       rb[p*2+rh] = make_uint4(0,0,0,0);
            }
        }
    }

    for (int k0 = 0; k0 < K; k0 += 32) {
        // store prefetched regs
#pragma unroll
        for (int p = 0; p < 2; p++) {
#pragma unroll
            for (int rh = 0; rh < 2; rh++) {
                int row = lr + rh * 64;
                *(uint4*)&As[p][row][lc*8] = ra[p*2+rh];
                *(uint4*)&Bs[p][row][lc*8] = rb[p*2+rh];
            }
        }
        __syncthreads();

        // prefetch next stage
        if (k0 + 32 < K) {
            const int kn = k0 + 32;
#pragma unroll
            for (int p = 0; p < 2; p++) {
#pragma unroll
                for (int rh = 0; rh < 2; rh++) {
                    int row = lr + rh * 64;
                    ra[p*2+rh] = *(const uint4*)(A + p*aPlane + (size_t)(brow + row) * K + kn + lc*8);
                    int n = bcol + row;
                    if (n < N) rb[p*2+rh] = *(const uint4*)(B + p*bPlane + (size_t)n * K + kn + lc*8);
                    else       rb[p*2+rh] = make_uint4(0,0,0,0);
                }
            }
        }

        // compute: two k-steps of 16
#pragma unroll
        for (int ks = 0; ks < 2; ks++) {
            const int kc = ks * 16;
            uint32_t a_h[2][4], a_l[2][4];
#pragma unroll
            for (int mi = 0; mi < 2; mi++) {
                uint32_t addr = sAs + ((wm + mi*16 + (lane & 15)) * LDPAD + kc + (lane >> 4) * 8) * 2;
                ldsm4(a_h[mi], addr);
                ldsm4(a_l[mi], addr + planeOff);
            }
#pragma unroll
            for (int ni = 0; ni < 8; ni++) {
                uint32_t baddr = sBs + ((wn + ni*8 + (lane & 7)) * LDPAD + kc + ((lane >> 3) & 1) * 8) * 2;
                uint32_t b_h[2], b_l[2];
                ldsm2(b_h, baddr);
                ldsm2(b_l, baddr + planeOff);
#pragma unroll
                for (int mi = 0; mi < 2; mi++) {
                    mma16816(acc[mi][ni], a_h[mi], b_h);
                    mma16816(acc[mi][ni], a_h[mi], b_l);
                    mma16816(acc[mi][ni], a_l[mi], b_h);
                }
            }
        }
        __syncthreads();
    }

    // epilogue
#pragma unroll
    for (int mi = 0; mi < 2; mi++) {
        int r0 = brow + wm + mi*16 + (lane >> 2);
#pragma unroll
        for (int ni = 0; ni < 8; ni++) {
            int c0 = bcol + wn + ni*8 + (lane & 3) * 2;
            if (c0 < N) {
                float b0 = bias[c0], b1 = bias[c0+1];
                C[(size_t)r0 * N + c0]       = acc[mi][ni][0] + b0;
                C[(size_t)r0 * N + c0 + 1]   = acc[mi][ni][1] + b1;
                C[(size_t)(r0+8) * N + c0]   = acc[mi][ni][2] + b0;
                C[(size_t)(r0+8) * N + c0+1] = acc[mi][ni][3] + b1;
            }
        }
    }
}

// ---------------- q rope + scale ----------------
__global__ void rope_q_kernel(const float* __restrict__ cosv, const float* __restrict__ sinv)
{
    int idx = blockIdx.x * blockDim.x + threadIdx.x;
    const int total = MTOT * HH * 96;
    if (idx >= total) return;
    int j   = idx % 96;
    int bth = idx / 96;
    int bt  = bth / HH;
    int t   = bt % TT;
    float* q = g_Q + (size_t)bth * QKD;
    if (j < 64) {
        q[2*j]   *= SCALE_F;
        q[2*j+1] *= SCALE_F;
    } else {
        int i = j - 64;
        float c = cosv[t*32 + i];
        float s = sinv[t*32 + i];
        float xr = q[NOPE + 2*i];
        float xi = q[NOPE + 2*i + 1];
        q[NOPE + 2*i]     = (xr*c - xi*s) * SCALE_F;
        q[NOPE + 2*i + 1] = (xr*s + xi*c) * SCALE_F;
    }
}

// ---------------- kv_a post: rms_norm -> g_KVN, rope -> g_KR ----------------
__global__ __launch_bounds__(128) void kva_post_kernel(const float* __restrict__ cosv,
                                                       const float* __restrict__ sinv)
{
    __shared__ float red[4];
    const int bt = blockIdx.x;
    const int t  = bt % TT;
    const float* a = g_KVA + (size_t)bt * (KVR + ROPE);
    const int tid = threadIdx.x;

    float ss = 0.f;
    for (int d = tid; d < KVR; d += 128) { float v = a[d]; ss += v * v; }
#pragma unroll
    for (int off = 16; off; off >>= 1) ss += __shfl_xor_sync(0xffffffffu, ss, off);
    if ((tid & 31) == 0) red[tid >> 5] = ss;
    __syncthreads();
    float total = red[0] + red[1] + red[2] + red[3];
    float r = rsqrtf(total * (1.0f / KVR) + 1e-6f);

    float* o = g_KVN + (size_t)bt * KVR;
    for (int d = tid; d < KVR; d += 128) o[d] = a[d] * r;

    if (tid < 32) {
        int i = tid;
        float c = cosv[t*32 + i];
        float s = sinv[t*32 + i];
        float xr = a[KVR + 2*i];
        float xi = a[KVR + 2*i + 1];
        g_KR[(size_t)bt * ROPE + 2*i]     = xr*c - xi*s;
        g_KR[(size_t)bt * ROPE + 2*i + 1] = xr*s + xi*c;
    }
}

// ---------------- flash attention (causal), 1 warp = 1 query ----------------
#define AQ 8
#define AK 64
#define KSTR 193
#define ATT_SMEM ((AQ*QKD + AK*KSTR + AK*VDIM) * 4)

__global__ __launch_bounds__(256) void attn_kernel()
{
    extern __shared__ float sm[];
    float* qs = sm;
    float* ks = qs + AQ * QKD;
    float* vs = ks + AK * KSTR;

    const int b  = blockIdx.z;
    const int h  = blockIdx.y;
    const int t0 = blockIdx.x * AQ;
    const int tid  = threadIdx.x;
    const int w    = tid >> 5;
    const int lane = tid & 31;

    for (int i = tid; i < AQ * QKD; i += 256) {
        int qi = i / QKD, d = i % QKD;
        qs[i] = g_Q[(((size_t)(b*TT + t0 + qi)) * HH + h) * QKD + d];
    }

    const int t = t0 + w;
    float m = -1e30f, l = 0.f;
    float o0 = 0.f, o1 = 0.f, o2 = 0.f, o3 = 0.f;

    const int nblocks = t0 / AK + 1;
    for (int kb = 0; kb < nblocks; kb++) {
        const int sbase = kb * AK;
        __syncthreads();
        for (int i = tid; i < AK * QKD; i += 256) {
            int j = i / QKD, d = i % QKD;
            size_t srow = (size_t)(b*TT + sbase + j);
            float v;
            if (d < NOPE) v = g_KV[(srow * HH + h) * (NOPE + VDIM) + d];
            else          v = g_KR[srow * ROPE + (d - NOPE)];
            ks[j * KSTR + d] = v;
        }
        for (int i = tid; i < AK * VDIM; i += 256) {
            int j = i / VDIM, d = i % VDIM;
            vs[i] = g_KV[((size_t)(b*TT + sbase + j) * HH + h) * (NOPE + VDIM) + NOPE + d];
        }
        __syncthreads();

        float sA = 0.f, sB = 0.f;
        const float* qrow = qs + w * QKD;
        const float* kA = ks + lane * KSTR;
        const float* kB = ks + (lane + 32) * KSTR;
#pragma unroll 8
        for (int d = 0; d < QKD; d++) {
            float qd = qrow[d];
            sA += qd * kA[d];
            sB += qd * kB[d];
        }
        if (sbase + lane      > t) sA = -1e30f;
        if (sbase + 32 + lane > t) sB = -1e30f;

        float bm = fmaxf(sA, sB);
#pragma unroll
        for (int off = 16; off; off >>= 1) bm = fmaxf(bm, __shfl_xor_sync(0xffffffffu, bm, off));
        float mn   = fmaxf(m, bm);
        float corr = __expf(m - mn);
        float pA = __expf(sA - mn);
        float pB = __expf(sB - mn);
        float ps = pA + pB;
#pragma unroll
        for (int off = 16; off; off >>= 1) ps += __shfl_xor_sync(0xffffffffu, ps, off);
        l = l * corr + ps;
        o0 *= corr; o1 *= corr; o2 *= corr; o3 *= corr;
        m = mn;

#pragma unroll 8
        for (int j = 0; j < 32; j++) {
            float pj = __shfl_sync(0xffffffffu, pA, j);
            const float* vr = vs + j * VDIM;
            o0 += pj * vr[lane];
            o1 += pj * vr[lane + 32];
            o2 += pj * vr[lane + 64];
            o3 += pj * vr[lane + 96];
        }
#pragma unroll 8
        for (int j = 0; j < 32; j++) {
            float pj = __shfl_sync(0xffffffffu, pB, j);
            const float* vr = vs + (j + 32) * VDIM;
            o0 += pj * vr[lane];
            o1 += pj * vr[lane + 32];
            o2 += pj * vr[lane + 64];
            o3 += pj * vr[lane + 96];
        }
    }

    float inv = 1.f / l;
    float* op = g_ATT + (((size_t)(b*TT + t)) * HH + h) * VDIM;
    op[lane]      = o0 * inv;
    op[lane + 32] = o1 * inv;
    op[lane + 64] = o2 * inv;
    op[lane + 96] = o3 * inv;
}

// ---------------- launch ----------------
static inline void conv_launch(const float* src, __nv_bfloat16* dst, size_t n)
{
    conv_hilo<<<(unsigned)((n + 255) / 256), 256>>>(src, dst, n);
}

extern "C" void kernel_launch(void* const* d_in, const int* in_sizes, int n_in,
                              void* d_out, int out_size)
{
    const float* x       = (const float*)d_in[0];
    const float* wq_w    = (const float*)d_in[1];
    const float* wq_b    = (const float*)d_in[2];
    const float* wkv_a_w = (const float*)d_in[3];
    const float* wkv_a_b = (const float*)d_in[4];
    const float* wkv_b_w = (const float*)d_in[5];
    const float* wkv_b_b = (const float*)d_in[6];
    const float* wo_w    = (const float*)d_in[7];
    const float* wo_b    = (const float*)d_in[8];
    const float* cosv    = (const float*)d_in[9];
    const float* sinv    = (const float*)d_in[10];
    float* out = (float*)d_out;

    float *Qp, *KVAp, *KVNp, *KVp, *ATTp;
    cudaGetSymbolAddress((void**)&Qp,   g_Q);
    cudaGetSymbolAddress((void**)&KVAp, g_KVA);
    cudaGetSymbolAddress((void**)&KVNp, g_KVN);
    cudaGetSymbolAddress((void**)&KVp,  g_KV);
    cudaGetSymbolAddress((void**)&ATTp, g_ATT);

    __nv_bfloat16 *xh, *wqh, *wkvah, *wkvbh, *woh, *kvnh, *atth;
    cudaGetSymbolAddress((void**)&xh,    g_xh);
    cudaGetSymbolAddress((void**)&wqh,   g_wqh);
    cudaGetSymbolAddress((void**)&wkvah, g_wkvah);
    cudaGetSymbolAddress((void**)&wkvbh, g_wkvbh);
    cudaGetSymbolAddress((void**)&woh,   g_woh);
    cudaGetSymbolAddress((void**)&kvnh,  g_kvnh);
    cudaGetSymbolAddress((void**)&atth,  g_atth);

    const size_t nX    = (size_t)MTOT * DIM;
    const size_t nWQ   = (size_t)(HH*QKD) * DIM;
    const size_t nWKVA = (size_t)(KVR+ROPE) * DIM;
    const size_t nWKVB = (size_t)(HH*(NOPE+VDIM)) * KVR;
    const size_t nWO   = (size_t)DIM * (HH*VDIM);
    const size_t nKVN  = (size_t)MTOT * KVR;
    const size_t nATT  = (size_t)MTOT * HH * VDIM;

    // conversions (weights + x)
    conv_launch(x,       xh,    nX);
    conv_launch(wq_w,    wqh,   nWQ);
    conv_launch(wkv_a_w, wkvah, nWKVA);
    conv_launch(wkv_b_w, wkvbh, nWKVB);
    conv_launch(wo_w,    woh,   nWO);

    // 1) q = x @ wq^T + b   [8192, 3072]
    gemm_hmma<<<dim3(3072/128, MTOT/128), 256>>>(xh, nX, wqh, nWQ, wq_b, Qp, MTOT, HH*QKD, DIM);
    // 2) rope + scale
    {
        int total = MTOT * HH * 96;
        rope_q_kernel<<<(total + 255) / 256, 256>>>(cosv, sinv);
    }
    // 3) kv_a = x @ wkv_a^T + b   [8192, 576]
    gemm_hmma<<<dim3((KVR+ROPE+127)/128, MTOT/128), 256>>>(xh, nX, wkvah, nWKVA, wkv_a_b, KVAp, MTOT, KVR+ROPE, DIM);
    // 4) rms norm + k rope
    kva_post_kernel<<<MTOT, 128>>>(cosv, sinv);
    conv_launch(KVNp, kvnh, nKVN);
    // 5) kv = norm @ wkv_b^T + b  [8192, 4096]
    gemm_hmma<<<dim3(HH*(NOPE+VDIM)/128, MTOT/128), 256>>>(kvnh, nKVN, wkvbh, nWKVB, wkv_b_b, KVp, MTOT, HH*(NOPE+VDIM), KVR);
    // 6) attention
    cudaFuncSetAttribute(attn_kernel, cudaFuncAttributeMaxDynamicSharedMemorySize, ATT_SMEM);
    attn_kernel<<<dim3(TT/AQ, HH, BB), 256, ATT_SMEM>>>();
    // 7) out = att @ wo^T + b     [8192, 1024]
    conv_launch(ATTp, atth, nATT);
    gemm_hmma<<<dim3(DIM/128, MTOT/128), 256>>>(atth, nATT, woh, nWO, wo_b, out, MTOT, DIM, HH*VDIM);
}

// round 5
// speedup vs baseline: 5.8447x; 5.1559x over previous
#include <cuda_runtime.h>
#include <cuda_bf16.h>
#include <math.h>
#include <stdint.h>

// ---------------- problem constants ----------------
#define BB 4
#define TT 2048
#define DIM 1024
#define HH 16
#define NOPE 128
#define ROPE 64
#define VDIM 128
#define KVR 512
#define QKD 192            // NOPE + ROPE
#define MTOT (BB*TT)       // 8192
#define SCALE_F (0.07216878364870323f)  // 192^-0.5

// ---------------- fp32 scratch ----------------
__device__ __align__(16) float g_Q  [(size_t)MTOT * HH * QKD];
__device__ __align__(16) float g_KVA[(size_t)MTOT * (KVR+ROPE)];
__device__ __align__(16) float g_KVN[(size_t)MTOT * KVR];
__device__ __align__(16) float g_KR [(size_t)MTOT * ROPE];
__device__ __align__(16) float g_KV [(size_t)MTOT * HH * (NOPE+VDIM)];
__device__ __align__(16) float g_ATT[(size_t)MTOT * HH * VDIM];

// ---------------- bf16 hi/lo planes for GEMMs ----------
__device__ __align__(16) __nv_bfloat16 g_xh   [2 * (size_t)MTOT * DIM];
__device__ __align__(16) __nv_bfloat16 g_wqh  [2 * (size_t)(HH*QKD) * DIM];
__device__ __align__(16) __nv_bfloat16 g_wkvah[2 * (size_t)(KVR+ROPE) * DIM];
__device__ __align__(16) __nv_bfloat16 g_wkvbh[2 * (size_t)(HH*(NOPE+VDIM)) * KVR];
__device__ __align__(16) __nv_bfloat16 g_woh  [2 * (size_t)DIM * (HH*VDIM)];
__device__ __align__(16) __nv_bfloat16 g_kvnh [2 * (size_t)MTOT * KVR];
__device__ __align__(16) __nv_bfloat16 g_atth [2 * (size_t)MTOT * HH * VDIM];

// ---------------- bf16 hi/lo attention tensors ----------
// qhl/khl: [b][h][t][192] (plane stride = MTOT*HH*QKD)
// vhl:     [b][h][d][t]   (transposed; plane stride = MTOT*HH*VDIM)
__device__ __align__(16) __nv_bfloat16 g_qhl[2 * (size_t)MTOT * HH * QKD];
__device__ __align__(16) __nv_bfloat16 g_khl[2 * (size_t)MTOT * HH * QKD];
__device__ __align__(16) __nv_bfloat16 g_vhl[2 * (size_t)MTOT * HH * VDIM];

// ---------------- fp32 -> (hi, lo) bf16 planes ----------------
__global__ void conv_hilo(const float* __restrict__ src, __nv_bfloat16* __restrict__ dst, size_t n)
{
    size_t i = (size_t)blockIdx.x * blockDim.x + threadIdx.x;
    if (i >= n) return;
    float v = src[i];
    __nv_bfloat16 h = __float2bfloat16(v);
    dst[i]     = h;
    dst[n + i] = __float2bfloat16(v - __bfloat162float(h));
}

// ---------------- HMMA helpers ----------------
__device__ __forceinline__ void ldsm4(uint32_t* r, uint32_t addr) {
    asm volatile("ldmatrix.sync.aligned.m8n8.x4.shared.b16 {%0,%1,%2,%3},[%4];"
                 : "=r"(r[0]), "=r"(r[1]), "=r"(r[2]), "=r"(r[3]) : "r"(addr));
}
__device__ __forceinline__ void ldsm2(uint32_t* r, uint32_t addr) {
    asm volatile("ldmatrix.sync.aligned.m8n8.x2.shared.b16 {%0,%1},[%2];"
                 : "=r"(r[0]), "=r"(r[1]) : "r"(addr));
}
__device__ __forceinline__ void mma16816(float* c, const uint32_t* a, const uint32_t* b) {
    asm volatile(
        "mma.sync.aligned.m16n8k16.row.col.f32.bf16.bf16.f32 "
        "{%0,%1,%2,%3},{%4,%5,%6,%7},{%8,%9},{%0,%1,%2,%3};"
        : "+f"(c[0]), "+f"(c[1]), "+f"(c[2]), "+f"(c[3])
        : "r"(a[0]), "r"(a[1]), "r"(a[2]), "r"(a[3]), "r"(b[0]), "r"(b[1]));
}
__device__ __forceinline__ uint32_t pack_bf2(__nv_bfloat16 a, __nv_bfloat16 b) {
    __nv_bfloat162 t; t.x = a; t.y = b;
    return *(uint32_t*)&t;
}

// ---------------- HMMA GEMM (unchanged from R4) ----------------
#define LDPAD 40

__global__ __launch_bounds__(256, 2) void gemm_hmma(
    const __nv_bfloat16* __restrict__ A, size_t aPlane,
    const __nv_bfloat16* __restrict__ B, size_t bPlane,
    const float* __restrict__ bias, float* __restrict__ C,
    int M, int N, int K)
{
    __shared__ __nv_bfloat16 As[2][128][LDPAD];
    __shared__ __nv_bfloat16 Bs[2][128][LDPAD];

    const int tid  = threadIdx.x;
    const int lane = tid & 31;
    const int wid  = tid >> 5;
    const int brow = blockIdx.y * 128;
    const int bcol = blockIdx.x * 128;

    const int lc = tid & 3;
    const int lr = tid >> 2;

    const int wm = (wid & 3) * 32;
    const int wn = (wid >> 2) * 64;

    float acc[2][8][4];
#pragma unroll
    for (int mi = 0; mi < 2; mi++)
#pragma unroll
        for (int ni = 0; ni < 8; ni++)
#pragma unroll
            for (int e = 0; e < 4; e++) acc[mi][ni][e] = 0.f;

    const uint32_t sAs = (uint32_t)__cvta_generic_to_shared(&As[0][0][0]);
    const uint32_t sBs = (uint32_t)__cvta_generic_to_shared(&Bs[0][0][0]);
    const uint32_t planeOff = 128 * LDPAD * 2;

    uint4 ra[4], rb[4];

    {
        const int k0 = 0;
#pragma unroll
        for (int p = 0; p < 2; p++) {
#pragma unroll
            for (int rh = 0; rh < 2; rh++) {
                int row = lr + rh * 64;
                ra[p*2+rh] = *(const uint4*)(A + p*aPlane + (size_t)(brow + row) * K + k0 + lc*8);
                int n = bcol + row;
                if (n < N) rb[p*2+rh] = *(const uint4*)(B + p*bPlane + (size_t)n * K + k0 + lc*8);
                else       rb[p*2+rh] = make_uint4(0,0,0,0);
            }
        }
    }

    for (int k0 = 0; k0 < K; k0 += 32) {
#pragma unroll
        for (int p = 0; p < 2; p++) {
#pragma unroll
            for (int rh = 0; rh < 2; rh++) {
                int row = lr + rh * 64;
                *(uint4*)&As[p][row][lc*8] = ra[p*2+rh];
                *(uint4*)&Bs[p][row][lc*8] = rb[p*2+rh];
            }
        }
        __syncthreads();

        if (k0 + 32 < K) {
            const int kn = k0 + 32;
#pragma unroll
            for (int p = 0; p < 2; p++) {
#pragma unroll
                for (int rh = 0; rh < 2; rh++) {
                    int row = lr + rh * 64;
                    ra[p*2+rh] = *(const uint4*)(A + p*aPlane + (size_t)(brow + row) * K + kn + lc*8);
                    int n = bcol + row;
                    if (n < N) rb[p*2+rh] = *(const uint4*)(B + p*bPlane + (size_t)n * K + kn + lc*8);
                    else       rb[p*2+rh] = make_uint4(0,0,0,0);
                }
            }
        }

#pragma unroll
        for (int ks = 0; ks < 2; ks++) {
            const int kc = ks * 16;
            uint32_t a_h[2][4], a_l[2][4];
#pragma unroll
            for (int mi = 0; mi < 2; mi++) {
                uint32_t addr = sAs + ((wm + mi*16 + (lane & 15)) * LDPAD + kc + (lane >> 4) * 8) * 2;
                ldsm4(a_h[mi], addr);
                ldsm4(a_l[mi], addr + planeOff);
            }
#pragma unroll
            for (int ni = 0; ni < 8; ni++) {
                uint32_t baddr = sBs + ((wn + ni*8 + (lane & 7)) * LDPAD + kc + ((lane >> 3) & 1) * 8) * 2;
                uint32_t b_h[2], b_l[2];
                ldsm2(b_h, baddr);
                ldsm2(b_l, baddr + planeOff);
#pragma unroll
                for (int mi = 0; mi < 2; mi++) {
                    mma16816(acc[mi][ni], a_h[mi], b_h);
                    mma16816(acc[mi][ni], a_h[mi], b_l);
                    mma16816(acc[mi][ni], a_l[mi], b_h);
                }
            }
        }
        __syncthreads();
    }

#pragma unroll
    for (int mi = 0; mi < 2; mi++) {
        int r0 = brow + wm + mi*16 + (lane >> 2);
#pragma unroll
        for (int ni = 0; ni < 8; ni++) {
            int c0 = bcol + wn + ni*8 + (lane & 3) * 2;
            if (c0 < N) {
                float b0 = bias[c0], b1 = bias[c0+1];
                C[(size_t)r0 * N + c0]       = acc[mi][ni][0] + b0;
                C[(size_t)r0 * N + c0 + 1]   = acc[mi][ni][1] + b1;
                C[(size_t)(r0+8) * N + c0]   = acc[mi][ni][2] + b0;
                C[(size_t)(r0+8) * N + c0+1] = acc[mi][ni][3] + b1;
            }
        }
    }
}

// ---------------- q rope + scale ----------------
__global__ void rope_q_kernel(const float* __restrict__ cosv, const float* __restrict__ sinv)
{
    int idx = blockIdx.x * blockDim.x + threadIdx.x;
    const int total = MTOT * HH * 96;
    if (idx >= total) return;
    int j   = idx % 96;
    int bth = idx / 96;
    int bt  = bth / HH;
    int t   = bt % TT;
    float* q = g_Q + (size_t)bth * QKD;
    if (j < 64) {
        q[2*j]   *= SCALE_F;
        q[2*j+1] *= SCALE_F;
    } else {
        int i = j - 64;
        float c = cosv[t*32 + i];
        float s = sinv[t*32 + i];
        float xr = q[NOPE + 2*i];
        float xi = q[NOPE + 2*i + 1];
        q[NOPE + 2*i]     = (xr*c - xi*s) * SCALE_F;
        q[NOPE + 2*i + 1] = (xr*s + xi*c) * SCALE_F;
    }
}

// ---------------- kv_a post: rms_norm -> g_KVN, rope -> g_KR ----------------
__global__ __launch_bounds__(128) void kva_post_kernel(const float* __restrict__ cosv,
                                                       const float* __restrict__ sinv)
{
    __shared__ float red[4];
    const int bt = blockIdx.x;
    const int t  = bt % TT;
    const float* a = g_KVA + (size_t)bt * (KVR + ROPE);
    const int tid = threadIdx.x;

    float ss = 0.f;
    for (int d = tid; d < KVR; d += 128) { float v = a[d]; ss += v * v; }
#pragma unroll
    for (int off = 16; off; off >>= 1) ss += __shfl_xor_sync(0xffffffffu, ss, off);
    if ((tid & 31) == 0) red[tid >> 5] = ss;
    __syncthreads();
    float total = red[0] + red[1] + red[2] + red[3];
    float r = rsqrtf(total * (1.0f / KVR) + 1e-6f);

    float* o = g_KVN + (size_t)bt * KVR;
    for (int d = tid; d < KVR; d += 128) o[d] = a[d] * r;

    if (tid < 32) {
        int i = tid;
        float c = cosv[t*32 + i];
        float s = sinv[t*32 + i];
        float xr = a[KVR + 2*i];
        float xi = a[KVR + 2*i + 1];
        g_KR[(size_t)bt * ROPE + 2*i]     = xr*c - xi*s;
        g_KR[(size_t)bt * ROPE + 2*i + 1] = xr*s + xi*c;
    }
}

// ---------------- build Q/K hi-lo tensors [b,h,t,192] ----------------
__global__ void build_qk_hl()
{
    const size_t NQ = (size_t)MTOT * HH * QKD;
    size_t i = (size_t)blockIdx.x * blockDim.x + threadIdx.x;
    if (i >= NQ) return;
    int d = (int)(i % QKD);
    size_t r = i / QKD;
    int h = (int)(r % HH);
    size_t bt = r / HH;
    int t = (int)(bt % TT);
    int b = (int)(bt / TT);
    size_t dst = (((size_t)b*HH + h)*TT + t)*QKD + d;

    float qv = g_Q[(bt*HH + h)*QKD + d];
    __nv_bfloat16 qh = __float2bfloat16(qv);
    g_qhl[dst]      = qh;
    g_qhl[NQ + dst] = __float2bfloat16(qv - __bfloat162float(qh));

    float kv;
    if (d < NOPE) kv = g_KV[(bt*HH + h)*(NOPE+VDIM) + d];
    else          kv = g_KR[bt*ROPE + (d - NOPE)];
    __nv_bfloat16 kh = __float2bfloat16(kv);
    g_khl[dst]      = kh;
    g_khl[NQ + dst] = __float2bfloat16(kv - __bfloat162float(kh));
}

// ---------------- build V transposed hi-lo [b,h,d,t] ----------------
__global__ void build_v_hl()
{
    __shared__ float tile[32][33];
    const size_t NV = (size_t)MTOT * HH * VDIM;
    const int bh = blockIdx.z;
    const int b = bh / HH, h = bh % HH;
    const int t0 = blockIdx.x * 32;
    const int d0 = blockIdx.y * 32;
    const int tx = threadIdx.x, ty = threadIdx.y;

#pragma unroll
    for (int k = 0; k < 4; k++) {
        int t = t0 + ty + k*8;
        tile[ty + k*8][tx] = g_KV[((size_t)(b*TT + t)*HH + h)*(NOPE+VDIM) + NOPE + d0 + tx];
    }
    __syncthreads();
#pragma unroll
    for (int k = 0; k < 4; k++) {
        int d = d0 + ty + k*8;
        float v = tile[tx][ty + k*8];
        size_t dst = ((size_t)bh*VDIM + d)*TT + t0 + tx;
        __nv_bfloat16 hi = __float2bfloat16(v);
        g_vhl[dst]      = hi;
        g_vhl[NV + dst] = __float2bfloat16(v - __bfloat162float(hi));
    }
}

// ---------------- HMMA flash attention ----------------
// CTA: 128 queries x one (b,h); 8 warps x 16 rows. 64-key tiles.
// smem (bf16 elems): qs 2x128x200 = 51200 | ks 2x64x200 = 25600 | vs 2x128x72 = 18432
#define QS_STRIDE 200
#define VS_STRIDE 72
#define SM_Q_ELEMS (2*128*QS_STRIDE)
#define SM_K_ELEMS (2*64*QS_STRIDE)
#define SM_V_ELEMS (2*128*VS_STRIDE)
#define ATT_SMEM_B ((SM_Q_ELEMS + SM_K_ELEMS + SM_V_ELEMS) * 2)

__global__ __launch_bounds__(256, 1) void attn_hmma()
{
    extern __shared__ __nv_bfloat16 smb[];
    __nv_bfloat16* qs = smb;
    __nv_bfloat16* ks = smb + SM_Q_ELEMS;
    __nv_bfloat16* vs = smb + SM_Q_ELEMS + SM_K_ELEMS;

    const int b = blockIdx.z, h = blockIdx.y;
    const int qbase = blockIdx.x * 128;
    const int tid = threadIdx.x, lane = tid & 31, w = tid >> 5;
    const size_t NQ = (size_t)MTOT * HH * QKD;
    const size_t NV = (size_t)MTOT * HH * VDIM;
    const size_t bh = (size_t)b * HH + h;

    // stage Q once
    {
        const __nv_bfloat16* qg = g_qhl + (bh*TT + qbase)*QKD;
        for (int i = tid; i < 2*128*24; i += 256) {
            int p = i / (128*24);
            int rem = i % (128*24);
            int r = rem / 24, c = rem % 24;
            *(uint4*)&qs[p*(128*QS_STRIDE) + r*QS_STRIDE + c*8] =
                *(const uint4*)&qg[(size_t)p*NQ + (size_t)r*QKD + c*8];
        }
    }

    const int g  = lane >> 2;
    const int qc = (lane & 3) * 2;
    const int qr0 = qbase + w*16 + g;     // rows qr0 (c0,c1) and qr0+8 (c2,c3)

    float m0 = -1e30f, m1 = -1e30f, l0 = 0.f, l1 = 0.f;
    float o[16][4];
#pragma unroll
    for (int nv = 0; nv < 16; nv++)
#pragma unroll
        for (int e = 0; e < 4; e++) o[nv][e] = 0.f;

    const uint32_t sQ = (uint32_t)__cvta_generic_to_shared(qs);
    const uint32_t sK = (uint32_t)__cvta_generic_to_shared(ks);
    const uint32_t sV = (uint32_t)__cvta_generic_to_shared(vs);
    const uint32_t QPB = 128*QS_STRIDE*2;
    const uint32_t KPB = 64*QS_STRIDE*2;
    const uint32_t VPB = 128*VS_STRIDE*2;

    const int ntiles = qbase/64 + 2;
    for (int kb = 0; kb < ntiles; kb++) {
        const int kbase = kb * 64;
        __syncthreads();
        // stage K
        {
            const __nv_bfloat16* kg = g_khl + (bh*TT + kbase)*QKD;
            for (int i = tid; i < 2*64*24; i += 256) {
                int p = i / (64*24);
                int rem = i % (64*24);
                int r = rem / 24, c = rem % 24;
                *(uint4*)&ks[p*(64*QS_STRIDE) + r*QS_STRIDE + c*8] =
                    *(const uint4*)&kg[(size_t)p*NQ + (size_t)r*QKD + c*8];
            }
            // stage V (already [d][t] in global)
            const __nv_bfloat16* vg = g_vhl + bh*VDIM*TT + kbase;
            for (int i = tid; i < 2*128*8; i += 256) {
                int p = i / (128*8);
                int rem = i % (128*8);
                int d = rem / 8, c = rem % 8;
                *(uint4*)&vs[p*(128*VS_STRIDE) + d*VS_STRIDE + c*8] =
                    *(const uint4*)&vg[(size_t)p*NV + (size_t)d*TT + c*8];
            }
        }
        __syncthreads();

        // ---- S = Q @ K^T (3-term hi/lo) ----
        float s[8][4];
#pragma unroll
        for (int ni = 0; ni < 8; ni++)
#pragma unroll
            for (int e = 0; e < 4; e++) s[ni][e] = 0.f;

#pragma unroll
        for (int kp = 0; kp < 6; kp++) {
            uint32_t ah0[4], ah1[4], al0[4], al1[4];
            uint32_t ab = sQ + ((w*16 + (lane & 15))*QS_STRIDE + kp*32 + (lane >> 4)*8) * 2;
            ldsm4(ah0, ab);
            ldsm4(ah1, ab + 32);
            ldsm4(al0, ab + QPB);
            ldsm4(al1, ab + QPB + 32);
#pragma unroll
            for (int ni = 0; ni < 8; ni++) {
                uint32_t bb = sK + ((ni*8 + (lane & 7))*QS_STRIDE + kp*32 + (lane >> 3)*8) * 2;
                uint32_t bh4[4], bl4[4];
                ldsm4(bh4, bb);
                ldsm4(bl4, bb + KPB);
                mma16816(s[ni], ah0, bh4);
                mma16816(s[ni], al0, bh4);
                mma16816(s[ni], ah0, bl4);
                mma16816(s[ni], ah1, bh4 + 2);
                mma16816(s[ni], al1, bh4 + 2);
                mma16816(s[ni], ah1, bl4 + 2);
            }
        }

        // ---- causal mask ----
        if (kbase + 63 > qr0) {
#pragma unroll
            for (int ni = 0; ni < 8; ni++) {
                int col = kbase + ni*8 + qc;
                if (col     > qr0)     s[ni][0] = -1e30f;
                if (col + 1 > qr0)     s[ni][1] = -1e30f;
                if (col     > qr0 + 8) s[ni][2] = -1e30f;
                if (col + 1 > qr0 + 8) s[ni][3] = -1e30f;
            }
        }

        // ---- online softmax ----
        float rm0 = -1e30f, rm1 = -1e30f;
#pragma unroll
        for (int ni = 0; ni < 8; ni++) {
            rm0 = fmaxf(rm0, fmaxf(s[ni][0], s[ni][1]));
            rm1 = fmaxf(rm1, fmaxf(s[ni][2], s[ni][3]));
        }
        rm0 = fmaxf(rm0, __shfl_xor_sync(0xffffffffu, rm0, 1));
        rm0 = fmaxf(rm0, __shfl_xor_sync(0xffffffffu, rm0, 2));
        rm1 = fmaxf(rm1, __shfl_xor_sync(0xffffffffu, rm1, 1));
        rm1 = fmaxf(rm1, __shfl_xor_sync(0xffffffffu, rm1, 2));
        float nm0 = fmaxf(m0, rm0), nm1 = fmaxf(m1, rm1);
        float c0 = __expf(m0 - nm0), c1 = __expf(m1 - nm1);

        float rs0 = 0.f, rs1 = 0.f;
#pragma unroll
        for (int ni = 0; ni < 8; ni++) {
            s[ni][0] = __expf(s[ni][0] - nm0); rs0 += s[ni][0];
            s[ni][1] = __expf(s[ni][1] - nm0); rs0 += s[ni][1];
            s[ni][2] = __expf(s[ni][2] - nm1); rs1 += s[ni][2];
            s[ni][3] = __expf(s[ni][3] - nm1); rs1 += s[ni][3];
        }
        rs0 += __shfl_xor_sync(0xffffffffu, rs0, 1);
        rs0 += __shfl_xor_sync(0xffffffffu, rs0, 2);
        rs1 += __shfl_xor_sync(0xffffffffu, rs1, 1);
        rs1 += __shfl_xor_sync(0xffffffffu, rs1, 2);
        l0 = l0 * c0 + rs0;
        l1 = l1 * c1 + rs1;
        m0 = nm0; m1 = nm1;
#pragma unroll
        for (int nv = 0; nv < 16; nv++) {
            o[nv][0] *= c0; o[nv][1] *= c0;
            o[nv][2] *= c1; o[nv][3] *= c1;
        }

        // ---- O += P @ V (3-term hi/lo) ----
#pragma unroll
        for (int kp = 0; kp < 2; kp++) {
            uint32_t ph[2][4], pl[2][4];
#pragma unroll
            for (int ss = 0; ss < 2; ss++) {        // kstep 2kp+ss
                int n0 = kp*4 + ss*2;
#pragma unroll
                for (int half = 0; half < 2; half++) {   // a0/a1 from tile n0, a2/a3 from n0+1
                    int nt = n0 + half;
                    float v0 = s[nt][0], v1 = s[nt][1], v2 = s[nt][2], v3 = s[nt][3];
                    __nv_bfloat16 h0 = __float2bfloat16(v0);
                    __nv_bfloat16 h1 = __float2bfloat16(v1);
                    __nv_bfloat16 h2 = __float2bfloat16(v2);
                    __nv_bfloat16 h3 = __float2bfloat16(v3);
                    ph[ss][half*2 + 0] = pack_bf2(h0, h1);
                    ph[ss][half*2 + 1] = pack_bf2(h2, h3);
                    pl[ss][half*2 + 0] = pack_bf2(__float2bfloat16(v0 - __bfloat162float(h0)),
                                                  __float2bfloat16(v1 - __bfloat162float(h1)));
                    pl[ss][half*2 + 1] = pack_bf2(__float2bfloat16(v2 - __bfloat162float(h2)),
                                                  __float2bfloat16(v3 - __bfloat162float(h3)));
                }
            }
#pragma unroll
            for (int nv = 0; nv < 16; nv++) {
                uint32_t vb = sV + ((nv*8 + (lane & 7))*VS_STRIDE + kp*32 + (lane >> 3)*8) * 2;
                uint32_t vh4[4], vl4[4];
                ldsm4(vh4, vb);
                ldsm4(vl4, vb + VPB);
                mma16816(o[nv], ph[0], vh4);
                mma16816(o[nv], pl[0], vh4);
                mma16816(o[nv], ph[0], vl4);
                mma16816(o[nv], ph[1], vh4 + 2);
                mma16816(o[nv], pl[1], vh4 + 2);
                mma16816(o[nv], ph[1], vl4 + 2);
            }
        }
    }

    // ---- epilogue ----
    float inv0 = 1.f / l0, inv1 = 1.f / l1;
    float* op0 = g_ATT + (size_t)(b*TT + qr0) * (HH*VDIM) + h*VDIM;
    float* op1 = op0 + (size_t)8 * (HH*VDIM);
#pragma unroll
    for (int nv = 0; nv < 16; nv++) {
        int d = nv*8 + qc;
        op0[d]     = o[nv][0] * inv0;
        op0[d + 1] = o[nv][1] * inv0;
        op1[d]     = o[nv][2] * inv1;
        op1[d + 1] = o[nv][3] * inv1;
    }
}

// ---------------- launch ----------------
static inline void conv_launch(const float* src, __nv_bfloat16* dst, size_t n)
{
    conv_hilo<<<(unsigned)((n + 255) / 256), 256>>>(src, dst, n);
}

extern "C" void kernel_launch(void* const* d_in, const int* in_sizes, int n_in,
                              void* d_out, int out_size)
{
    const float* x       = (const float*)d_in[0];
    const float* wq_w    = (const float*)d_in[1];
    const float* wq_b    = (const float*)d_in[2];
    const float* wkv_a_w = (const float*)d_in[3];
    const float* wkv_a_b = (const float*)d_in[4];
    const float* wkv_b_w = (const float*)d_in[5];
    const float* wkv_b_b = (const float*)d_in[6];
    const float* wo_w    = (const float*)d_in[7];
    const float* wo_b    = (const float*)d_in[8];
    const float* cosv    = (const float*)d_in[9];
    const float* sinv    = (const float*)d_in[10];
    float* out = (float*)d_out;

    float *Qp, *KVAp, *KVNp, *KVp, *ATTp;
    cudaGetSymbolAddress((void**)&Qp,   g_Q);
    cudaGetSymbolAddress((void**)&KVAp, g_KVA);
    cudaGetSymbolAddress((void**)&KVNp, g_KVN);
    cudaGetSymbolAddress((void**)&KVp,  g_KV);
    cudaGetSymbolAddress((void**)&ATTp, g_ATT);

    __nv_bfloat16 *xh, *wqh, *wkvah, *wkvbh, *woh, *kvnh, *atth;
    cudaGetSymbolAddress((void**)&xh,    g_xh);
    cudaGetSymbolAddress((void**)&wqh,   g_wqh);
    cudaGetSymbolAddress((void**)&wkvah, g_wkvah);
    cudaGetSymbolAddress((void**)&wkvbh, g_wkvbh);
    cudaGetSymbolAddress((void**)&woh,   g_woh);
    cudaGetSymbolAddress((void**)&kvnh,  g_kvnh);
    cudaGetSymbolAddress((void**)&atth,  g_atth);

    const size_t nX    = (size_t)MTOT * DIM;
    const size_t nWQ   = (size_t)(HH*QKD) * DIM;
    const size_t nWKVA = (size_t)(KVR+ROPE) * DIM;
    const size_t nWKVB = (size_t)(HH*(NOPE+VDIM)) * KVR;
    const size_t nWO   = (size_t)DIM * (HH*VDIM);
    const size_t nKVN  = (size_t)MTOT * KVR;
    const size_t nATT  = (size_t)MTOT * HH * VDIM;
    const size_t nQK   = (size_t)MTOT * HH * QKD;

    // conversions (weights + x)
    conv_launch(x,       xh,    nX);
    conv_launch(wq_w,    wqh,   nWQ);
    conv_launch(wkv_a_w, wkvah, nWKVA);
    conv_launch(wkv_b_w, wkvbh, nWKVB);
    conv_launch(wo_w,    woh,   nWO);

    // 1) q = x @ wq^T + b
    gemm_hmma<<<dim3(3072/128, MTOT/128), 256>>>(xh, nX, wqh, nWQ, wq_b, Qp, MTOT, HH*QKD, DIM);
    // 2) rope + scale
    {
        int total = MTOT * HH * 96;
        rope_q_kernel<<<(total + 255) / 256, 256>>>(cosv, sinv);
    }
    // 3) kv_a = x @ wkv_a^T + b
    gemm_hmma<<<dim3((KVR+ROPE+127)/128, MTOT/128), 256>>>(xh, nX, wkvah, nWKVA, wkv_a_b, KVAp, MTOT, KVR+ROPE, DIM);
    // 4) rms norm + k rope
    kva_post_kernel<<<MTOT, 128>>>(cosv, sinv);
    conv_launch(KVNp, kvnh, nKVN);
    // 5) kv = norm @ wkv_b^T + b
    gemm_hmma<<<dim3(HH*(NOPE+VDIM)/128, MTOT/128), 256>>>(kvnh, nKVN, wkvbh, nWKVB, wkv_b_b, KVp, MTOT, HH*(NOPE+VDIM), KVR);
    // 6) build attention tensors
    build_qk_hl<<<(unsigned)((nQK + 255) / 256), 256>>>();
    build_v_hl<<<dim3(TT/32, VDIM/32, BB*HH), dim3(32, 8)>>>();
    // 7) flash attention (HMMA)
    cudaFuncSetAttribute(attn_hmma, cudaFuncAttributeMaxDynamicSharedMemorySize, ATT_SMEM_B);
    attn_hmma<<<dim3(TT/128, HH, BB), 256, ATT_SMEM_B>>>();
    // 8) out = att @ wo^T + b
    conv_launch(ATTp, atth, nATT);
    gemm_hmma<<<dim3(DIM/128, MTOT/128), 256>>>(atth, nATT, woh, nWO, wo_b, out, MTOT, DIM, HH*VDIM);
}

// round 9
// speedup vs baseline: 6.0853x; 1.0412x over previous
#include <cuda_runtime.h>
#include <cuda_bf16.h>
#include <math.h>
#include <stdint.h>

// ---------------- problem constants ----------------
#define BB 4
#define TT 2048
#define DIM 1024
#define HH 16
#define NOPE 128
#define ROPE 64
#define VDIM 128
#define KVR 512
#define QKD 192            // NOPE + ROPE
#define MTOT (BB*TT)       // 8192
#define SCALE_F (0.07216878364870323f)  // 192^-0.5

// ---------------- fp32 scratch ----------------
__device__ __align__(16) float g_Q  [(size_t)MTOT * HH * QKD];   // raw q proj (pre-rope)
__device__ __align__(16) float g_KVA[(size_t)MTOT * (KVR+ROPE)];
__device__ __align__(16) float g_KR [(size_t)MTOT * ROPE];
__device__ __align__(16) float g_KV [(size_t)MTOT * HH * (NOPE+VDIM)];

// ---------------- bf16 hi/lo planes for GEMMs ----------
__device__ __align__(16) __nv_bfloat16 g_xh   [2 * (size_t)MTOT * DIM];
__device__ __align__(16) __nv_bfloat16 g_wqh  [2 * (size_t)(HH*QKD) * DIM];
__device__ __align__(16) __nv_bfloat16 g_wkvah[2 * (size_t)(KVR+ROPE) * DIM];
__device__ __align__(16) __nv_bfloat16 g_wkvbh[2 * (size_t)(HH*(NOPE+VDIM)) * KVR];
__device__ __align__(16) __nv_bfloat16 g_woh  [2 * (size_t)DIM * (HH*VDIM)];
__device__ __align__(16) __nv_bfloat16 g_kvnh [2 * (size_t)MTOT * KVR];
__device__ __align__(16) __nv_bfloat16 g_atth [2 * (size_t)MTOT * HH * VDIM];

// ---------------- bf16 hi/lo attention tensors ----------
__device__ __align__(16) __nv_bfloat16 g_qhl[2 * (size_t)MTOT * HH * QKD];
__device__ __align__(16) __nv_bfloat16 g_khl[2 * (size_t)MTOT * HH * QKD];
__device__ __align__(16) __nv_bfloat16 g_vhl[2 * (size_t)MTOT * HH * VDIM];

// ---------------- fp32 -> (hi, lo) bf16 planes ----------------
__global__ void conv_hilo(const float* __restrict__ src, __nv_bfloat16* __restrict__ dst, size_t n)
{
    size_t i = (size_t)blockIdx.x * blockDim.x + threadIdx.x;
    if (i >= n) return;
    float v = src[i];
    __nv_bfloat16 h = __float2bfloat16(v);
    dst[i]     = h;
    dst[n + i] = __float2bfloat16(v - __bfloat162float(h));
}

// ---------------- HMMA helpers ----------------
__device__ __forceinline__ void ldsm4(uint32_t* r, uint32_t addr) {
    asm volatile("ldmatrix.sync.aligned.m8n8.x4.shared.b16 {%0,%1,%2,%3},[%4];"
                 : "=r"(r[0]), "=r"(r[1]), "=r"(r[2]), "=r"(r[3]) : "r"(addr));
}
__device__ __forceinline__ void mma16816(float* c, const uint32_t* a, const uint32_t* b) {
    asm volatile(
        "mma.sync.aligned.m16n8k16.row.col.f32.bf16.bf16.f32 "
        "{%0,%1,%2,%3},{%4,%5,%6,%7},{%8,%9},{%0,%1,%2,%3};"
        : "+f"(c[0]), "+f"(c[1]), "+f"(c[2]), "+f"(c[3])
        : "r"(a[0]), "r"(a[1]), "r"(a[2]), "r"(a[3]), "r"(b[0]), "r"(b[1]));
}
__device__ __forceinline__ void mma16816b(float* c, const uint32_t* a, uint32_t b0, uint32_t b1) {
    asm volatile(
        "mma.sync.aligned.m16n8k16.row.col.f32.bf16.bf16.f32 "
        "{%0,%1,%2,%3},{%4,%5,%6,%7},{%8,%9},{%0,%1,%2,%3};"
        : "+f"(c[0]), "+f"(c[1]), "+f"(c[2]), "+f"(c[3])
        : "r"(a[0]), "r"(a[1]), "r"(a[2]), "r"(a[3]), "r"(b0), "r"(b1));
}
__device__ __forceinline__ uint32_t pack_bf2(__nv_bfloat16 a, __nv_bfloat16 b) {
    __nv_bfloat162 t; t.x = a; t.y = b;
    return *(uint32_t*)&t;
}
__device__ __forceinline__ uint32_t smem_u32(const void* p) {
    uint32_t a;
    asm("{ .reg .u64 t; cvta.to.shared.u64 t, %1; cvt.u32.u64 %0, t; }" : "=r"(a) : "l"(p));
    return a;
}

// ---------------- HMMA GEMM: C[M,N] = A@B^T + bias (hi/lo bf16 planes) ----
// BM=BN=128, BK=32, 256 threads, warps 4(m)x2(n), warp tile 32x64.
#define LDPAD 40   // bf16 elems per smem row (80B, conflict-free ldmatrix)

__global__ __launch_bounds__(256, 2) void gemm_hmma(
    const __nv_bfloat16* __restrict__ A, size_t aPlane,
    const __nv_bfloat16* __restrict__ B, size_t bPlane,
    const float* __restrict__ bias, float* __restrict__ C,
    int M, int N, int K)
{
    __shared__ __nv_bfloat16 As[2][128][LDPAD];
    __shared__ __nv_bfloat16 Bs[2][128][LDPAD];

    const int tid  = threadIdx.x;
    const int lane = tid & 31;
    const int wid  = tid >> 5;
    const int brow = blockIdx.y * 128;
    const int bcol = blockIdx.x * 128;

    const int lc = tid & 3;        // k-chunk (8 bf16 = 16B)
    const int lr = tid >> 2;       // 0..63 -> rows lr, lr+64

    const int wm = (wid & 3) * 32;
    const int wn = (wid >> 2) * 64;

    float acc[2][8][4];
#pragma unroll
    for (int mi = 0; mi < 2; mi++)
#pragma unroll
        for (int ni = 0; ni < 8; ni++)
#pragma unroll
            for (int e = 0; e < 4; e++) acc[mi][ni][e] = 0.f;

    const uint32_t sAs = smem_u32(&As[0][0][0]);
    const uint32_t sBs = smem_u32(&Bs[0][0][0]);
    const uint32_t planeOff = 128 * LDPAD * 2;

    uint4 ra[4], rb[4];

    {
        const int k0 = 0;
#pragma unroll
        for (int p = 0; p < 2; p++) {
#pragma unroll
            for (int rh = 0; rh < 2; rh++) {
                int row = lr + rh * 64;
                ra[p*2+rh] = *(const uint4*)(A + p*aPlane + (size_t)(brow + row) * K + k0 + lc*8);
                int n = bcol + row;
                if (n < N) rb[p*2+rh] = *(const uint4*)(B + p*bPlane + (size_t)n * K + k0 + lc*8);
                else       rb[p*2+rh] = make_uint4(0,0,0,0);
            }
        }
    }

    for (int k0 = 0; k0 < K; k0 += 32) {
#pragma unroll
        for (int p = 0; p < 2; p++) {
#pragma unroll
            for (int rh = 0; rh < 2; rh++) {
                int row = lr + rh * 64;
                *(uint4*)&As[p][row][lc*8] = ra[p*2+rh];
                *(uint4*)&Bs[p][row][lc*8] = rb[p*2+rh];
            }
        }
        __syncthreads();

        if (k0 + 32 < K) {
            const int kn = k0 + 32;
#pragma unroll
            for (int p = 0; p < 2; p++) {
#pragma unroll
                for (int rh = 0; rh < 2; rh++) {
                    int row = lr + rh * 64;
                    ra[p*2+rh] = *(const uint4*)(A + p*aPlane + (size_t)(brow + row) * K + kn + lc*8);
                    int n = bcol + row;
                    if (n < N) rb[p*2+rh] = *(const uint4*)(B + p*bPlane + (size_t)n * K + kn + lc*8);
                    else       rb[p*2+rh] = make_uint4(0,0,0,0);
                }
            }
        }

        // compute: two k-steps of 16; hoist ALL fragment loads, then dense mma burst
#pragma unroll
        for (int ks = 0; ks < 2; ks++) {
            const int kc = ks * 16;
            uint32_t a_h[2][4], a_l[2][4];
            uint32_t b_h[4][4], b_l[4][4];
#pragma unroll
            for (int mi = 0; mi < 2; mi++) {
                uint32_t addr = sAs + ((wm + mi*16 + (lane & 15)) * LDPAD + kc + (lane >> 4) * 8) * 2;
                ldsm4(a_h[mi], addr);
                ldsm4(a_l[mi], addr + planeOff);
            }
#pragma unroll
            for (int np = 0; np < 4; np++) {
                uint32_t baddr = sBs + ((wn + np*16 + (lane & 15)) * LDPAD + kc + (lane >> 4) * 8) * 2;
                ldsm4(b_h[np], baddr);
                ldsm4(b_l[np], baddr + planeOff);
            }
            // x4 over 16 B-rows: matrices {r0,r2} = rows +0..7, {r1,r3} = rows +8..15
#pragma unroll
            for (int np = 0; np < 4; np++) {
#pragma unroll
                for (int hf = 0; hf < 2; hf++) {
                    const int ni = np*2 + hf;
#pragma unroll
                    for (int mi = 0; mi < 2; mi++) {
                        mma16816b(acc[mi][ni], a_h[mi], b_h[np][hf], b_h[np][hf+2]);
                        mma16816b(acc[mi][ni], a_l[mi], b_h[np][hf], b_h[np][hf+2]);
                        mma16816b(acc[mi][ni], a_h[mi], b_l[np][hf], b_l[np][hf+2]);
                    }
                }
            }
        }
        __syncthreads();
    }

#pragma unroll
    for (int mi = 0; mi < 2; mi++) {
        int r0 = brow + wm + mi*16 + (lane >> 2);
#pragma unroll
        for (int ni = 0; ni < 8; ni++) {
            int c0 = bcol + wn + ni*8 + (lane & 3) * 2;
            if (c0 < N) {
                float b0 = bias[c0], b1 = bias[c0+1];
                C[(size_t)r0 * N + c0]       = acc[mi][ni][0] + b0;
                C[(size_t)r0 * N + c0 + 1]   = acc[mi][ni][1] + b1;
                C[(size_t)(r0+8) * N + c0]   = acc[mi][ni][2] + b0;
                C[(size_t)(r0+8) * N + c0+1] = acc[mi][ni][3] + b1;
            }
        }
    }
}

// ---------------- kv_a post: rms_norm -> g_kvnh (hi/lo), rope -> g_KR ----------------
__global__ __launch_bounds__(128) void kva_post_kernel(const float* __restrict__ cosv,
                                                       const float* __restrict__ sinv)
{
    __shared__ float red[4];
    const int bt = blockIdx.x;
    const int t  = bt % TT;
    const float* a = g_KVA + (size_t)bt * (KVR + ROPE);
    const int tid = threadIdx.x;
    const size_t nKVN = (size_t)MTOT * KVR;

    float ss = 0.f;
    for (int d = tid; d < KVR; d += 128) { float v = a[d]; ss += v * v; }
#pragma unroll
    for (int off = 16; off; off >>= 1) ss += __shfl_xor_sync(0xffffffffu, ss, off);
    if ((tid & 31) == 0) red[tid >> 5] = ss;
    __syncthreads();
    float total = red[0] + red[1] + red[2] + red[3];
    float r = rsqrtf(total * (1.0f / KVR) + 1e-6f);

    __nv_bfloat16* o = g_kvnh + (size_t)bt * KVR;
    for (int d = tid; d < KVR; d += 128) {
        float v = a[d] * r;
        __nv_bfloat16 hi = __float2bfloat16(v);
        o[d]        = hi;
        o[nKVN + d] = __float2bfloat16(v - __bfloat162float(hi));
    }

    if (tid < 32) {
        int i = tid;
        float c = cosv[t*32 + i];
        float s = sinv[t*32 + i];
        float xr = a[KVR + 2*i];
        float xi = a[KVR + 2*i + 1];
        g_KR[(size_t)bt * ROPE + 2*i]     = xr*c - xi*s;
        g_KR[(size_t)bt * ROPE + 2*i + 1] = xr*s + xi*c;
    }
}

// ---------------- build Q/K hi-lo tensors [b,h,t,192]; q-rope+scale fused ----------------
__global__ void build_qk_hl(const float* __restrict__ cosv, const float* __restrict__ sinv)
{
    const size_t NQ = (size_t)MTOT * HH * QKD;
    size_t i = (size_t)blockIdx.x * blockDim.x + threadIdx.x;
    if (i >= NQ) return;
    int d = (int)(i % QKD);
    size_t r = i / QKD;
    int h = (int)(r % HH);
    size_t bt = r / HH;
    int t = (int)(bt % TT);
    int b = (int)(bt / TT);
    size_t dst = (((size_t)b*HH + h)*TT + t)*QKD + d;

    float qv;
    if (d < NOPE) {
        qv = g_Q[(bt*HH + h)*QKD + d] * SCALE_F;
    } else {
        int i2 = d - NOPE;         // 0..63
        int pi = i2 >> 1;          // pair index
        float c = cosv[t*32 + pi];
        float s = sinv[t*32 + pi];
        size_t base = (bt*HH + h)*QKD + NOPE + 2*pi;
        float xr = g_Q[base];
        float xi = g_Q[base + 1];
        qv = ((i2 & 1) ? (xr*s + xi*c) : (xr*c - xi*s)) * SCALE_F;
    }
    __nv_bfloat16 qh = __float2bfloat16(qv);
    g_qhl[dst]      = qh;
    g_qhl[NQ + dst] = __float2bfloat16(qv - __bfloat162float(qh));

    float kv;
    if (d < NOPE) kv = g_KV[(bt*HH + h)*(NOPE+VDIM) + d];
    else          kv = g_KR[bt*ROPE + (d - NOPE)];
    __nv_bfloat16 kh = __float2bfloat16(kv);
    g_khl[dst]      = kh;
    g_khl[NQ + dst] = __float2bfloat16(kv - __bfloat162float(kh));
}

// ---------------- build V transposed hi-lo [b,h,d,t] ----------------
__global__ void build_v_hl()
{
    __shared__ float tile[32][33];
    const size_t NV = (size_t)MTOT * HH * VDIM;
    const int bh = blockIdx.z;
    const int b = bh / HH, h = bh % HH;
    const int t0 = blockIdx.x * 32;
    const int d0 = blockIdx.y * 32;
    const int tx = threadIdx.x, ty = threadIdx.y;

#pragma unroll
    for (int k = 0; k < 4; k++) {
        int t = t0 + ty + k*8;
        tile[ty + k*8][tx] = g_KV[((size_t)(b*TT + t)*HH + h)*(NOPE+VDIM) + NOPE + d0 + tx];
    }
    __syncthreads();
#pragma unroll
    for (int k = 0; k < 4; k++) {
        int d = d0 + ty + k*8;
        float v = tile[tx][ty + k*8];
        size_t dst = ((size_t)bh*VDIM + d)*TT + t0 + tx;
        __nv_bfloat16 hi = __float2bfloat16(v);
        g_vhl[dst]      = hi;
        g_vhl[NV + dst] = __float2bfloat16(v - __bfloat162float(hi));
    }
}

// ---------------- HMMA flash attention ----------------
#define QS_STRIDE 200
#define VS_STRIDE 72
#define SM_Q_ELEMS (2*128*QS_STRIDE)
#define SM_K_ELEMS (2*64*QS_STRIDE)
#define SM_V_ELEMS (2*128*VS_STRIDE)
#define ATT_SMEM_B ((SM_Q_ELEMS + SM_K_ELEMS + SM_V_ELEMS) * 2)

__global__ __launch_bounds__(256, 1) void attn_hmma()
{
    extern __shared__ __nv_bfloat16 smb[];
    __nv_bfloat16* qs = smb;
    __nv_bfloat16* ks = smb + SM_Q_ELEMS;
    __nv_bfloat16* vs = smb + SM_Q_ELEMS + SM_K_ELEMS;

    const int b = blockIdx.z, h = blockIdx.y;
    const int qbase = blockIdx.x * 128;
    const int tid = threadIdx.x, lane = tid & 31, w = tid >> 5;
    const size_t NQ = (size_t)MTOT * HH * QKD;
    const size_t NV = (size_t)MTOT * HH * VDIM;
    const size_t bh = (size_t)b * HH + h;

    {
        const __nv_bfloat16* qg = g_qhl + (bh*TT + qbase)*QKD;
        for (int i = tid; i < 2*128*24; i += 256) {
            int p = i / (128*24);
            int rem = i % (128*24);
            int r = rem / 24, c = rem % 24;
            *(uint4*)&qs[p*(128*QS_STRIDE) + r*QS_STRIDE + c*8] =
                *(const uint4*)&qg[(size_t)p*NQ + (size_t)r*QKD + c*8];
        }
    }

    const int g  = lane >> 2;
    const int qc = (lane & 3) * 2;
    const int qr0 = qbase + w*16 + g;

    float m0 = -1e30f, m1 = -1e30f, l0 = 0.f, l1 = 0.f;
    float o[16][4];
#pragma unroll
    for (int nv = 0; nv < 16; nv++)
#pragma unroll
        for (int e = 0; e < 4; e++) o[nv][e] = 0.f;

    const uint32_t sQ = smem_u32(qs);
    const uint32_t sK = smem_u32(ks);
    const uint32_t sV = smem_u32(vs);
    const uint32_t QPB = 128*QS_STRIDE*2;
    const uint32_t KPB = 64*QS_STRIDE*2;
    const uint32_t VPB = 128*VS_STRIDE*2;

    const int ntiles = qbase/64 + 2;
    for (int kb = 0; kb < ntiles; kb++) {
        const int kbase = kb * 64;
        __syncthreads();
        {
            const __nv_bfloat16* kg = g_khl + (bh*TT + kbase)*QKD;
            for (int i = tid; i < 2*64*24; i += 256) {
                int p = i / (64*24);
                int rem = i % (64*24);
                int r = rem / 24, c = rem % 24;
                *(uint4*)&ks[p*(64*QS_STRIDE) + r*QS_STRIDE + c*8] =
                    *(const uint4*)&kg[(size_t)p*NQ + (size_t)r*QKD + c*8];
            }
            const __nv_bfloat16* vg = g_vhl + bh*VDIM*TT + kbase;
            for (int i = tid; i < 2*128*8; i += 256) {
                int p = i / (128*8);
                int rem = i % (128*8);
                int d = rem / 8, c = rem % 8;
                *(uint4*)&vs[p*(128*VS_STRIDE) + d*VS_STRIDE + c*8] =
                    *(const uint4*)&vg[(size_t)p*NV + (size_t)d*TT + c*8];
            }
        }
        __syncthreads();

        float s[8][4];
#pragma unroll
        for (int ni = 0; ni < 8; ni++)
#pragma unroll
            for (int e = 0; e < 4; e++) s[ni][e] = 0.f;

#pragma unroll
        for (int kp = 0; kp < 6; kp++) {
            uint32_t ah0[4], ah1[4], al0[4], al1[4];
            uint32_t ab = sQ + ((w*16 + (lane & 15))*QS_STRIDE + kp*32 + (lane >> 4)*8) * 2;
            ldsm4(ah0, ab);
            ldsm4(ah1, ab + 32);
            ldsm4(al0, ab + QPB);
            ldsm4(al1, ab + QPB + 32);
#pragma unroll
            for (int ni = 0; ni < 8; ni++) {
                uint32_t bb = sK + ((ni*8 + (lane & 7))*QS_STRIDE + kp*32 + (lane >> 3)*8) * 2;
                uint32_t bh4[4], bl4[4];
                ldsm4(bh4, bb);
                ldsm4(bl4, bb + KPB);
                mma16816(s[ni], ah0, bh4);
                mma16816(s[ni], al0, bh4);
                mma16816(s[ni], ah0, bl4);
                mma16816(s[ni], ah1, bh4 + 2);
                mma16816(s[ni], al1, bh4 + 2);
                mma16816(s[ni], ah1, bl4 + 2);
            }
        }

        if (kbase + 63 > qr0) {
#pragma unroll
            for (int ni = 0; ni < 8; ni++) {
                int col = kbase + ni*8 + qc;
                if (col     > qr0)     s[ni][0] = -1e30f;
                if (col + 1 > qr0)     s[ni][1] = -1e30f;
                if (col     > qr0 + 8) s[ni][2] = -1e30f;
                if (col + 1 > qr0 + 8) s[ni][3] = -1e30f;
            }
        }

        float rm0 = -1e30f, rm1 = -1e30f;
#pragma unroll
        for (int ni = 0; ni < 8; ni++) {
            rm0 = fmaxf(rm0, fmaxf(s[ni][0], s[ni][1]));
            rm1 = fmaxf(rm1, fmaxf(s[ni][2], s[ni][3]));
        }
        rm0 = fmaxf(rm0, __shfl_xor_sync(0xffffffffu, rm0, 1));
        rm0 = fmaxf(rm0, __shfl_xor_sync(0xffffffffu, rm0, 2));
        rm1 = fmaxf(rm1, __shfl_xor_sync(0xffffffffu, rm1, 1));
        rm1 = fmaxf(rm1, __shfl_xor_sync(0xffffffffu, rm1, 2));
        float nm0 = fmaxf(m0, rm0), nm1 = fmaxf(m1, rm1);
        float c0 = __expf(m0 - nm0), c1 = __expf(m1 - nm1);

        float rs0 = 0.f, rs1 = 0.f;
#pragma unroll
        for (int ni = 0; ni < 8; ni++) {
            s[ni][0] = __expf(s[ni][0] - nm0); rs0 += s[ni][0];
            s[ni][1] = __expf(s[ni][1] - nm0); rs0 += s[ni][1];
            s[ni][2] = __expf(s[ni][2] - nm1); rs1 += s[ni][2];
            s[ni][3] = __expf(s[ni][3] - nm1); rs1 += s[ni][3];
        }
        rs0 += __shfl_xor_sync(0xffffffffu, rs0, 1);
        rs0 += __shfl_xor_sync(0xffffffffu, rs0, 2);
        rs1 += __shfl_xor_sync(0xffffffffu, rs1, 1);
        rs1 += __shfl_xor_sync(0xffffffffu, rs1, 2);
        l0 = l0 * c0 + rs0;
        l1 = l1 * c1 + rs1;
        m0 = nm0; m1 = nm1;
#pragma unroll
        for (int nv = 0; nv < 16; nv++) {
            o[nv][0] *= c0; o[nv][1] *= c0;
            o[nv][2] *= c1; o[nv][3] *= c1;
        }

#pragma unroll
        for (int kp = 0; kp < 2; kp++) {
            uint32_t ph[2][4], pl[2][4];
#pragma unroll
            for (int ss2 = 0; ss2 < 2; ss2++) {
                int n0 = kp*4 + ss2*2;
#pragma unroll
                for (int half = 0; half < 2; half++) {
                    int nt = n0 + half;
                    float v0 = s[nt][0], v1 = s[nt][1], v2 = s[nt][2], v3 = s[nt][3];
                    __nv_bfloat16 h0 = __float2bfloat16(v0);
                    __nv_bfloat16 h1 = __float2bfloat16(v1);
                    __nv_bfloat16 h2 = __float2bfloat16(v2);
                    __nv_bfloat16 h3 = __float2bfloat16(v3);
                    ph[ss2][half*2 + 0] = pack_bf2(h0, h1);
                    ph[ss2][half*2 + 1] = pack_bf2(h2, h3);
                    pl[ss2][half*2 + 0] = pack_bf2(__float2bfloat16(v0 - __bfloat162float(h0)),
                                                   __float2bfloat16(v1 - __bfloat162float(h1)));
                    pl[ss2][half*2 + 1] = pack_bf2(__float2bfloat16(v2 - __bfloat162float(h2)),
                                                   __float2bfloat16(v3 - __bfloat162float(h3)));
                }
            }
#pragma unroll
            for (int nv = 0; nv < 16; nv++) {
                uint32_t vb = sV + ((nv*8 + (lane & 7))*VS_STRIDE + kp*32 + (lane >> 3)*8) * 2;
                uint32_t vh4[4], vl4[4];
                ldsm4(vh4, vb);
                ldsm4(vl4, vb + VPB);
                mma16816(o[nv], ph[0], vh4);
                mma16816(o[nv], pl[0], vh4);
                mma16816(o[nv], ph[0], vl4);
                mma16816(o[nv], ph[1], vh4 + 2);
                mma16816(o[nv], pl[1], vh4 + 2);
                mma16816(o[nv], ph[1], vl4 + 2);
            }
        }
    }

    // epilogue: write g_atth hi/lo directly (skips fp32 round trip + conv kernel)
    float inv0 = 1.f / l0, inv1 = 1.f / l1;
    const size_t nATT = (size_t)MTOT * HH * VDIM;
    __nv_bfloat16* op0 = g_atth + (size_t)(b*TT + qr0) * (HH*VDIM) + h*VDIM;
    __nv_bfloat16* op1 = op0 + (size_t)8 * (HH*VDIM);
#pragma unroll
    for (int nv = 0; nv < 16; nv++) {
        int d = nv*8 + qc;
        float v00 = o[nv][0] * inv0, v01 = o[nv][1] * inv0;
        float v10 = o[nv][2] * inv1, v11 = o[nv][3] * inv1;
        __nv_bfloat16 h00 = __float2bfloat16(v00);
        __nv_bfloat16 h01 = __float2bfloat16(v01);
        __nv_bfloat16 h10 = __float2bfloat16(v10);
        __nv_bfloat16 h11 = __float2bfloat16(v11);
        op0[d]            = h00;
        op0[d + 1]        = h01;
        op1[d]            = h10;
        op1[d + 1]        = h11;
        op0[nATT + d]     = __float2bfloat16(v00 - __bfloat162float(h00));
        op0[nATT + d + 1] = __float2bfloat16(v01 - __bfloat162float(h01));
        op1[nATT + d]     = __float2bfloat16(v10 - __bfloat162float(h10));
        op1[nATT + d + 1] = __float2bfloat16(v11 - __bfloat162float(h11));
    }
}

// ---------------- launch ----------------
static inline void conv_launch(const float* src, __nv_bfloat16* dst, size_t n)
{
    conv_hilo<<<(unsigned)((n + 255) / 256), 256>>>(src, dst, n);
}

extern "C" void kernel_launch(void* const* d_in, const int* in_sizes, int n_in,
                              void* d_out, int out_size)
{
    const float* x       = (const float*)d_in[0];
    const float* wq_w    = (const float*)d_in[1];
    const float* wq_b    = (const float*)d_in[2];
    const float* wkv_a_w = (const float*)d_in[3];
    const float* wkv_a_b = (const float*)d_in[4];
    const float* wkv_b_w = (const float*)d_in[5];
    const float* wkv_b_b = (const float*)d_in[6];
    const float* wo_w    = (const float*)d_in[7];
    const float* wo_b    = (const float*)d_in[8];
    const float* cosv    = (const float*)d_in[9];
    const float* sinv    = (const float*)d_in[10];
    float* out = (float*)d_out;

    float *Qp, *KVAp, *KVp;
    cudaGetSymbolAddress((void**)&Qp,   g_Q);
    cudaGetSymbolAddress((void**)&KVAp, g_KVA);
    cudaGetSymbolAddress((void**)&KVp,  g_KV);

    __nv_bfloat16 *xh, *wqh, *wkvah, *wkvbh, *woh, *kvnh, *atth;
    cudaGetSymbolAddress((void**)&xh,    g_xh);
    cudaGetSymbolAddress((void**)&wqh,   g_wqh);
    cudaGetSymbolAddress((void**)&wkvah, g_wkvah);
    cudaGetSymbolAddress((void**)&wkvbh, g_wkvbh);
    cudaGetSymbolAddress((void**)&woh,   g_woh);
    cudaGetSymbolAddress((void**)&kvnh,  g_kvnh);
    cudaGetSymbolAddress((void**)&atth,  g_atth);

    const size_t nX    = (size_t)MTOT * DIM;
    const size_t nWQ   = (size_t)(HH*QKD) * DIM;
    const size_t nWKVA = (size_t)(KVR+ROPE) * DIM;
    const size_t nWKVB = (size_t)(HH*(NOPE+VDIM)) * KVR;
    const size_t nWO   = (size_t)DIM * (HH*VDIM);
    const size_t nKVN  = (size_t)MTOT * KVR;
    const size_t nATT  = (size_t)MTOT * HH * VDIM;
    const size_t nQK   = (size_t)MTOT * HH * QKD;

    // conversions (weights + x)
    conv_launch(x,       xh,    nX);
    conv_launch(wq_w,    wqh,   nWQ);
    conv_launch(wkv_a_w, wkvah, nWKVA);
    conv_launch(wkv_b_w, wkvbh, nWKVB);
    conv_launch(wo_w,    woh,   nWO);

    // 1) q = x @ wq^T + b
    gemm_hmma<<<dim3(3072/128, MTOT/128), 256>>>(xh, nX, wqh, nWQ, wq_b, Qp, MTOT, HH*QKD, DIM);
    // 2) kv_a = x @ wkv_a^T + b
    gemm_hmma<<<dim3((KVR+ROPE+127)/128, MTOT/128), 256>>>(xh, nX, wkvah, nWKVA, wkv_a_b, KVAp, MTOT, KVR+ROPE, DIM);
    // 3) rms norm (-> bf16 hi/lo direct) + k rope
    kva_post_kernel<<<MTOT, 128>>>(cosv, sinv);
    // 4) kv = norm @ wkv_b^T + b
    gemm_hmma<<<dim3(HH*(NOPE+VDIM)/128, MTOT/128), 256>>>(kvnh, nKVN, wkvbh, nWKVB, wkv_b_b, KVp, MTOT, HH*(NOPE+VDIM), KVR);
    // 5) build attention tensors (q rope+scale fused into build_qk_hl)
    build_qk_hl<<<(unsigned)((nQK + 255) / 256), 256>>>(cosv, sinv);
    build_v_hl<<<dim3(TT/32, VDIM/32, BB*HH), dim3(32, 8)>>>();
    // 6) flash attention (HMMA) -> writes g_atth hi/lo directly
    cudaFuncSetAttribute(attn_hmma, cudaFuncAttributeMaxDynamicSharedMemorySize, ATT_SMEM_B);
    attn_hmma<<<dim3(TT/128, HH, BB), 256, ATT_SMEM_B>>>();
    // 7) out = att @ wo^T + b
    gemm_hmma<<<dim3(DIM/128, MTOT/128), 256>>>(atth, nATT, woh, nWO, wo_b, out, MTOT, DIM, HH*VDIM);
}

// round 10
// speedup vs baseline: 6.1485x; 1.0104x over previous
#include <cuda_runtime.h>
#include <cuda_bf16.h>
#include <math.h>
#include <stdint.h>

// ---------------- problem constants ----------------
#define BB 4
#define TT 2048
#define DIM 1024
#define HH 16
#define NOPE 128
#define ROPE 64
#define VDIM 128
#define KVR 512
#define QKD 192            // NOPE + ROPE
#define MTOT (BB*TT)       // 8192
#define SCALE_F (0.07216878364870323f)  // 192^-0.5

// ---------------- fp32 scratch ----------------
__device__ __align__(16) float g_Q  [(size_t)MTOT * HH * QKD];   // raw q proj (pre-rope)
__device__ __align__(16) float g_KVA[(size_t)MTOT * (KVR+ROPE)];
__device__ __align__(16) float g_KR [(size_t)MTOT * ROPE];
__device__ __align__(16) float g_KV [(size_t)MTOT * HH * (NOPE+VDIM)];

// ---------------- bf16 hi/lo planes for GEMMs ----------
__device__ __align__(16) __nv_bfloat16 g_xh   [2 * (size_t)MTOT * DIM];
__device__ __align__(16) __nv_bfloat16 g_wqh  [2 * (size_t)(HH*QKD) * DIM];
__device__ __align__(16) __nv_bfloat16 g_wkvah[2 * (size_t)(KVR+ROPE) * DIM];
__device__ __align__(16) __nv_bfloat16 g_wkvbh[2 * (size_t)(HH*(NOPE+VDIM)) * KVR];
__device__ __align__(16) __nv_bfloat16 g_woh  [2 * (size_t)DIM * (HH*VDIM)];
__device__ __align__(16) __nv_bfloat16 g_kvnh [2 * (size_t)MTOT * KVR];
__device__ __align__(16) __nv_bfloat16 g_atth [2 * (size_t)MTOT * HH * VDIM];

// ---------------- bf16 hi/lo attention tensors ----------
__device__ __align__(16) __nv_bfloat16 g_qhl[2 * (size_t)MTOT * HH * QKD];
__device__ __align__(16) __nv_bfloat16 g_khl[2 * (size_t)MTOT * HH * QKD];
__device__ __align__(16) __nv_bfloat16 g_vhl[2 * (size_t)MTOT * HH * VDIM];

// ---------------- fp32 -> (hi, lo) bf16 planes ----------------
__global__ void conv_hilo(const float* __restrict__ src, __nv_bfloat16* __restrict__ dst, size_t n)
{
    size_t i = (size_t)blockIdx.x * blockDim.x + threadIdx.x;
    if (i >= n) return;
    float v = src[i];
    __nv_bfloat16 h = __float2bfloat16(v);
    dst[i]     = h;
    dst[n + i] = __float2bfloat16(v - __bfloat162float(h));
}

// ---------------- HMMA helpers ----------------
__device__ __forceinline__ void ldsm4(uint32_t* r, uint32_t addr) {
    asm volatile("ldmatrix.sync.aligned.m8n8.x4.shared.b16 {%0,%1,%2,%3},[%4];"
                 : "=r"(r[0]), "=r"(r[1]), "=r"(r[2]), "=r"(r[3]) : "r"(addr));
}
__device__ __forceinline__ void mma16816(float* c, const uint32_t* a, const uint32_t* b) {
    asm volatile(
        "mma.sync.aligned.m16n8k16.row.col.f32.bf16.bf16.f32 "
        "{%0,%1,%2,%3},{%4,%5,%6,%7},{%8,%9},{%0,%1,%2,%3};"
        : "+f"(c[0]), "+f"(c[1]), "+f"(c[2]), "+f"(c[3])
        : "r"(a[0]), "r"(a[1]), "r"(a[2]), "r"(a[3]), "r"(b[0]), "r"(b[1]));
}
__device__ __forceinline__ void mma16816b(float* c, const uint32_t* a, uint32_t b0, uint32_t b1) {
    asm volatile(
        "mma.sync.aligned.m16n8k16.row.col.f32.bf16.bf16.f32 "
        "{%0,%1,%2,%3},{%4,%5,%6,%7},{%8,%9},{%0,%1,%2,%3};"
        : "+f"(c[0]), "+f"(c[1]), "+f"(c[2]), "+f"(c[3])
        : "r"(a[0]), "r"(a[1]), "r"(a[2]), "r"(a[3]), "r"(b0), "r"(b1));
}
__device__ __forceinline__ uint32_t pack_bf2(__nv_bfloat16 a, __nv_bfloat16 b) {
    __nv_bfloat162 t; t.x = a; t.y = b;
    return *(uint32_t*)&t;
}
__device__ __forceinline__ uint32_t smem_u32(const void* p) {
    uint32_t a;
    asm("{ .reg .u64 t; cvta.to.shared.u64 t, %1; cvt.u32.u64 %0, t; }" : "=r"(a) : "l"(p));
    return a;
}
__device__ __forceinline__ void cp16(uint32_t d, const void* s) {
    asm volatile("cp.async.cg.shared.global [%0],[%1],16;" :: "r"(d), "l"(s));
}
__device__ __forceinline__ void cp16z(uint32_t d, const void* s, unsigned sz) {
    asm volatile("cp.async.cg.shared.global [%0],[%1],16,%2;" :: "r"(d), "l"(s), "r"(sz));
}
__device__ __forceinline__ void cp_commit() { asm volatile("cp.async.commit_group;"); }
template <int N>
__device__ __forceinline__ void cp_wait() {
    asm volatile("cp.async.wait_group %0;" :: "n"(N) : "memory");
}

// ---------------- HMMA GEMM (cp.async 2-stage): C[M,N] = A@B^T + bias ----
// BM=BN=128, BK=32, 256 threads, warps 4(m)x2(n), warp tile 32x64.
#define LDPAD 40   // bf16 elems per smem row (80B, conflict-free ldmatrix)
#define G_PLANE_B (128 * LDPAD * 2)                 // one plane, bytes (10240)
#define G_AS_B    (2 * 2 * G_PLANE_B)               // A: 2 stages x 2 planes
#define G_SMEM_B  (2 * G_AS_B)                      // + B same size = 81920

__global__ __launch_bounds__(256, 2) void gemm_hmma(
    const __nv_bfloat16* __restrict__ A, size_t aPlane,
    const __nv_bfloat16* __restrict__ B, size_t bPlane,
    const float* __restrict__ bias, float* __restrict__ C,
    int M, int N, int K)
{
    extern __shared__ char smraw[];
    const uint32_t sbase = smem_u32(smraw);

    const int tid  = threadIdx.x;
    const int lane = tid & 31;
    const int wid  = tid >> 5;
    const int brow = blockIdx.y * 128;
    const int bcol = blockIdx.x * 128;

    const int lc = tid & 3;        // k-chunk (8 bf16 = 16B)
    const int lr = tid >> 2;       // 0..63 -> rows lr, lr+64

    const int wm = (wid & 3) * 32;
    const int wn = (wid >> 2) * 64;

    float acc[2][8][4];
#pragma unroll
    for (int mi = 0; mi < 2; mi++)
#pragma unroll
        for (int ni = 0; ni < 8; ni++)
#pragma unroll
            for (int e = 0; e < 4; e++) acc[mi][ni][e] = 0.f;

    // smem addresses for this thread's cp.async destinations
    const uint32_t rowoff0 = (uint32_t)(lr * LDPAD + lc * 8) * 2;
    const uint32_t rowoff1 = (uint32_t)((lr + 64) * LDPAD + lc * 8) * 2;

    // global source bases
    const int arow0 = brow + lr, arow1 = brow + lr + 64;
    const int ncol0 = bcol + lr, ncol1 = bcol + lr + 64;
    const int nc0 = ncol0 < N ? ncol0 : 0;
    const int nc1 = ncol1 < N ? ncol1 : 0;
    const unsigned bz0 = ncol0 < N ? 16u : 0u;
    const unsigned bz1 = ncol1 < N ? 16u : 0u;

    const int nch = K / 32;

    // issue loads for stage s covering k-chunk c
    auto stage_load = [&](int c, int s) {
        const int kk = c * 32 + lc * 8;
        const uint32_t as = sbase + (uint32_t)s * 2 * G_PLANE_B;
        const uint32_t bs = sbase + G_AS_B + (uint32_t)s * 2 * G_PLANE_B;
        const __nv_bfloat16* a0 = A + (size_t)arow0 * K + kk;
        const __nv_bfloat16* a1 = A + (size_t)arow1 * K + kk;
        cp16(as + rowoff0, a0);
        cp16(as + rowoff1, a1);
        cp16(as + G_PLANE_B + rowoff0, a0 + aPlane);
        cp16(as + G_PLANE_B + rowoff1, a1 + aPlane);
        const __nv_bfloat16* b0 = B + (size_t)nc0 * K + kk;
        const __nv_bfloat16* b1 = B + (size_t)nc1 * K + kk;
        cp16z(bs + rowoff0, b0, bz0);
        cp16z(bs + rowoff1, b1, bz1);
        cp16z(bs + G_PLANE_B + rowoff0, b0 + bPlane, bz0);
        cp16z(bs + G_PLANE_B + rowoff1, b1 + bPlane, bz1);
        cp_commit();
    };

    stage_load(0, 0);
    if (nch > 1) stage_load(1, 1);

    for (int c = 0; c < nch; c++) {
        const int s = c & 1;
        cp_wait<1>();
        __syncthreads();

        const uint32_t aS = sbase + (uint32_t)s * 2 * G_PLANE_B;
        const uint32_t bS = sbase + G_AS_B + (uint32_t)s * 2 * G_PLANE_B;

#pragma unroll
        for (int ks = 0; ks < 2; ks++) {
            const int kc = ks * 16;
            uint32_t a_h[2][4], a_l[2][4];
#pragma unroll
            for (int mi = 0; mi < 2; mi++) {
                uint32_t addr = aS + ((wm + mi*16 + (lane & 15)) * LDPAD + kc + (lane >> 4) * 8) * 2;
                ldsm4(a_h[mi], addr);
                ldsm4(a_l[mi], addr + G_PLANE_B);
            }
            // process B in two np-pairs to bound register pressure
#pragma unroll
            for (int half2 = 0; half2 < 2; half2++) {
                uint32_t b_h[2][4], b_l[2][4];
#pragma unroll
                for (int j = 0; j < 2; j++) {
                    const int np = half2*2 + j;
                    uint32_t baddr = bS + ((wn + np*16 + (lane & 15)) * LDPAD + kc + (lane >> 4) * 8) * 2;
                    ldsm4(b_h[j], baddr);
                    ldsm4(b_l[j], baddr + G_PLANE_B);
                }
#pragma unroll
                for (int j = 0; j < 2; j++) {
                    const int np = half2*2 + j;
#pragma unroll
                    for (int hf = 0; hf < 2; hf++) {
                        const int ni = np*2 + hf;
#pragma unroll
                        for (int mi = 0; mi < 2; mi++) {
                            mma16816b(acc[mi][ni], a_h[mi], b_h[j][hf], b_h[j][hf+2]);
                            mma16816b(acc[mi][ni], a_l[mi], b_h[j][hf], b_h[j][hf+2]);
                            mma16816b(acc[mi][ni], a_h[mi], b_l[j][hf], b_l[j][hf+2]);
                        }
                    }
                }
            }
        }
        __syncthreads();
        if (c + 2 < nch) stage_load(c + 2, s);
    }

#pragma unroll
    for (int mi = 0; mi < 2; mi++) {
        int r0 = brow + wm + mi*16 + (lane >> 2);
#pragma unroll
        for (int ni = 0; ni < 8; ni++) {
            int c0 = bcol + wn + ni*8 + (lane & 3) * 2;
            if (c0 < N) {
                float b0 = bias[c0], b1 = bias[c0+1];
                C[(size_t)r0 * N + c0]       = acc[mi][ni][0] + b0;
                C[(size_t)r0 * N + c0 + 1]   = acc[mi][ni][1] + b1;
                C[(size_t)(r0+8) * N + c0]   = acc[mi][ni][2] + b0;
                C[(size_t)(r0+8) * N + c0+1] = acc[mi][ni][3] + b1;
            }
        }
    }
}

// ---------------- kv_a post: rms_norm -> g_kvnh (hi/lo), rope -> g_KR ----------------
__global__ __launch_bounds__(128) void kva_post_kernel(const float* __restrict__ cosv,
                                                       const float* __restrict__ sinv)
{
    __shared__ float red[4];
    const int bt = blockIdx.x;
    const int t  = bt % TT;
    const float* a = g_KVA + (size_t)bt * (KVR + ROPE);
    const int tid = threadIdx.x;
    const size_t nKVN = (size_t)MTOT * KVR;

    float ss = 0.f;
    for (int d = tid; d < KVR; d += 128) { float v = a[d]; ss += v * v; }
#pragma unroll
    for (int off = 16; off; off >>= 1) ss += __shfl_xor_sync(0xffffffffu, ss, off);
    if ((tid & 31) == 0) red[tid >> 5] = ss;
    __syncthreads();
    float total = red[0] + red[1] + red[2] + red[3];
    float r = rsqrtf(total * (1.0f / KVR) + 1e-6f);

    __nv_bfloat16* o = g_kvnh + (size_t)bt * KVR;
    for (int d = tid; d < KVR; d += 128) {
        float v = a[d] * r;
        __nv_bfloat16 hi = __float2bfloat16(v);
        o[d]        = hi;
        o[nKVN + d] = __float2bfloat16(v - __bfloat162float(hi));
    }

    if (tid < 32) {
        int i = tid;
        float c = cosv[t*32 + i];
        float s = sinv[t*32 + i];
        float xr = a[KVR + 2*i];
        float xi = a[KVR + 2*i + 1];
        g_KR[(size_t)bt * ROPE + 2*i]     = xr*c - xi*s;
        g_KR[(size_t)bt * ROPE + 2*i + 1] = xr*s + xi*c;
    }
}

// ---------------- build Q/K hi-lo tensors [b,h,t,192]; q-rope+scale fused ----------------
__global__ void build_qk_hl(const float* __restrict__ cosv, const float* __restrict__ sinv)
{
    const size_t NQ = (size_t)MTOT * HH * QKD;
    size_t i = (size_t)blockIdx.x * blockDim.x + threadIdx.x;
    if (i >= NQ) return;
    int d = (int)(i % QKD);
    size_t r = i / QKD;
    int h = (int)(r % HH);
    size_t bt = r / HH;
    int t = (int)(bt % TT);
    int b = (int)(bt / TT);
    size_t dst = (((size_t)b*HH + h)*TT + t)*QKD + d;

    float qv;
    if (d < NOPE) {
        qv = g_Q[(bt*HH + h)*QKD + d] * SCALE_F;
    } else {
        int i2 = d - NOPE;         // 0..63
        int pi = i2 >> 1;          // pair index
        float c = cosv[t*32 + pi];
        float s = sinv[t*32 + pi];
        size_t base = (bt*HH + h)*QKD + NOPE + 2*pi;
        float xr = g_Q[base];
        float xi = g_Q[base + 1];
        qv = ((i2 & 1) ? (xr*s + xi*c) : (xr*c - xi*s)) * SCALE_F;
    }
    __nv_bfloat16 qh = __float2bfloat16(qv);
    g_qhl[dst]      = qh;
    g_qhl[NQ + dst] = __float2bfloat16(qv - __bfloat162float(qh));

    float kv;
    if (d < NOPE) kv = g_KV[(bt*HH + h)*(NOPE+VDIM) + d];
    else          kv = g_KR[bt*ROPE + (d - NOPE)];
    __nv_bfloat16 kh = __float2bfloat16(kv);
    g_khl[dst]      = kh;
    g_khl[NQ + dst] = __float2bfloat16(kv - __bfloat162float(kh));
}

// ---------------- build V transposed hi-lo [b,h,d,t] ----------------
__global__ void build_v_hl()
{
    __shared__ float tile[32][33];
    const size_t NV = (size_t)MTOT * HH * VDIM;
    const int bh = blockIdx.z;
    const int b = bh / HH, h = bh % HH;
    const int t0 = blockIdx.x * 32;
    const int d0 = blockIdx.y * 32;
    const int tx = threadIdx.x, ty = threadIdx.y;

#pragma unroll
    for (int k = 0; k < 4; k++) {
        int t = t0 + ty + k*8;
        tile[ty + k*8][tx] = g_KV[((size_t)(b*TT + t)*HH + h)*(NOPE+VDIM) + NOPE + d0 + tx];
    }
    __syncthreads();
#pragma unroll
    for (int k = 0; k < 4; k++) {
        int d = d0 + ty + k*8;
        float v = tile[tx][ty + k*8];
        size_t dst = ((size_t)bh*VDIM + d)*TT + t0 + tx;
        __nv_bfloat16 hi = __float2bfloat16(v);
        g_vhl[dst]      = hi;
        g_vhl[NV + dst] = __float2bfloat16(v - __bfloat162float(hi));
    }
}

// ---------------- HMMA flash attention ----------------
#define QS_STRIDE 200
#define VS_STRIDE 72
#define SM_Q_ELEMS (2*128*QS_STRIDE)
#define SM_K_ELEMS (2*64*QS_STRIDE)
#define SM_V_ELEMS (2*128*VS_STRIDE)
#define ATT_SMEM_B ((SM_Q_ELEMS + SM_K_ELEMS + SM_V_ELEMS) * 2)

__global__ __launch_bounds__(256, 1) void attn_hmma()
{
    extern __shared__ __nv_bfloat16 smb[];
    __nv_bfloat16* qs = smb;
    __nv_bfloat16* ks = smb + SM_Q_ELEMS;
    __nv_bfloat16* vs = smb + SM_Q_ELEMS + SM_K_ELEMS;

    const int b = blockIdx.z, h = blockIdx.y;
    const int qbase = blockIdx.x * 128;
    const int tid = threadIdx.x, lane = tid & 31, w = tid >> 5;
    const size_t NQ = (size_t)MTOT * HH * QKD;
    const size_t NV = (size_t)MTOT * HH * VDIM;
    const size_t bh = (size_t)b * HH + h;

    {
        const __nv_bfloat16* qg = g_qhl + (bh*TT + qbase)*QKD;
        for (int i = tid; i < 2*128*24; i += 256) {
            int p = i / (128*24);
            int rem = i % (128*24);
            int r = rem / 24, c = rem % 24;
            *(uint4*)&qs[p*(128*QS_STRIDE) + r*QS_STRIDE + c*8] =
                *(const uint4*)&qg[(size_t)p*NQ + (size_t)r*QKD + c*8];
        }
    }

    const int g  = lane >> 2;
    const int qc = (lane & 3) * 2;
    const int qr0 = qbase + w*16 + g;

    float m0 = -1e30f, m1 = -1e30f, l0 = 0.f, l1 = 0.f;
    float o[16][4];
#pragma unroll
    for (int nv = 0; nv < 16; nv++)
#pragma unroll
        for (int e = 0; e < 4; e++) o[nv][e] = 0.f;

    const uint32_t sQ = smem_u32(qs);
    const uint32_t sK = smem_u32(ks);
    const uint32_t sV = smem_u32(vs);
    const uint32_t QPB = 128*QS_STRIDE*2;
    const uint32_t KPB = 64*QS_STRIDE*2;
    const uint32_t VPB = 128*VS_STRIDE*2;

    const int ntiles = qbase/64 + 2;
    for (int kb = 0; kb < ntiles; kb++) {
        const int kbase = kb * 64;
        __syncthreads();
        {
            const __nv_bfloat16* kg = g_khl + (bh*TT + kbase)*QKD;
            for (int i = tid; i < 2*64*24; i += 256) {
                int p = i / (64*24);
                int rem = i % (64*24);
                int r = rem / 24, c = rem % 24;
                *(uint4*)&ks[p*(64*QS_STRIDE) + r*QS_STRIDE + c*8] =
                    *(const uint4*)&kg[(size_t)p*NQ + (size_t)r*QKD + c*8];
            }
            const __nv_bfloat16* vg = g_vhl + bh*VDIM*TT + kbase;
            for (int i = tid; i < 2*128*8; i += 256) {
                int p = i / (128*8);
                int rem = i % (128*8);
                int d = rem / 8, c = rem % 8;
                *(uint4*)&vs[p*(128*VS_STRIDE) + d*VS_STRIDE + c*8] =
                    *(const uint4*)&vg[(size_t)p*NV + (size_t)d*TT + c*8];
            }
        }
        __syncthreads();

        float s[8][4];
#pragma unroll
        for (int ni = 0; ni < 8; ni++)
#pragma unroll
            for (int e = 0; e < 4; e++) s[ni][e] = 0.f;

#pragma unroll
        for (int kp = 0; kp < 6; kp++) {
            uint32_t ah0[4], ah1[4], al0[4], al1[4];
            uint32_t ab = sQ + ((w*16 + (lane & 15))*QS_STRIDE + kp*32 + (lane >> 4)*8) * 2;
            ldsm4(ah0, ab);
            ldsm4(ah1, ab + 32);
            ldsm4(al0, ab + QPB);
            ldsm4(al1, ab + QPB + 32);
#pragma unroll
            for (int ni = 0; ni < 8; ni++) {
                uint32_t bb = sK + ((ni*8 + (lane & 7))*QS_STRIDE + kp*32 + (lane >> 3)*8) * 2;
                uint32_t bh4[4], bl4[4];
                ldsm4(bh4, bb);
                ldsm4(bl4, bb + KPB);
                mma16816(s[ni], ah0, bh4);
                mma16816(s[ni], al0, bh4);
                mma16816(s[ni], ah0, bl4);
                mma16816(s[ni], ah1, bh4 + 2);
                mma16816(s[ni], al1, bh4 + 2);
                mma16816(s[ni], ah1, bl4 + 2);
            }
        }

        if (kbase + 63 > qr0) {
#pragma unroll
            for (int ni = 0; ni < 8; ni++) {
                int col = kbase + ni*8 + qc;
                if (col     > qr0)     s[ni][0] = -1e30f;
                if (col + 1 > qr0)     s[ni][1] = -1e30f;
                if (col     > qr0 + 8) s[ni][2] = -1e30f;
                if (col + 1 > qr0 + 8) s[ni][3] = -1e30f;
            }
        }

        float rm0 = -1e30f, rm1 = -1e30f;
#pragma unroll
        for (int ni = 0; ni < 8; ni++) {
            rm0 = fmaxf(rm0, fmaxf(s[ni][0], s[ni][1]));
            rm1 = fmaxf(rm1, fmaxf(s[ni][2], s[ni][3]));
        }
        rm0 = fmaxf(rm0, __shfl_xor_sync(0xffffffffu, rm0, 1));
        rm0 = fmaxf(rm0, __shfl_xor_sync(0xffffffffu, rm0, 2));
        rm1 = fmaxf(rm1, __shfl_xor_sync(0xffffffffu, rm1, 1));
        rm1 = fmaxf(rm1, __shfl_xor_sync(0xffffffffu, rm1, 2));
        float nm0 = fmaxf(m0, rm0), nm1 = fmaxf(m1, rm1);
        float c0 = __expf(m0 - nm0), c1 = __expf(m1 - nm1);

        float rs0 = 0.f, rs1 = 0.f;
#pragma unroll
        for (int ni = 0; ni < 8; ni++) {
            s[ni][0] = __expf(s[ni][0] - nm0); rs0 += s[ni][0];
            s[ni][1] = __expf(s[ni][1] - nm0); rs0 += s[ni][1];
            s[ni][2] = __expf(s[ni][2] - nm1); rs1 += s[ni][2];
            s[ni][3] = __expf(s[ni][3] - nm1); rs1 += s[ni][3];
        }
        rs0 += __shfl_xor_sync(0xffffffffu, rs0, 1);
        rs0 += __shfl_xor_sync(0xffffffffu, rs0, 2);
        rs1 += __shfl_xor_sync(0xffffffffu, rs1, 1);
        rs1 += __shfl_xor_sync(0xffffffffu, rs1, 2);
        l0 = l0 * c0 + rs0;
        l1 = l1 * c1 + rs1;
        m0 = nm0; m1 = nm1;
#pragma unroll
        for (int nv = 0; nv < 16; nv++) {
            o[nv][0] *= c0; o[nv][1] *= c0;
            o[nv][2] *= c1; o[nv][3] *= c1;
        }

#pragma unroll
        for (int kp = 0; kp < 2; kp++) {
            uint32_t ph[2][4], pl[2][4];
#pragma unroll
            for (int ss2 = 0; ss2 < 2; ss2++) {
                int n0 = kp*4 + ss2*2;
#pragma unroll
                for (int half = 0; half < 2; half++) {
                    int nt = n0 + half;
                    float v0 = s[nt][0], v1 = s[nt][1], v2 = s[nt][2], v3 = s[nt][3];
                    __nv_bfloat16 h0 = __float2bfloat16(v0);
                    __nv_bfloat16 h1 = __float2bfloat16(v1);
                    __nv_bfloat16 h2 = __float2bfloat16(v2);
                    __nv_bfloat16 h3 = __float2bfloat16(v3);
                    ph[ss2][half*2 + 0] = pack_bf2(h0, h1);
                    ph[ss2][half*2 + 1] = pack_bf2(h2, h3);
                    pl[ss2][half*2 + 0] = pack_bf2(__float2bfloat16(v0 - __bfloat162float(h0)),
                                                   __float2bfloat16(v1 - __bfloat162float(h1)));
                    pl[ss2][half*2 + 1] = pack_bf2(__float2bfloat16(v2 - __bfloat162float(h2)),
                                                   __float2bfloat16(v3 - __bfloat162float(h3)));
                }
            }
#pragma unroll
            for (int nv = 0; nv < 16; nv++) {
                uint32_t vb = sV + ((nv*8 + (lane & 7))*VS_STRIDE + kp*32 + (lane >> 3)*8) * 2;
                uint32_t vh4[4], vl4[4];
                ldsm4(vh4, vb);
                ldsm4(vl4, vb + VPB);
                mma16816(o[nv], ph[0], vh4);
                mma16816(o[nv], pl[0], vh4);
                mma16816(o[nv], ph[0], vl4);
                mma16816(o[nv], ph[1], vh4 + 2);
                mma16816(o[nv], pl[1], vh4 + 2);
                mma16816(o[nv], ph[1], vl4 + 2);
            }
        }
    }

    // epilogue: write g_atth hi/lo directly
    float inv0 = 1.f / l0, inv1 = 1.f / l1;
    const size_t nATT = (size_t)MTOT * HH * VDIM;
    __nv_bfloat16* op0 = g_atth + (size_t)(b*TT + qr0) * (HH*VDIM) + h*VDIM;
    __nv_bfloat16* op1 = op0 + (size_t)8 * (HH*VDIM);
#pragma unroll
    for (int nv = 0; nv < 16; nv++) {
        int d = nv*8 + qc;
        float v00 = o[nv][0] * inv0, v01 = o[nv][1] * inv0;
        float v10 = o[nv][2] * inv1, v11 = o[nv][3] * inv1;
        __nv_bfloat16 h00 = __float2bfloat16(v00);
        __nv_bfloat16 h01 = __float2bfloat16(v01);
        __nv_bfloat16 h10 = __float2bfloat16(v10);
        __nv_bfloat16 h11 = __float2bfloat16(v11);
        op0[d]            = h00;
        op0[d + 1]        = h01;
        op1[d]            = h10;
        op1[d + 1]        = h11;
        op0[nATT + d]     = __float2bfloat16(v00 - __bfloat162float(h00));
        op0[nATT + d + 1] = __float2bfloat16(v01 - __bfloat162float(h01));
        op1[nATT + d]     = __float2bfloat16(v10 - __bfloat162float(h10));
        op1[nATT + d + 1] = __float2bfloat16(v11 - __bfloat162float(h11));
    }
}

// ---------------- launch ----------------
static inline void conv_launch(const float* src, __nv_bfloat16* dst, size_t n)
{
    conv_hilo<<<(unsigned)((n + 255) / 256), 256>>>(src, dst, n);
}

extern "C" void kernel_launch(void* const* d_in, const int* in_sizes, int n_in,
                              void* d_out, int out_size)
{
    const float* x       = (const float*)d_in[0];
    const float* wq_w    = (const float*)d_in[1];
    const float* wq_b    = (const float*)d_in[2];
    const float* wkv_a_w = (const float*)d_in[3];
    const float* wkv_a_b = (const float*)d_in[4];
    const float* wkv_b_w = (const float*)d_in[5];
    const float* wkv_b_b = (const float*)d_in[6];
    const float* wo_w    = (const float*)d_in[7];
    const float* wo_b    = (const float*)d_in[8];
    const float* cosv    = (const float*)d_in[9];
    const float* sinv    = (const float*)d_in[10];
    float* out = (float*)d_out;

    float *Qp, *KVAp, *KVp;
    cudaGetSymbolAddress((void**)&Qp,   g_Q);
    cudaGetSymbolAddress((void**)&KVAp, g_KVA);
    cudaGetSymbolAddress((void**)&KVp,  g_KV);

    __nv_bfloat16 *xh, *wqh, *wkvah, *wkvbh, *woh, *kvnh, *atth;
    cudaGetSymbolAddress((void**)&xh,    g_xh);
    cudaGetSymbolAddress((void**)&wqh,   g_wqh);
    cudaGetSymbolAddress((void**)&wkvah, g_wkvah);
    cudaGetSymbolAddress((void**)&wkvbh, g_wkvbh);
    cudaGetSymbolAddress((void**)&woh,   g_woh);
    cudaGetSymbolAddress((void**)&kvnh,  g_kvnh);
    cudaGetSymbolAddress((void**)&atth,  g_atth);

    const size_t nX    = (size_t)MTOT * DIM;
    const size_t nWQ   = (size_t)(HH*QKD) * DIM;
    const size_t nWKVA = (size_t)(KVR+ROPE) * DIM;
    const size_t nWKVB = (size_t)(HH*(NOPE+VDIM)) * KVR;
    const size_t nWO   = (size_t)DIM * (HH*VDIM);
    const size_t nKVN  = (size_t)MTOT * KVR;
    const size_t nATT  = (size_t)MTOT * HH * VDIM;
    const size_t nQK   = (size_t)MTOT * HH * QKD;

    cudaFuncSetAttribute(gemm_hmma, cudaFuncAttributeMaxDynamicSharedMemorySize, G_SMEM_B);

    // conversions (weights + x)
    conv_launch(x,       xh,    nX);
    conv_launch(wq_w,    wqh,   nWQ);
    conv_launch(wkv_a_w, wkvah, nWKVA);
    conv_launch(wkv_b_w, wkvbh, nWKVB);
    conv_launch(wo_w,    woh,   nWO);

    // 1) q = x @ wq^T + b
    gemm_hmma<<<dim3(3072/128, MTOT/128), 256, G_SMEM_B>>>(xh, nX, wqh, nWQ, wq_b, Qp, MTOT, HH*QKD, DIM);
    // 2) kv_a = x @ wkv_a^T + b
    gemm_hmma<<<dim3((KVR+ROPE+127)/128, MTOT/128), 256, G_SMEM_B>>>(xh, nX, wkvah, nWKVA, wkv_a_b, KVAp, MTOT, KVR+ROPE, DIM);
    // 3) rms norm (-> bf16 hi/lo direct) + k rope
    kva_post_kernel<<<MTOT, 128>>>(cosv, sinv);
    // 4) kv = norm @ wkv_b^T + b
    gemm_hmma<<<dim3(HH*(NOPE+VDIM)/128, MTOT/128), 256, G_SMEM_B>>>(kvnh, nKVN, wkvbh, nWKVB, wkv_b_b, KVp, MTOT, HH*(NOPE+VDIM), KVR);
    // 5) build attention tensors (q rope+scale fused into build_qk_hl)
    build_qk_hl<<<(unsigned)((nQK + 255) / 256), 256>>>(cosv, sinv);
    build_v_hl<<<dim3(TT/32, VDIM/32, BB*HH), dim3(32, 8)>>>();
    // 6) flash attention (HMMA) -> writes g_atth hi/lo directly
    cudaFuncSetAttribute(attn_hmma, cudaFuncAttributeMaxDynamicSharedMemorySize, ATT_SMEM_B);
    attn_hmma<<<dim3(TT/128, HH, BB), 256, ATT_SMEM_B>>>();
    // 7) out = att @ wo^T + b
    gemm_hmma<<<dim3(DIM/128, MTOT/128), 256, G_SMEM_B>>>(atth, nATT, woh, nWO, wo_b, out, MTOT, DIM, HH*VDIM);
}

// round 11
// speedup vs baseline: 7.0768x; 1.1510x over previous
#include <cuda_runtime.h>
#include <cuda_fp16.h>
#include <math.h>
#include <stdint.h>

// ---------------- problem constants ----------------
#define BB 4
#define TT 2048
#define DIM 1024
#define HH 16
#define NOPE 128
#define ROPE 64
#define VDIM 128
#define KVR 512
#define QKD 192            // NOPE + ROPE
#define MTOT (BB*TT)       // 8192
#define SCALE_F (0.07216878364870323f)  // 192^-0.5

// ---------------- fp32 scratch ----------------
__device__ __align__(16) float g_Q  [(size_t)MTOT * HH * QKD];   // raw q proj (pre-rope)
__device__ __align__(16) float g_KVA[(size_t)MTOT * (KVR+ROPE)];
__device__ __align__(16) float g_KR [(size_t)MTOT * ROPE];
__device__ __align__(16) float g_KV [(size_t)MTOT * HH * (NOPE+VDIM)];

// ---------------- fp16 hi/lo planes for GEMMs (lo plane used for A-side only) ----
__device__ __align__(16) __half g_xh   [2 * (size_t)MTOT * DIM];
__device__ __align__(16) __half g_wqh  [(size_t)(HH*QKD) * DIM];
__device__ __align__(16) __half g_wkvah[(size_t)(KVR+ROPE) * DIM];
__device__ __align__(16) __half g_wkvbh[(size_t)(HH*(NOPE+VDIM)) * KVR];
__device__ __align__(16) __half g_woh  [(size_t)DIM * (HH*VDIM)];
__device__ __align__(16) __half g_kvnh [2 * (size_t)MTOT * KVR];
__device__ __align__(16) __half g_atth [2 * (size_t)MTOT * HH * VDIM];

// ---------------- fp16 attention tensors ----------
// qhl: hi/lo [b][h][t][192]; khl: hi only; vh: hi only [b][h][d][t]
__device__ __align__(16) __half g_qhl[2 * (size_t)MTOT * HH * QKD];
__device__ __align__(16) __half g_khl[(size_t)MTOT * HH * QKD];
__device__ __align__(16) __half g_vhl[(size_t)MTOT * HH * VDIM];

// ---------------- fp32 -> fp16 conversions ----------------
__global__ void conv_hilo(const float* __restrict__ src, __half* __restrict__ dst, size_t n)
{
    size_t i = (size_t)blockIdx.x * blockDim.x + threadIdx.x;
    if (i >= n) return;
    float v = src[i];
    __half h = __float2half_rn(v);
    dst[i]     = h;
    dst[n + i] = __float2half_rn(v - __half2float(h));
}
__global__ void conv_hi(const float* __restrict__ src, __half* __restrict__ dst, size_t n)
{
    size_t i = (size_t)blockIdx.x * blockDim.x + threadIdx.x;
    if (i >= n) return;
    dst[i] = __float2half_rn(src[i]);
}

// ---------------- HMMA helpers (fp16 in, fp32 accum) ----------------
__device__ __forceinline__ void ldsm4(uint32_t* r, uint32_t addr) {
    asm volatile("ldmatrix.sync.aligned.m8n8.x4.shared.b16 {%0,%1,%2,%3},[%4];"
                 : "=r"(r[0]), "=r"(r[1]), "=r"(r[2]), "=r"(r[3]) : "r"(addr));
}
__device__ __forceinline__ void mma16816(float* c, const uint32_t* a, const uint32_t* b) {
    asm volatile(
        "mma.sync.aligned.m16n8k16.row.col.f32.f16.f16.f32 "
        "{%0,%1,%2,%3},{%4,%5,%6,%7},{%8,%9},{%0,%1,%2,%3};"
        : "+f"(c[0]), "+f"(c[1]), "+f"(c[2]), "+f"(c[3])
        : "r"(a[0]), "r"(a[1]), "r"(a[2]), "r"(a[3]), "r"(b[0]), "r"(b[1]));
}
__device__ __forceinline__ void mma16816b(float* c, const uint32_t* a, uint32_t b0, uint32_t b1) {
    asm volatile(
        "mma.sync.aligned.m16n8k16.row.col.f32.f16.f16.f32 "
        "{%0,%1,%2,%3},{%4,%5,%6,%7},{%8,%9},{%0,%1,%2,%3};"
        : "+f"(c[0]), "+f"(c[1]), "+f"(c[2]), "+f"(c[3])
        : "r"(a[0]), "r"(a[1]), "r"(a[2]), "r"(a[3]), "r"(b0), "r"(b1));
}
__device__ __forceinline__ uint32_t pack_h2(__half a, __half b) {
    __half2 t; t.x = a; t.y = b;
    return *(uint32_t*)&t;
}
__device__ __forceinline__ uint32_t smem_u32(const void* p) {
    uint32_t a;
    asm("{ .reg .u64 t; cvta.to.shared.u64 t, %1; cvt.u32.u64 %0, t; }" : "=r"(a) : "l"(p));
    return a;
}
__device__ __forceinline__ void cp16(uint32_t d, const void* s) {
    asm volatile("cp.async.cg.shared.global [%0],[%1],16;" :: "r"(d), "l"(s));
}
__device__ __forceinline__ void cp16z(uint32_t d, const void* s, unsigned sz) {
    asm volatile("cp.async.cg.shared.global [%0],[%1],16,%2;" :: "r"(d), "l"(s), "r"(sz));
}
__device__ __forceinline__ void cp_commit() { asm volatile("cp.async.commit_group;"); }
template <int N>
__device__ __forceinline__ void cp_wait() {
    asm volatile("cp.async.wait_group %0;" :: "n"(N) : "memory");
}

// ---------------- HMMA GEMM (cp.async 2-stage, fp16 2-term): C = A@B^T + bias ----
// BM=BN=128, BK=32, 256 threads, warps 4(m)x2(n), warp tile 32x64.
// A: hi+lo planes (fully corrected). B: hi plane only.
#define LDPAD 40   // fp16 elems per smem row (80B, conflict-free ldmatrix)
#define G_PLANE_B (128 * LDPAD * 2)                 // one plane, bytes (10240)
#define G_STAGE_B (3 * G_PLANE_B)                   // Ah, Al, Bh
#define G_SMEM_B  (2 * G_STAGE_B)                   // 61440

__global__ __launch_bounds__(256, 2) void gemm_hmma(
    const __half* __restrict__ A, size_t aPlane,
    const __half* __restrict__ B,
    const float* __restrict__ bias, float* __restrict__ C,
    int M, int N, int K)
{
    extern __shared__ char smraw[];
    const uint32_t sbase = smem_u32(smraw);

    const int tid  = threadIdx.x;
    const int lane = tid & 31;
    const int wid  = tid >> 5;
    const int brow = blockIdx.y * 128;
    const int bcol = blockIdx.x * 128;

    const int lc = tid & 3;        // k-chunk (8 fp16 = 16B)
    const int lr = tid >> 2;       // 0..63 -> rows lr, lr+64

    const int wm = (wid & 3) * 32;
    const int wn = (wid >> 2) * 64;

    float acc[2][8][4];
#pragma unroll
    for (int mi = 0; mi < 2; mi++)
#pragma unroll
        for (int ni = 0; ni < 8; ni++)
#pragma unroll
            for (int e = 0; e < 4; e++) acc[mi][ni][e] = 0.f;

    const uint32_t rowoff0 = (uint32_t)(lr * LDPAD + lc * 8) * 2;
    const uint32_t rowoff1 = (uint32_t)((lr + 64) * LDPAD + lc * 8) * 2;

    const int arow0 = brow + lr, arow1 = brow + lr + 64;
    const int ncol0 = bcol + lr, ncol1 = bcol + lr + 64;
    const int nc0 = ncol0 < N ? ncol0 : 0;
    const int nc1 = ncol1 < N ? ncol1 : 0;
    const unsigned bz0 = ncol0 < N ? 16u : 0u;
    const unsigned bz1 = ncol1 < N ? 16u : 0u;

    const int nch = K / 32;

    auto stage_load = [&](int c, int s) {
        const int kk = c * 32 + lc * 8;
        const uint32_t as = sbase + (uint32_t)s * G_STAGE_B;
        const uint32_t bs = as + 2 * G_PLANE_B;
        const __half* a0 = A + (size_t)arow0 * K + kk;
        const __half* a1 = A + (size_t)arow1 * K + kk;
        cp16(as + rowoff0, a0);
        cp16(as + rowoff1, a1);
        cp16(as + G_PLANE_B + rowoff0, a0 + aPlane);
        cp16(as + G_PLANE_B + rowoff1, a1 + aPlane);
        const __half* b0 = B + (size_t)nc0 * K + kk;
        const __half* b1 = B + (size_t)nc1 * K + kk;
        cp16z(bs + rowoff0, b0, bz0);
        cp16z(bs + rowoff1, b1, bz1);
        cp_commit();
    };

    stage_load(0, 0);
    if (nch > 1) stage_load(1, 1);

    for (int c = 0; c < nch; c++) {
        const int s = c & 1;
        cp_wait<1>();
        __syncthreads();

        const uint32_t aS = sbase + (uint32_t)s * G_STAGE_B;
        const uint32_t bS = aS + 2 * G_PLANE_B;

#pragma unroll
        for (int ks = 0; ks < 2; ks++) {
            const int kc = ks * 16;
            uint32_t a_h[2][4], a_l[2][4];
#pragma unroll
            for (int mi = 0; mi < 2; mi++) {
                uint32_t addr = aS + ((wm + mi*16 + (lane & 15)) * LDPAD + kc + (lane >> 4) * 8) * 2;
                ldsm4(a_h[mi], addr);
                ldsm4(a_l[mi], addr + G_PLANE_B);
            }
            uint32_t b_h[4][4];
#pragma unroll
            for (int np = 0; np < 4; np++) {
                uint32_t baddr = bS + ((wn + np*16 + (lane & 15)) * LDPAD + kc + (lane >> 4) * 8) * 2;
                ldsm4(b_h[np], baddr);
            }
#pragma unroll
            for (int np = 0; np < 4; np++) {
#pragma unroll
                for (int hf = 0; hf < 2; hf++) {
                    const int ni = np*2 + hf;
#pragma unroll
                    for (int mi = 0; mi < 2; mi++) {
                        mma16816b(acc[mi][ni], a_h[mi], b_h[np][hf], b_h[np][hf+2]);
                        mma16816b(acc[mi][ni], a_l[mi], b_h[np][hf], b_h[np][hf+2]);
                    }
                }
            }
        }
        __syncthreads();
        if (c + 2 < nch) stage_load(c + 2, s);
    }

#pragma unroll
    for (int mi = 0; mi < 2; mi++) {
        int r0 = brow + wm + mi*16 + (lane >> 2);
#pragma unroll
        for (int ni = 0; ni < 8; ni++) {
            int c0 = bcol + wn + ni*8 + (lane & 3) * 2;
            if (c0 < N) {
                float b0 = bias[c0], b1 = bias[c0+1];
                C[(size_t)r0 * N + c0]       = acc[mi][ni][0] + b0;
                C[(size_t)r0 * N + c0 + 1]   = acc[mi][ni][1] + b1;
                C[(size_t)(r0+8) * N + c0]   = acc[mi][ni][2] + b0;
                C[(size_t)(r0+8) * N + c0+1] = acc[mi][ni][3] + b1;
            }
        }
    }
}

// ---------------- kv_a post: rms_norm -> g_kvnh (fp16 hi/lo), rope -> g_KR ----------------
__global__ __launch_bounds__(128) void kva_post_kernel(const float* __restrict__ cosv,
                                                       const float* __restrict__ sinv)
{
    __shared__ float red[4];
    const int bt = blockIdx.x;
    const int t  = bt % TT;
    const float* a = g_KVA + (size_t)bt * (KVR + ROPE);
    const int tid = threadIdx.x;
    const size_t nKVN = (size_t)MTOT * KVR;

    float ss = 0.f;
    for (int d = tid; d < KVR; d += 128) { float v = a[d]; ss += v * v; }
#pragma unroll
    for (int off = 16; off; off >>= 1) ss += __shfl_xor_sync(0xffffffffu, ss, off);
    if ((tid & 31) == 0) red[tid >> 5] = ss;
    __syncthreads();
    float total = red[0] + red[1] + red[2] + red[3];
    float r = rsqrtf(total * (1.0f / KVR) + 1e-6f);

    __half* o = g_kvnh + (size_t)bt * KVR;
    for (int d = tid; d < KVR; d += 128) {
        float v = a[d] * r;
        __half hi = __float2half_rn(v);
        o[d]        = hi;
        o[nKVN + d] = __float2half_rn(v - __half2float(hi));
    }

    if (tid < 32) {
        int i = tid;
        float c = cosv[t*32 + i];
        float s = sinv[t*32 + i];
        float xr = a[KVR + 2*i];
        float xi = a[KVR + 2*i + 1];
        g_KR[(size_t)bt * ROPE + 2*i]     = xr*c - xi*s;
        g_KR[(size_t)bt * ROPE + 2*i + 1] = xr*s + xi*c;
    }
}

// ---------------- build Q (hi/lo) / K (hi) tensors [b,h,t,192]; q-rope+scale fused ----
__global__ void build_qk_hl(const float* __restrict__ cosv, const float* __restrict__ sinv)
{
    const size_t NQ = (size_t)MTOT * HH * QKD;
    size_t i = (size_t)blockIdx.x * blockDim.x + threadIdx.x;
    if (i >= NQ) return;
    int d = (int)(i % QKD);
    size_t r = i / QKD;
    int h = (int)(r % HH);
    size_t bt = r / HH;
    int t = (int)(bt % TT);
    int b = (int)(bt / TT);
    size_t dst = (((size_t)b*HH + h)*TT + t)*QKD + d;

    float qv;
    if (d < NOPE) {
        qv = g_Q[(bt*HH + h)*QKD + d] * SCALE_F;
    } else {
        int i2 = d - NOPE;
        int pi = i2 >> 1;
        float c = cosv[t*32 + pi];
        float s = sinv[t*32 + pi];
        size_t base = (bt*HH + h)*QKD + NOPE + 2*pi;
        float xr = g_Q[base];
        float xi = g_Q[base + 1];
        qv = ((i2 & 1) ? (xr*s + xi*c) : (xr*c - xi*s)) * SCALE_F;
    }
    __half qh = __float2half_rn(qv);
    g_qhl[dst]      = qh;
    g_qhl[NQ + dst] = __float2half_rn(qv - __half2float(qh));

    float kv;
    if (d < NOPE) kv = g_KV[(bt*HH + h)*(NOPE+VDIM) + d];
    else          kv = g_KR[bt*ROPE + (d - NOPE)];
    g_khl[dst] = __float2half_rn(kv);
}

// ---------------- build V transposed (hi) [b,h,d,t] ----------------
__global__ void build_v_hl()
{
    __shared__ float tile[32][33];
    const int bh = blockIdx.z;
    const int b = bh / HH, h = bh % HH;
    const int t0 = blockIdx.x * 32;
    const int d0 = blockIdx.y * 32;
    const int tx = threadIdx.x, ty = threadIdx.y;

#pragma unroll
    for (int k = 0; k < 4; k++) {
        int t = t0 + ty + k*8;
        tile[ty + k*8][tx] = g_KV[((size_t)(b*TT + t)*HH + h)*(NOPE+VDIM) + NOPE + d0 + tx];
    }
    __syncthreads();
#pragma unroll
    for (int k = 0; k < 4; k++) {
        int d = d0 + ty + k*8;
        float v = tile[tx][ty + k*8];
        g_vhl[((size_t)bh*VDIM + d)*TT + t0 + tx] = __float2half_rn(v);
    }
}

// ---------------- HMMA flash attention (fp16 2-term) ----------------
#define QS_STRIDE 200
#define VS_STRIDE 72
#define SM_Q_ELEMS (2*128*QS_STRIDE)
#define SM_K_ELEMS (64*QS_STRIDE)
#define SM_V_ELEMS (128*VS_STRIDE)
#define ATT_SMEM_B ((SM_Q_ELEMS + SM_K_ELEMS + SM_V_ELEMS) * 2)

__global__ __launch_bounds__(256, 1) void attn_hmma()
{
    extern __shared__ __half smb[];
    __half* qs = smb;
    __half* ks = smb + SM_Q_ELEMS;
    __half* vs = smb + SM_Q_ELEMS + SM_K_ELEMS;

    const int b = blockIdx.z, h = blockIdx.y;
    const int qbase = blockIdx.x * 128;
    const int tid = threadIdx.x, lane = tid & 31, w = tid >> 5;
    const size_t NQ = (size_t)MTOT * HH * QKD;
    const size_t bh = (size_t)b * HH + h;

    {
        const __half* qg = g_qhl + (bh*TT + qbase)*QKD;
        for (int i = tid; i < 2*128*24; i += 256) {
            int p = i / (128*24);
            int rem = i % (128*24);
            int r = rem / 24, c = rem % 24;
            *(uint4*)&qs[p*(128*QS_STRIDE) + r*QS_STRIDE + c*8] =
                *(const uint4*)&qg[(size_t)p*NQ + (size_t)r*QKD + c*8];
        }
    }

    const int g  = lane >> 2;
    const int qc = (lane & 3) * 2;
    const int qr0 = qbase + w*16 + g;

    float m0 = -1e30f, m1 = -1e30f, l0 = 0.f, l1 = 0.f;
    float o[16][4];
#pragma unroll
    for (int nv = 0; nv < 16; nv++)
#pragma unroll
        for (int e = 0; e < 4; e++) o[nv][e] = 0.f;

    const uint32_t sQ = smem_u32(qs);
    const uint32_t sK = smem_u32(ks);
    const uint32_t sV = smem_u32(vs);
    const uint32_t QPB = 128*QS_STRIDE*2;

    const int ntiles = qbase/64 + 2;
    for (int kb = 0; kb < ntiles; kb++) {
        const int kbase = kb * 64;
        __syncthreads();
        {
            const __half* kg = g_khl + (bh*TT + kbase)*QKD;
            for (int i = tid; i < 64*24; i += 256) {
                int r = i / 24, c = i % 24;
                *(uint4*)&ks[r*QS_STRIDE + c*8] = *(const uint4*)&kg[(size_t)r*QKD + c*8];
            }
            const __half* vg = g_vhl + bh*VDIM*TT + kbase;
            for (int i = tid; i < 128*8; i += 256) {
                int d = i / 8, c = i % 8;
                *(uint4*)&vs[d*VS_STRIDE + c*8] = *(const uint4*)&vg[(size_t)d*TT + c*8];
            }
        }
        __syncthreads();

        float s[8][4];
#pragma unroll
        for (int ni = 0; ni < 8; ni++)
#pragma unroll
            for (int e = 0; e < 4; e++) s[ni][e] = 0.f;

#pragma unroll
        for (int kp = 0; kp < 6; kp++) {
            uint32_t ah0[4], ah1[4], al0[4], al1[4];
            uint32_t ab = sQ + ((w*16 + (lane & 15))*QS_STRIDE + kp*32 + (lane >> 4)*8) * 2;
            ldsm4(ah0, ab);
            ldsm4(ah1, ab + 32);
            ldsm4(al0, ab + QPB);
            ldsm4(al1, ab + QPB + 32);
#pragma unroll
            for (int ni = 0; ni < 8; ni++) {
                uint32_t bb = sK + ((ni*8 + (lane & 7))*QS_STRIDE + kp*32 + (lane >> 3)*8) * 2;
                uint32_t bh4[4];
                ldsm4(bh4, bb);
                mma16816(s[ni], ah0, bh4);
                mma16816(s[ni], al0, bh4);
                mma16816(s[ni], ah1, bh4 + 2);
                mma16816(s[ni], al1, bh4 + 2);
            }
        }

        if (kbase + 63 > qr0) {
#pragma unroll
            for (int ni = 0; ni < 8; ni++) {
                int col = kbase + ni*8 + qc;
                if (col     > qr0)     s[ni][0] = -1e30f;
                if (col + 1 > qr0)     s[ni][1] = -1e30f;
                if (col     > qr0 + 8) s[ni][2] = -1e30f;
                if (col + 1 > qr0 + 8) s[ni][3] = -1e30f;
            }
        }

        float rm0 = -1e30f, rm1 = -1e30f;
#pragma unroll
        for (int ni = 0; ni < 8; ni++) {
            rm0 = fmaxf(rm0, fmaxf(s[ni][0], s[ni][1]));
            rm1 = fmaxf(rm1, fmaxf(s[ni][2], s[ni][3]));
        }
        rm0 = fmaxf(rm0, __shfl_xor_sync(0xffffffffu, rm0, 1));
        rm0 = fmaxf(rm0, __shfl_xor_sync(0xffffffffu, rm0, 2));
        rm1 = fmaxf(rm1, __shfl_xor_sync(0xffffffffu, rm1, 1));
        rm1 = fmaxf(rm1, __shfl_xor_sync(0xffffffffu, rm1, 2));
        float nm0 = fmaxf(m0, rm0), nm1 = fmaxf(m1, rm1);
        float c0 = __expf(m0 - nm0), c1 = __expf(m1 - nm1);

        float rs0 = 0.f, rs1 = 0.f;
#pragma unroll
        for (int ni = 0; ni < 8; ni++) {
            s[ni][0] = __expf(s[ni][0] - nm0); rs0 += s[ni][0];
            s[ni][1] = __expf(s[ni][1] - nm0); rs0 += s[ni][1];
            s[ni][2] = __expf(s[ni][2] - nm1); rs1 += s[ni][2];
            s[ni][3] = __expf(s[ni][3] - nm1); rs1 += s[ni][3];
        }
        rs0 += __shfl_xor_sync(0xffffffffu, rs0, 1);
        rs0 += __shfl_xor_sync(0xffffffffu, rs0, 2);
        rs1 += __shfl_xor_sync(0xffffffffu, rs1, 1);
        rs1 += __shfl_xor_sync(0xffffffffu, rs1, 2);
        l0 = l0 * c0 + rs0;
        l1 = l1 * c1 + rs1;
        m0 = nm0; m1 = nm1;
#pragma unroll
        for (int nv = 0; nv < 16; nv++) {
            o[nv][0] *= c0; o[nv][1] *= c0;
            o[nv][2] *= c1; o[nv][3] *= c1;
        }

#pragma unroll
        for (int kp = 0; kp < 2; kp++) {
            uint32_t ph[2][4], pl[2][4];
#pragma unroll
            for (int ss2 = 0; ss2 < 2; ss2++) {
                int n0 = kp*4 + ss2*2;
#pragma unroll
                for (int half = 0; half < 2; half++) {
                    int nt = n0 + half;
                    float v0 = s[nt][0], v1 = s[nt][1], v2 = s[nt][2], v3 = s[nt][3];
                    __half h0 = __float2half_rn(v0);
                    __half h1 = __float2half_rn(v1);
                    __half h2 = __float2half_rn(v2);
                    __half h3 = __float2half_rn(v3);
                    ph[ss2][half*2 + 0] = pack_h2(h0, h1);
                    ph[ss2][half*2 + 1] = pack_h2(h2, h3);
                    pl[ss2][half*2 + 0] = pack_h2(__float2half_rn(v0 - __half2float(h0)),
                                                  __float2half_rn(v1 - __half2float(h1)));
                    pl[ss2][half*2 + 1] = pack_h2(__float2half_rn(v2 - __half2float(h2)),
                                                  __float2half_rn(v3 - __half2float(h3)));
                }
            }
#pragma unroll
            for (int nv = 0; nv < 16; nv++) {
                uint32_t vb = sV + ((nv*8 + (lane & 7))*VS_STRIDE + kp*32 + (lane >> 3)*8) * 2;
                uint32_t vh4[4];
                ldsm4(vh4, vb);
                mma16816(o[nv], ph[0], vh4);
                mma16816(o[nv], pl[0], vh4);
                mma16816(o[nv], ph[1], vh4 + 2);
                mma16816(o[nv], pl[1], vh4 + 2);
            }
        }
    }

    // epilogue: write g_atth fp16 hi/lo directly
    float inv0 = 1.f / l0, inv1 = 1.f / l1;
    const size_t nATT = (size_t)MTOT * HH * VDIM;
    __half* op0 = g_atth + (size_t)(b*TT + qr0) * (HH*VDIM) + h*VDIM;
    __half* op1 = op0 + (size_t)8 * (HH*VDIM);
#pragma unroll
    for (int nv = 0; nv < 16; nv++) {
        int d = nv*8 + qc;
        float v00 = o[nv][0] * inv0, v01 = o[nv][1] * inv0;
        float v10 = o[nv][2] * inv1, v11 = o[nv][3] * inv1;
        __half h00 = __float2half_rn(v00);
        __half h01 = __float2half_rn(v01);
        __half h10 = __float2half_rn(v10);
        __half h11 = __float2half_rn(v11);
        op0[d]            = h00;
        op0[d + 1]        = h01;
        op1[d]            = h10;
        op1[d + 1]        = h11;
        op0[nATT + d]     = __float2half_rn(v00 - __half2float(h00));
        op0[nATT + d + 1] = __float2half_rn(v01 - __half2float(h01));
        op1[nATT + d]     = __float2half_rn(v10 - __half2float(h10));
        op1[nATT + d + 1] = __float2half_rn(v11 - __half2float(h11));
    }
}

// ---------------- launch ----------------
extern "C" void kernel_launch(void* const* d_in, const int* in_sizes, int n_in,
                              void* d_out, int out_size)
{
    const float* x       = (const float*)d_in[0];
    const float* wq_w    = (const float*)d_in[1];
    const float* wq_b    = (const float*)d_in[2];
    const float* wkv_a_w = (const float*)d_in[3];
    const float* wkv_a_b = (const float*)d_in[4];
    const float* wkv_b_w = (const float*)d_in[5];
    const float* wkv_b_b = (const float*)d_in[6];
    const float* wo_w    = (const float*)d_in[7];
    const float* wo_b    = (const float*)d_in[8];
    const float* cosv    = (const float*)d_in[9];
    const float* sinv    = (const float*)d_in[10];
    float* out = (float*)d_out;

    float *Qp, *KVAp, *KVp;
    cudaGetSymbolAddress((void**)&Qp,   g_Q);
    cudaGetSymbolAddress((void**)&KVAp, g_KVA);
    cudaGetSymbolAddress((void**)&KVp,  g_KV);

    __half *xh, *wqh, *wkvah, *wkvbh, *woh, *kvnh, *atth;
    cudaGetSymbolAddress((void**)&xh,    g_xh);
    cudaGetSymbolAddress((void**)&wqh,   g_wqh);
    cudaGetSymbolAddress((void**)&wkvah, g_wkvah);
    cudaGetSymbolAddress((void**)&wkvbh, g_wkvbh);
    cudaGetSymbolAddress((void**)&woh,   g_woh);
    cudaGetSymbolAddress((void**)&kvnh,  g_kvnh);
    cudaGetSymbolAddress((void**)&atth,  g_atth);

    const size_t nX    = (size_t)MTOT * DIM;
    const size_t nWQ   = (size_t)(HH*QKD) * DIM;
    const size_t nWKVA = (size_t)(KVR+ROPE) * DIM;
    const size_t nWKVB = (size_t)(HH*(NOPE+VDIM)) * KVR;
    const size_t nWO   = (size_t)DIM * (HH*VDIM);
    const size_t nKVN  = (size_t)MTOT * KVR;
    const size_t nATT  = (size_t)MTOT * HH * VDIM;
    const size_t nQK   = (size_t)MTOT * HH * QKD;

    cudaFuncSetAttribute(gemm_hmma, cudaFuncAttributeMaxDynamicSharedMemorySize, G_SMEM_B);

    // conversions: x hi/lo, weights hi only
    conv_hilo<<<(unsigned)((nX + 255) / 256), 256>>>(x, xh, nX);
    conv_hi  <<<(unsigned)((nWQ + 255) / 256), 256>>>(wq_w, wqh, nWQ);
    conv_hi  <<<(unsigned)((nWKVA + 255) / 256), 256>>>(wkv_a_w, wkvah, nWKVA);
    conv_hi  <<<(unsigned)((nWKVB + 255) / 256), 256>>>(wkv_b_w, wkvbh, nWKVB);
    conv_hi  <<<(unsigned)((nWO + 255) / 256), 256>>>(wo_w, woh, nWO);

    // 1) q = x @ wq^T + b
    gemm_hmma<<<dim3(3072/128, MTOT/128), 256, G_SMEM_B>>>(xh, nX, wqh, wq_b, Qp, MTOT, HH*QKD, DIM);
    // 2) kv_a = x @ wkv_a^T + b
    gemm_hmma<<<dim3((KVR+ROPE+127)/128, MTOT/128), 256, G_SMEM_B>>>(xh, nX, wkvah, wkv_a_b, KVAp, MTOT, KVR+ROPE, DIM);
    // 3) rms norm (-> fp16 hi/lo direct) + k rope
    kva_post_kernel<<<MTOT, 128>>>(cosv, sinv);
    // 4) kv = norm @ wkv_b^T + b
    gemm_hmma<<<dim3(HH*(NOPE+VDIM)/128, MTOT/128), 256, G_SMEM_B>>>(kvnh, nKVN, wkvbh, wkv_b_b, KVp, MTOT, HH*(NOPE+VDIM), KVR);
    // 5) build attention tensors (q rope+scale fused)
    build_qk_hl<<<(unsigned)((nQK + 255) / 256), 256>>>(cosv, sinv);
    build_v_hl<<<dim3(TT/32, VDIM/32, BB*HH), dim3(32, 8)>>>();
    // 6) flash attention (fp16 HMMA) -> writes g_atth hi/lo directly
    cudaFuncSetAttribute(attn_hmma, cudaFuncAttributeMaxDynamicSharedMemorySize, ATT_SMEM_B);
    attn_hmma<<<dim3(TT/128, HH, BB), 256, ATT_SMEM_B>>>();
    // 7) out = att @ wo^T + b
    gemm_hmma<<<dim3(DIM/128, MTOT/128), 256, G_SMEM_B>>>(atth, nATT, woh, wo_b, out, MTOT, DIM, HH*VDIM);
}

// round 13
// speedup vs baseline: 9.3538x; 1.3218x over previous
#include <cuda_runtime.h>
#include <cuda_fp16.h>
#include <math.h>
#include <stdint.h>

// ---------------- problem constants ----------------
#define BB 4
#define TT 2048
#define DIM 1024
#define HH 16
#define NOPE 128
#define ROPE 64
#define VDIM 128
#define KVR 512
#define QKD 192            // NOPE + ROPE
#define MTOT (BB*TT)       // 8192
#define SCALE_F (0.07216878364870323f)  // 192^-0.5

// ---------------- fp32 scratch ----------------
__device__ __align__(16) float g_Q  [(size_t)MTOT * HH * QKD];   // raw q proj (pre-rope)
__device__ __align__(16) float g_KVA[(size_t)MTOT * (KVR+ROPE)];
__device__ __align__(16) float g_KR [(size_t)MTOT * ROPE];
__device__ __align__(16) float g_KV [(size_t)MTOT * HH * (NOPE+VDIM)];

// ---------------- fp16 planes (hi only) ----------
__device__ __align__(16) __half g_xh   [(size_t)MTOT * DIM];
__device__ __align__(16) __half g_wqh  [(size_t)(HH*QKD) * DIM];
__device__ __align__(16) __half g_wkvah[(size_t)(KVR+ROPE) * DIM];
__device__ __align__(16) __half g_wkvbh[(size_t)(HH*(NOPE+VDIM)) * KVR];
__device__ __align__(16) __half g_woh  [(size_t)DIM * (HH*VDIM)];
__device__ __align__(16) __half g_kvnh [(size_t)MTOT * KVR];
__device__ __align__(16) __half g_atth [(size_t)MTOT * HH * VDIM];

// ---------------- fp16 attention tensors ----------
__device__ __align__(16) __half g_qhl[(size_t)MTOT * HH * QKD];  // [b,h,t,192]
__device__ __align__(16) __half g_khl[(size_t)MTOT * HH * QKD];  // [b,h,t,192]
__device__ __align__(16) __half g_vhl[(size_t)MTOT * HH * VDIM]; // [b,h,d,t]

// ---------------- fp32 -> fp16 ----------------
__global__ void conv_hi(const float* __restrict__ src, __half* __restrict__ dst, size_t n)
{
    size_t i = (size_t)blockIdx.x * blockDim.x + threadIdx.x;
    if (i >= n) return;
    dst[i] = __float2half_rn(src[i]);
}

// ---------------- HMMA helpers (fp16 in, fp32 accum) ----------------
__device__ __forceinline__ void ldsm4(uint32_t* r, uint32_t addr) {
    asm volatile("ldmatrix.sync.aligned.m8n8.x4.shared.b16 {%0,%1,%2,%3},[%4];"
                 : "=r"(r[0]), "=r"(r[1]), "=r"(r[2]), "=r"(r[3]) : "r"(addr));
}
__device__ __forceinline__ void mma16816(float* c, const uint32_t* a, const uint32_t* b) {
    asm volatile(
        "mma.sync.aligned.m16n8k16.row.col.f32.f16.f16.f32 "
        "{%0,%1,%2,%3},{%4,%5,%6,%7},{%8,%9},{%0,%1,%2,%3};"
        : "+f"(c[0]), "+f"(c[1]), "+f"(c[2]), "+f"(c[3])
        : "r"(a[0]), "r"(a[1]), "r"(a[2]), "r"(a[3]), "r"(b[0]), "r"(b[1]));
}
__device__ __forceinline__ void mma16816b(float* c, const uint32_t* a, uint32_t b0, uint32_t b1) {
    asm volatile(
        "mma.sync.aligned.m16n8k16.row.col.f32.f16.f16.f32 "
        "{%0,%1,%2,%3},{%4,%5,%6,%7},{%8,%9},{%0,%1,%2,%3};"
        : "+f"(c[0]), "+f"(c[1]), "+f"(c[2]), "+f"(c[3])
        : "r"(a[0]), "r"(a[1]), "r"(a[2]), "r"(a[3]), "r"(b0), "r"(b1));
}
__device__ __forceinline__ uint32_t pack_h2(__half a, __half b) {
    __half2 t; t.x = a; t.y = b;
    return *(uint32_t*)&t;
}
__device__ __forceinline__ uint32_t smem_u32(const void* p) {
    uint32_t a;
    asm("{ .reg .u64 t; cvta.to.shared.u64 t, %1; cvt.u32.u64 %0, t; }" : "=r"(a) : "l"(p));
    return a;
}
__device__ __forceinline__ void cp16(uint32_t d, const void* s) {
    asm volatile("cp.async.cg.shared.global [%0],[%1],16;" :: "r"(d), "l"(s));
}
__device__ __forceinline__ void cp16z(uint32_t d, const void* s, unsigned sz) {
    asm volatile("cp.async.cg.shared.global [%0],[%1],16,%2;" :: "r"(d), "l"(s), "r"(sz));
}
__device__ __forceinline__ void cp_commit() { asm volatile("cp.async.commit_group;"); }
template <int N>
__device__ __forceinline__ void cp_wait() {
    asm volatile("cp.async.wait_group %0;" :: "n"(N) : "memory");
}

// ---------------- HMMA GEMM (cp.async 2-stage, pure fp16): C = A@B^T + bias ----
// BM=BN=128, BK=32, 256 threads, warps 4(m)x2(n), warp tile 32x64.
#define LDPAD 40   // fp16 elems per smem row (80B, conflict-free ldmatrix)
#define G_PLANE_B (128 * LDPAD * 2)                 // one tile, bytes (10240)
#define G_STAGE_B (2 * G_PLANE_B)                   // A, B
#define G_SMEM_B  (2 * G_STAGE_B)                   // 40960

__global__ __launch_bounds__(256, 2) void gemm_hmma(
    const __half* __restrict__ A,
    const __half* __restrict__ B,
    const float* __restrict__ bias, float* __restrict__ C,
    int M, int N, int K)
{
    extern __shared__ char smraw[];
    const uint32_t sbase = smem_u32(smraw);

    const int tid  = threadIdx.x;
    const int lane = tid & 31;
    const int wid  = tid >> 5;
    const int brow = blockIdx.y * 128;
    const int bcol = blockIdx.x * 128;

    const int lc = tid & 3;        // k-chunk (8 fp16 = 16B)
    const int lr = tid >> 2;       // 0..63 -> rows lr, lr+64

    const int wm = (wid & 3) * 32;
    const int wn = (wid >> 2) * 64;

    float acc[2][8][4];
#pragma unroll
    for (int mi = 0; mi < 2; mi++)
#pragma unroll
        for (int ni = 0; ni < 8; ni++)
#pragma unroll
            for (int e = 0; e < 4; e++) acc[mi][ni][e] = 0.f;

    const uint32_t rowoff0 = (uint32_t)(lr * LDPAD + lc * 8) * 2;
    const uint32_t rowoff1 = (uint32_t)((lr + 64) * LDPAD + lc * 8) * 2;

    const int arow0 = brow + lr, arow1 = brow + lr + 64;
    const int ncol0 = bcol + lr, ncol1 = bcol + lr + 64;
    const int nc0 = ncol0 < N ? ncol0 : 0;
    const int nc1 = ncol1 < N ? ncol1 : 0;
    const unsigned bz0 = ncol0 < N ? 16u : 0u;
    const unsigned bz1 = ncol1 < N ? 16u : 0u;

    const int nch = K / 32;

    auto stage_load = [&](int c, int s) {
        const int kk = c * 32 + lc * 8;
        const uint32_t as = sbase + (uint32_t)s * G_STAGE_B;
        const uint32_t bs = as + G_PLANE_B;
        cp16(as + rowoff0, A + (size_t)arow0 * K + kk);
        cp16(as + rowoff1, A + (size_t)arow1 * K + kk);
        cp16z(bs + rowoff0, B + (size_t)nc0 * K + kk, bz0);
        cp16z(bs + rowoff1, B + (size_t)nc1 * K + kk, bz1);
        cp_commit();
    };

    stage_load(0, 0);
    if (nch > 1) stage_load(1, 1);

    for (int c = 0; c < nch; c++) {
        const int s = c & 1;
        cp_wait<1>();
        __syncthreads();

        const uint32_t aS = sbase + (uint32_t)s * G_STAGE_B;
        const uint32_t bS = aS + G_PLANE_B;

#pragma unroll
        for (int ks = 0; ks < 2; ks++) {
            const int kc = ks * 16;
            uint32_t a_h[2][4];
#pragma unroll
            for (int mi = 0; mi < 2; mi++) {
                uint32_t addr = aS + ((wm + mi*16 + (lane & 15)) * LDPAD + kc + (lane >> 4) * 8) * 2;
                ldsm4(a_h[mi], addr);
            }
            uint32_t b_h[4][4];
#pragma unroll
            for (int np = 0; np < 4; np++) {
                uint32_t baddr = bS + ((wn + np*16 + (lane & 15)) * LDPAD + kc + (lane >> 4) * 8) * 2;
                ldsm4(b_h[np], baddr);
            }
#pragma unroll
            for (int np = 0; np < 4; np++) {
#pragma unroll
                for (int hf = 0; hf < 2; hf++) {
                    const int ni = np*2 + hf;
#pragma unroll
                    for (int mi = 0; mi < 2; mi++) {
                        mma16816b(acc[mi][ni], a_h[mi], b_h[np][hf], b_h[np][hf+2]);
                    }
                }
            }
        }
        __syncthreads();
        if (c + 2 < nch) stage_load(c + 2, s);
    }

#pragma unroll
    for (int mi = 0; mi < 2; mi++) {
        int r0 = brow + wm + mi*16 + (lane >> 2);
#pragma unroll
        for (int ni = 0; ni < 8; ni++) {
            int c0 = bcol + wn + ni*8 + (lane & 3) * 2;
            if (c0 < N) {
                float b0 = bias[c0], b1 = bias[c0+1];
                C[(size_t)r0 * N + c0]       = acc[mi][ni][0] + b0;
                C[(size_t)r0 * N + c0 + 1]   = acc[mi][ni][1] + b1;
                C[(size_t)(r0+8) * N + c0]   = acc[mi][ni][2] + b0;
                C[(size_t)(r0+8) * N + c0+1] = acc[mi][ni][3] + b1;
            }
        }
    }
}

// ---------------- kv_a post: rms_norm -> g_kvnh (fp16), rope -> g_KR ----------------
__global__ __launch_bounds__(128) void kva_post_kernel(const float* __restrict__ cosv,
                                                       const float* __restrict__ sinv)
{
    __shared__ float red[4];
    const int bt = blockIdx.x;
    const int t  = bt % TT;
    const float* a = g_KVA + (size_t)bt * (KVR + ROPE);
    const int tid = threadIdx.x;

    float ss = 0.f;
    for (int d = tid; d < KVR; d += 128) { float v = a[d]; ss += v * v; }
#pragma unroll
    for (int off = 16; off; off >>= 1) ss += __shfl_xor_sync(0xffffffffu, ss, off);
    if ((tid & 31) == 0) red[tid >> 5] = ss;
    __syncthreads();
    float total = red[0] + red[1] + red[2] + red[3];
    float r = rsqrtf(total * (1.0f / KVR) + 1e-6f);

    __half* o = g_kvnh + (size_t)bt * KVR;
    for (int d = tid; d < KVR; d += 128) o[d] = __float2half_rn(a[d] * r);

    if (tid < 32) {
        int i = tid;
        float c = cosv[t*32 + i];
        float s = sinv[t*32 + i];
        float xr = a[KVR + 2*i];
        float xi = a[KVR + 2*i + 1];
        g_KR[(size_t)bt * ROPE + 2*i]     = xr*c - xi*s;
        g_KR[(size_t)bt * ROPE + 2*i + 1] = xr*s + xi*c;
    }
}

// ---------------- build Q / K tensors [b,h,t,192]; q-rope+scale fused ----
__global__ void build_qk_hl(const float* __restrict__ cosv, const float* __restrict__ sinv)
{
    const size_t NQ = (size_t)MTOT * HH * QKD;
    size_t i = (size_t)blockIdx.x * blockDim.x + threadIdx.x;
    if (i >= NQ) return;
    int d = (int)(i % QKD);
    size_t r = i / QKD;
    int h = (int)(r % HH);
    size_t bt = r / HH;
    int t = (int)(bt % TT);
    int b = (int)(bt / TT);
    size_t dst = (((size_t)b*HH + h)*TT + t)*QKD + d;

    float qv;
    if (d < NOPE) {
        qv = g_Q[(bt*HH + h)*QKD + d] * SCALE_F;
    } else {
        int i2 = d - NOPE;
        int pi = i2 >> 1;
        float c = cosv[t*32 + pi];
        float s = sinv[t*32 + pi];
        size_t base = (bt*HH + h)*QKD + NOPE + 2*pi;
        float xr = g_Q[base];
        float xi = g_Q[base + 1];
        qv = ((i2 & 1) ? (xr*s + xi*c) : (xr*c - xi*s)) * SCALE_F;
    }
    g_qhl[dst] = __float2half_rn(qv);

    float kv;
    if (d < NOPE) kv = g_KV[(bt*HH + h)*(NOPE+VDIM) + d];
    else          kv = g_KR[bt*ROPE + (d - NOPE)];
    g_khl[dst] = __float2half_rn(kv);
}

// ---------------- build V transposed [b,h,d,t] ----------------
__global__ void build_v_hl()
{
    __shared__ float tile[32][33];
    const int bh = blockIdx.z;
    const int b = bh / HH, h = bh % HH;
    const int t0 = blockIdx.x * 32;
    const int d0 = blockIdx.y * 32;
    const int tx = threadIdx.x, ty = threadIdx.y;

#pragma unroll
    for (int k = 0; k < 4; k++) {
        int t = t0 + ty + k*8;
        tile[ty + k*8][tx] = g_KV[((size_t)(b*TT + t)*HH + h)*(NOPE+VDIM) + NOPE + d0 + tx];
    }
    __syncthreads();
#pragma unroll
    for (int k = 0; k < 4; k++) {
        int d = d0 + ty + k*8;
        g_vhl[((size_t)bh*VDIM + d)*TT + t0 + tx] = __float2half_rn(tile[tx][ty + k*8]);
    }
}

// ---------------- HMMA flash attention (pure fp16 operands, fp32 accum) ----------------
#define QS_STRIDE 200
#define VS_STRIDE 72
#define SM_Q_ELEMS (128*QS_STRIDE)
#define SM_K_ELEMS (64*QS_STRIDE)
#define SM_V_ELEMS (128*VS_STRIDE)
#define ATT_SMEM_B ((SM_Q_ELEMS + SM_K_ELEMS + SM_V_ELEMS) * 2)

__global__ __launch_bounds__(256, 1) void attn_hmma()
{
    extern __shared__ __half smb[];
    __half* qs = smb;
    __half* ks = smb + SM_Q_ELEMS;
    __half* vs = smb + SM_Q_ELEMS + SM_K_ELEMS;

    const int b = blockIdx.z, h = blockIdx.y;
    const int qbase = blockIdx.x * 128;
    const int tid = threadIdx.x, lane = tid & 31, w = tid >> 5;
    const size_t bh = (size_t)b * HH + h;

    {
        const __half* qg = g_qhl + (bh*TT + qbase)*QKD;
        for (int i = tid; i < 128*24; i += 256) {
            int r = i / 24, c = i % 24;
            *(uint4*)&qs[r*QS_STRIDE + c*8] = *(const uint4*)&qg[(size_t)r*QKD + c*8];
        }
    }

    const int g  = lane >> 2;
    const int qc = (lane & 3) * 2;
    const int qr0 = qbase + w*16 + g;

    float m0 = -1e30f, m1 = -1e30f, l0 = 0.f, l1 = 0.f;
    float o[16][4];
#pragma unroll
    for (int nv = 0; nv < 16; nv++)
#pragma unroll
        for (int e = 0; e < 4; e++) o[nv][e] = 0.f;

    const uint32_t sQ = smem_u32(qs);
    const uint32_t sK = smem_u32(ks);
    const uint32_t sV = smem_u32(vs);

    const int ntiles = qbase/64 + 2;
    for (int kb = 0; kb < ntiles; kb++) {
        const int kbase = kb * 64;
        __syncthreads();
        {
            const __half* kg = g_khl + (bh*TT + kbase)*QKD;
            for (int i = tid; i < 64*24; i += 256) {
                int r = i / 24, c = i % 24;
                *(uint4*)&ks[r*QS_STRIDE + c*8] = *(const uint4*)&kg[(size_t)r*QKD + c*8];
            }
            const __half* vg = g_vhl + bh*VDIM*TT + kbase;
            for (int i = tid; i < 128*8; i += 256) {
                int d = i / 8, c = i % 8;
                *(uint4*)&vs[d*VS_STRIDE + c*8] = *(const uint4*)&vg[(size_t)d*TT + c*8];
            }
        }
        __syncthreads();

        float s[8][4];
#pragma unroll
        for (int ni = 0; ni < 8; ni++)
#pragma unroll
            for (int e = 0; e < 4; e++) s[ni][e] = 0.f;

#pragma unroll
        for (int kp = 0; kp < 6; kp++) {
            uint32_t ah0[4], ah1[4];
            uint32_t ab = sQ + ((w*16 + (lane & 15))*QS_STRIDE + kp*32 + (lane >> 4)*8) * 2;
            ldsm4(ah0, ab);
            ldsm4(ah1, ab + 32);
#pragma unroll
            for (int ni = 0; ni < 8; ni++) {
                uint32_t bb = sK + ((ni*8 + (lane & 7))*QS_STRIDE + kp*32 + (lane >> 3)*8) * 2;
                uint32_t bh4[4];
                ldsm4(bh4, bb);
                mma16816(s[ni], ah0, bh4);
                mma16816(s[ni], ah1, bh4 + 2);
            }
        }

        if (kbase + 63 > qr0) {
#pragma unroll
            for (int ni = 0; ni < 8; ni++) {
                int col = kbase + ni*8 + qc;
                if (col     > qr0)     s[ni][0] = -1e30f;
                if (col + 1 > qr0)     s[ni][1] = -1e30f;
                if (col     > qr0 + 8) s[ni][2] = -1e30f;
                if (col + 1 > qr0 + 8) s[ni][3] = -1e30f;
            }
        }

        float rm0 = -1e30f, rm1 = -1e30f;
#pragma unroll
        for (int ni = 0; ni < 8; ni++) {
            rm0 = fmaxf(rm0, fmaxf(s[ni][0], s[ni][1]));
            rm1 = fmaxf(rm1, fmaxf(s[ni][2], s[ni][3]));
        }
        rm0 = fmaxf(rm0, __shfl_xor_sync(0xffffffffu, rm0, 1));
        rm0 = fmaxf(rm0, __shfl_xor_sync(0xffffffffu, rm0, 2));
        rm1 = fmaxf(rm1, __shfl_xor_sync(0xffffffffu, rm1, 1));
        rm1 = fmaxf(rm1, __shfl_xor_sync(0xffffffffu, rm1, 2));
        float nm0 = fmaxf(m0, rm0), nm1 = fmaxf(m1, rm1);
        float c0 = __expf(m0 - nm0), c1 = __expf(m1 - nm1);

        float rs0 = 0.f, rs1 = 0.f;
#pragma unroll
        for (int ni = 0; ni < 8; ni++) {
            s[ni][0] = __expf(s[ni][0] - nm0); rs0 += s[ni][0];
            s[ni][1] = __expf(s[ni][1] - nm0); rs0 += s[ni][1];
            s[ni][2] = __expf(s[ni][2] - nm1); rs1 += s[ni][2];
            s[ni][3] = __expf(s[ni][3] - nm1); rs1 += s[ni][3];
        }
        rs0 += __shfl_xor_sync(0xffffffffu, rs0, 1);
        rs0 += __shfl_xor_sync(0xffffffffu, rs0, 2);
        rs1 += __shfl_xor_sync(0xffffffffu, rs1, 1);
        rs1 += __shfl_xor_sync(0xffffffffu, rs1, 2);
        l0 = l0 * c0 + rs0;
        l1 = l1 * c1 + rs1;
        m0 = nm0; m1 = nm1;
#pragma unroll
        for (int nv = 0; nv < 16; nv++) {
            o[nv][0] *= c0; o[nv][1] *= c0;
            o[nv][2] *= c1; o[nv][3] *= c1;
        }

#pragma unroll
        for (int kp = 0; kp < 2; kp++) {
            uint32_t ph[2][4];
#pragma unroll
            for (int ss2 = 0; ss2 < 2; ss2++) {
                int n0 = kp*4 + ss2*2;
#pragma unroll
                for (int half = 0; half < 2; half++) {
                    int nt = n0 + half;
                    ph[ss2][half*2 + 0] = pack_h2(__float2half_rn(s[nt][0]), __float2half_rn(s[nt][1]));
                    ph[ss2][half*2 + 1] = pack_h2(__float2half_rn(s[nt][2]), __float2half_rn(s[nt][3]));
                }
            }
#pragma unroll
            for (int nv = 0; nv < 16; nv++) {
                uint32_t vb = sV + ((nv*8 + (lane & 7))*VS_STRIDE + kp*32 + (lane >> 3)*8) * 2;
                uint32_t vh4[4];
                ldsm4(vh4, vb);
                mma16816(o[nv], ph[0], vh4);
                mma16816(o[nv], ph[1], vh4 + 2);
            }
        }
    }

    // epilogue: write g_atth fp16 directly
    float inv0 = 1.f / l0, inv1 = 1.f / l1;
    __half* op0 = g_atth + (size_t)(b*TT + qr0) * (HH*VDIM) + h*VDIM;
    __half* op1 = op0 + (size_t)8 * (HH*VDIM);
#pragma unroll
    for (int nv = 0; nv < 16; nv++) {
        int d = nv*8 + qc;
        op0[d]     = __float2half_rn(o[nv][0] * inv0);
        op0[d + 1] = __float2half_rn(o[nv][1] * inv0);
        op1[d]     = __float2half_rn(o[nv][2] * inv1);
        op1[d + 1] = __float2half_rn(o[nv][3] * inv1);
    }
}

// ---------------- launch ----------------
extern "C" void kernel_launch(void* const* d_in, const int* in_sizes, int n_in,
                              void* d_out, int out_size)
{
    const float* x       = (const float*)d_in[0];
    const float* wq_w    = (const float*)d_in[1];
    const float* wq_b    = (const float*)d_in[2];
    const float* wkv_a_w = (const float*)d_in[3];
    const float* wkv_a_b = (const float*)d_in[4];
    const float* wkv_b_w = (const float*)d_in[5];
    const float* wkv_b_b = (const float*)d_in[6];
    const float* wo_w    = (const float*)d_in[7];
    const float* wo_b    = (const float*)d_in[8];
    const float* cosv    = (const float*)d_in[9];
    const float* sinv    = (const float*)d_in[10];
    float* out = (float*)d_out;

    float *Qp, *KVAp, *KVp;
    cudaGetSymbolAddress((void**)&Qp,   g_Q);
    cudaGetSymbolAddress((void**)&KVAp, g_KVA);
    cudaGetSymbolAddress((void**)&KVp,  g_KV);

    __half *xh, *wqh, *wkvah, *wkvbh, *woh, *kvnh, *atth;
    cudaGetSymbolAddress((void**)&xh,    g_xh);
    cudaGetSymbolAddress((void**)&wqh,   g_wqh);
    cudaGetSymbolAddress((void**)&wkvah, g_wkvah);
    cudaGetSymbolAddress((void**)&wkvbh, g_wkvbh);
    cudaGetSymbolAddress((void**)&woh,   g_woh);
    cudaGetSymbolAddress((void**)&kvnh,  g_kvnh);
    cudaGetSymbolAddress((void**)&atth,  g_atth);

    const size_t nX    = (size_t)MTOT * DIM;
    const size_t nWQ   = (size_t)(HH*QKD) * DIM;
    const size_t nWKVA = (size_t)(KVR+ROPE) * DIM;
    const size_t nWKVB = (size_t)(HH*(NOPE+VDIM)) * KVR;
    const size_t nWO   = (size_t)DIM * (HH*VDIM);
    const size_t nQK   = (size_t)MTOT * HH * QKD;

    cudaFuncSetAttribute(gemm_hmma, cudaFuncAttributeMaxDynamicSharedMemorySize, G_SMEM_B);

    // conversions: everything hi-only fp16
    conv_hi<<<(unsigned)((nX + 255) / 256), 256>>>(x, xh, nX);
    conv_hi<<<(unsigned)((nWQ + 255) / 256), 256>>>(wq_w, wqh, nWQ);
    conv_hi<<<(unsigned)((nWKVA + 255) / 256), 256>>>(wkv_a_w, wkvah, nWKVA);
    conv_hi<<<(unsigned)((nWKVB + 255) / 256), 256>>>(wkv_b_w, wkvbh, nWKVB);
    conv_hi<<<(unsigned)((nWO + 255) / 256), 256>>>(wo_w, woh, nWO);

    // 1) q = x @ wq^T + b
    gemm_hmma<<<dim3(3072/128, MTOT/128), 256, G_SMEM_B>>>(xh, wqh, wq_b, Qp, MTOT, HH*QKD, DIM);
    // 2) kv_a = x @ wkv_a^T + b
    gemm_hmma<<<dim3((KVR+ROPE+127)/128, MTOT/128), 256, G_SMEM_B>>>(xh, wkvah, wkv_a_b, KVAp, MTOT, KVR+ROPE, DIM);
    // 3) rms norm (-> fp16 direct) + k rope
    kva_post_kernel<<<MTOT, 128>>>(cosv, sinv);
    // 4) kv = norm @ wkv_b^T + b
    gemm_hmma<<<dim3(HH*(NOPE+VDIM)/128, MTOT/128), 256, G_SMEM_B>>>(kvnh, wkvbh, wkv_b_b, KVp, MTOT, HH*(NOPE+VDIM), KVR);
    // 5) build attention tensors (q rope+scale fused)
    build_qk_hl<<<(unsigned)((nQK + 255) / 256), 256>>>(cosv, sinv);
    build_v_hl<<<dim3(TT/32, VDIM/32, BB*HH), dim3(32, 8)>>>();
    // 6) flash attention (fp16 HMMA) -> writes g_atth directly
    cudaFuncSetAttribute(attn_hmma, cudaFuncAttributeMaxDynamicSharedMemorySize, ATT_SMEM_B);
    attn_hmma<<<dim3(TT/128, HH, BB), 256, ATT_SMEM_B>>>();
    // 7) out = att @ wo^T + b
    gemm_hmma<<<dim3(DIM/128, MTOT/128), 256, G_SMEM_B>>>(atth, woh, wo_b, out, MTOT, DIM, HH*VDIM);
}

// round 15
// speedup vs baseline: 15.6878x; 1.6772x over previous
#include <cuda_runtime.h>
#include <cuda_fp16.h>
#include <math.h>
#include <stdint.h>

// ---------------- problem constants ----------------
#define BB 4
#define TT 2048
#define DIM 1024
#define HH 16
#define NOPE 128
#define ROPE 64
#define VDIM 128
#define KVR 512
#define QKD 192            // NOPE + ROPE
#define MTOT (BB*TT)       // 8192
#define SCALE_F (0.07216878364870323f)  // 192^-0.5

// ---------------- fp32 scratch ----------------
__device__ __align__(16) float g_KVA[(size_t)MTOT * (KVR+ROPE)];

// ---------------- fp16 planes ----------
__device__ __align__(16) __half g_xh   [(size_t)MTOT * DIM];
__device__ __align__(16) __half g_wqh  [(size_t)(HH*QKD) * DIM];
__device__ __align__(16) __half g_wkvah[(size_t)(KVR+ROPE) * DIM];
__device__ __align__(16) __half g_wkvbh[(size_t)(HH*(NOPE+VDIM)) * KVR];
__device__ __align__(16) __half g_woh  [(size_t)DIM * (HH*VDIM)];
__device__ __align__(16) __half g_kvnh [(size_t)MTOT * KVR];
__device__ __align__(16) __half g_atth [(size_t)MTOT * HH * VDIM];

// ---------------- fp16 attention tensors ----------
__device__ __align__(16) __half g_qhl[(size_t)MTOT * HH * QKD];  // [b,h,t,192]
__device__ __align__(16) __half g_khl[(size_t)MTOT * HH * QKD];  // [b,h,t,192]
__device__ __align__(16) __half g_v16[(size_t)MTOT * HH * VDIM]; // [bt,h,128]
__device__ __align__(16) __half g_vhl[(size_t)MTOT * HH * VDIM]; // [b,h,d,t]

// ---------------- fp32 -> fp16 ----------------
__global__ void conv_hi(const float* __restrict__ src, __half* __restrict__ dst, size_t n)
{
    size_t i = (size_t)blockIdx.x * blockDim.x + threadIdx.x;
    if (i >= n) return;
    dst[i] = __float2half_rn(src[i]);
}

// ---------------- HMMA helpers ----------------
__device__ __forceinline__ void ldsm4(uint32_t* r, uint32_t addr) {
    asm volatile("ldmatrix.sync.aligned.m8n8.x4.shared.b16 {%0,%1,%2,%3},[%4];"
                 : "=r"(r[0]), "=r"(r[1]), "=r"(r[2]), "=r"(r[3]) : "r"(addr));
}
__device__ __forceinline__ void mma16816(float* c, const uint32_t* a, const uint32_t* b) {
    asm volatile(
        "mma.sync.aligned.m16n8k16.row.col.f32.f16.f16.f32 "
        "{%0,%1,%2,%3},{%4,%5,%6,%7},{%8,%9},{%0,%1,%2,%3};"
        : "+f"(c[0]), "+f"(c[1]), "+f"(c[2]), "+f"(c[3])
        : "r"(a[0]), "r"(a[1]), "r"(a[2]), "r"(a[3]), "r"(b[0]), "r"(b[1]));
}
__device__ __forceinline__ void mma16816b(float* c, const uint32_t* a, uint32_t b0, uint32_t b1) {
    asm volatile(
        "mma.sync.aligned.m16n8k16.row.col.f32.f16.f16.f32 "
        "{%0,%1,%2,%3},{%4,%5,%6,%7},{%8,%9},{%0,%1,%2,%3};"
        : "+f"(c[0]), "+f"(c[1]), "+f"(c[2]), "+f"(c[3])
        : "r"(a[0]), "r"(a[1]), "r"(a[2]), "r"(a[3]), "r"(b0), "r"(b1));
}
__device__ __forceinline__ uint32_t pack_h2(__half a, __half b) {
    __half2 t; t.x = a; t.y = b;
    return *(uint32_t*)&t;
}
__device__ __forceinline__ uint32_t smem_u32(const void* p) {
    uint32_t a;
    asm("{ .reg .u64 t; cvta.to.shared.u64 t, %1; cvt.u32.u64 %0, t; }" : "=r"(a) : "l"(p));
    return a;
}
__device__ __forceinline__ void cp16(uint32_t d, const void* s) {
    asm volatile("cp.async.cg.shared.global [%0],[%1],16;" :: "r"(d), "l"(s));
}
__device__ __forceinline__ void cp16z(uint32_t d, const void* s, unsigned sz) {
    asm volatile("cp.async.cg.shared.global [%0],[%1],16,%2;" :: "r"(d), "l"(s), "r"(sz));
}
__device__ __forceinline__ void cp_commit() { asm volatile("cp.async.commit_group;"); }
template <int N>
__device__ __forceinline__ void cp_wait() {
    asm volatile("cp.async.wait_group %0;" :: "n"(N) : "memory");
}

// ---------------- HMMA GEMM (cp.async 2-stage, fp16): C = A@B^T + bias ----
// MODE 0: fp32 C.  MODE 1: q epilogue (rope+scale -> g_qhl).  MODE 2: kv split -> g_khl/g_v16.
#define LDPAD 40
#define G_PLANE_B (128 * LDPAD * 2)
#define G_STAGE_B (2 * G_PLANE_B)
#define G_SMEM_B  (2 * G_STAGE_B)   // 40960

template<int MODE>
__global__ __launch_bounds__(256, 2) void gemm_hmma(
    const __half* __restrict__ A,
    const __half* __restrict__ B,
    const float* __restrict__ bias, float* __restrict__ C,
    int M, int N, int K,
    const float* __restrict__ cosv, const float* __restrict__ sinv)
{
    extern __shared__ char smraw[];
    const uint32_t sbase = smem_u32(smraw);

    const int tid  = threadIdx.x;
    const int lane = tid & 31;
    const int wid  = tid >> 5;
    const int brow = blockIdx.y * 128;
    const int bcol = blockIdx.x * 128;

    const int lc = tid & 3;
    const int lr = tid >> 2;

    const int wm = (wid & 3) * 32;
    const int wn = (wid >> 2) * 64;

    float acc[2][8][4];
#pragma unroll
    for (int mi = 0; mi < 2; mi++)
#pragma unroll
        for (int ni = 0; ni < 8; ni++)
#pragma unroll
            for (int e = 0; e < 4; e++) acc[mi][ni][e] = 0.f;

    const uint32_t rowoff0 = (uint32_t)(lr * LDPAD + lc * 8) * 2;
    const uint32_t rowoff1 = (uint32_t)((lr + 64) * LDPAD + lc * 8) * 2;

    const int arow0 = brow + lr, arow1 = brow + lr + 64;
    const int ncol0 = bcol + lr, ncol1 = bcol + lr + 64;
    const int nc0 = ncol0 < N ? ncol0 : 0;
    const int nc1 = ncol1 < N ? ncol1 : 0;
    const unsigned bz0 = ncol0 < N ? 16u : 0u;
    const unsigned bz1 = ncol1 < N ? 16u : 0u;

    const int nch = K / 32;

    auto stage_load = [&](int c, int s) {
        const int kk = c * 32 + lc * 8;
        const uint32_t as = sbase + (uint32_t)s * G_STAGE_B;
        const uint32_t bs = as + G_PLANE_B;
        cp16(as + rowoff0, A + (size_t)arow0 * K + kk);
        cp16(as + rowoff1, A + (size_t)arow1 * K + kk);
        cp16z(bs + rowoff0, B + (size_t)nc0 * K + kk, bz0);
        cp16z(bs + rowoff1, B + (size_t)nc1 * K + kk, bz1);
        cp_commit();
    };

    stage_load(0, 0);
    if (nch > 1) stage_load(1, 1);

    for (int c = 0; c < nch; c++) {
        const int s = c & 1;
        cp_wait<1>();
        __syncthreads();

        const uint32_t aS = sbase + (uint32_t)s * G_STAGE_B;
        const uint32_t bS = aS + G_PLANE_B;

#pragma unroll
        for (int ks = 0; ks < 2; ks++) {
            const int kc = ks * 16;
            uint32_t a_h[2][4];
#pragma unroll
            for (int mi = 0; mi < 2; mi++) {
                uint32_t addr = aS + ((wm + mi*16 + (lane & 15)) * LDPAD + kc + (lane >> 4) * 8) * 2;
                ldsm4(a_h[mi], addr);
            }
            uint32_t b_h[4][4];
#pragma unroll
            for (int np = 0; np < 4; np++) {
                uint32_t baddr = bS + ((wn + np*16 + (lane & 15)) * LDPAD + kc + (lane >> 4) * 8) * 2;
                ldsm4(b_h[np], baddr);
            }
#pragma unroll
            for (int np = 0; np < 4; np++) {
#pragma unroll
                for (int hf = 0; hf < 2; hf++) {
                    const int ni = np*2 + hf;
#pragma unroll
                    for (int mi = 0; mi < 2; mi++) {
                        mma16816b(acc[mi][ni], a_h[mi], b_h[np][hf], b_h[np][hf+2]);
                    }
                }
            }
        }
        __syncthreads();
        if (c + 2 < nch) stage_load(c + 2, s);
    }

    // ---------------- epilogues ----------------
#pragma unroll
    for (int mi = 0; mi < 2; mi++) {
        int r0 = brow + wm + mi*16 + (lane >> 2);
        int bq = r0 >> 11;          // batch
        int tq = r0 & (TT - 1);     // time (rows r0 and r0+8 same batch)
#pragma unroll
        for (int ni = 0; ni < 8; ni++) {
            int c0 = bcol + wn + ni*8 + (lane & 3) * 2;
            if (MODE == 0) {
                if (c0 < N) {
                    float b0 = bias[c0], b1 = bias[c0+1];
                    C[(size_t)r0 * N + c0]       = acc[mi][ni][0] + b0;
                    C[(size_t)r0 * N + c0 + 1]   = acc[mi][ni][1] + b1;
                    C[(size_t)(r0+8) * N + c0]   = acc[mi][ni][2] + b0;
                    C[(size_t)(r0+8) * N + c0+1] = acc[mi][ni][3] + b1;
                }
            } else if (MODE == 1) {
                // q: rope + scale, write fp16 [b,h,t,192]
                int h = c0 / QKD;
                int d = c0 - h * QKD;
                float b0 = bias[c0], b1 = bias[c0+1];
                float v0 = acc[mi][ni][0] + b0, v1 = acc[mi][ni][1] + b1; // row r0
                float w0 = acc[mi][ni][2] + b0, w1 = acc[mi][ni][3] + b1; // row r0+8
                if (d < NOPE) {
                    v0 *= SCALE_F; v1 *= SCALE_F; w0 *= SCALE_F; w1 *= SCALE_F;
                } else {
                    int pi = (d - NOPE) >> 1;
                    float ca = cosv[tq*32 + pi],     sa = sinv[tq*32 + pi];
                    float cb = cosv[(tq+8)*32 + pi], sb = sinv[(tq+8)*32 + pi];
                    float t0 = (v0*ca - v1*sa) * SCALE_F;
                    float t1 = (v0*sa + v1*ca) * SCALE_F;
                    v0 = t0; v1 = t1;
                    t0 = (w0*cb - w1*sb) * SCALE_F;
                    t1 = (w0*sb + w1*cb) * SCALE_F;
                    w0 = t0; w1 = t1;
                }
                size_t base = (((size_t)bq*HH + h)*TT + tq)*QKD + d;
                *(__half2*)&g_qhl[base]           = __floats2half2_rn(v0, v1);
                *(__half2*)&g_qhl[base + 8*QKD]   = __floats2half2_rn(w0, w1);
            } else {
                // kv: split k_nope -> g_khl [b,h,t,192], v -> g_v16 [bt,h,128]
                int h  = c0 >> 8;
                int dd = c0 & 255;
                float b0 = bias[c0], b1 = bias[c0+1];
                float v0 = acc[mi][ni][0] + b0, v1 = acc[mi][ni][1] + b1;
                float w0 = acc[mi][ni][2] + b0, w1 = acc[mi][ni][3] + b1;
                if (dd < NOPE) {
                    size_t base = (((size_t)bq*HH + h)*TT + tq)*QKD + dd;
                    *(__half2*)&g_khl[base]         = __floats2half2_rn(v0, v1);
                    *(__half2*)&g_khl[base + 8*QKD] = __floats2half2_rn(w0, w1);
                } else {
                    size_t base = ((size_t)r0*HH + h)*VDIM + (dd - NOPE);
                    *(__half2*)&g_v16[base]               = __floats2half2_rn(v0, v1);
                    *(__half2*)&g_v16[base + 8*HH*VDIM]   = __floats2half2_rn(w0, w1);
                }
            }
        }
    }
}

// ---------------- kv_a post: rms_norm -> g_kvnh (fp16), k_rope -> g_khl (all heads) ----
__global__ __launch_bounds__(128) void kva_post_kernel(const float* __restrict__ cosv,
                                                       const float* __restrict__ sinv)
{
    __shared__ float red[4];
    __shared__ float kr[64];
    const int bt = blockIdx.x;
    const int b  = bt >> 11;
    const int t  = bt & (TT - 1);
    const float* a = g_KVA + (size_t)bt * (KVR + ROPE);
    const int tid = threadIdx.x;

    float ss = 0.f;
    for (int d = tid; d < KVR; d += 128) { float v = a[d]; ss += v * v; }
#pragma unroll
    for (int off = 16; off; off >>= 1) ss += __shfl_xor_sync(0xffffffffu, ss, off);
    if ((tid & 31) == 0) red[tid >> 5] = ss;

    if (tid < 32) {
        int i = tid;
        float c = cosv[t*32 + i];
        float s = sinv[t*32 + i];
        float xr = a[KVR + 2*i];
        float xi = a[KVR + 2*i + 1];
        kr[2*i]     = xr*c - xi*s;
        kr[2*i + 1] = xr*s + xi*c;
    }
    __syncthreads();
    float total = red[0] + red[1] + red[2] + red[3];
    float r = rsqrtf(total * (1.0f / KVR) + 1e-6f);

    __half* o = g_kvnh + (size_t)bt * KVR;
    for (int d = tid; d < KVR; d += 128) o[d] = __float2half_rn(a[d] * r);

    // write rope section of K for all heads
    for (int idx = tid; idx < HH * ROPE; idx += 128) {
        int h  = idx >> 6;
        int i2 = idx & 63;
        g_khl[(((size_t)b*HH + h)*TT + t)*QKD + NOPE + i2] = __float2half_rn(kr[i2]);
    }
}

// ---------------- build V transposed [b,h,d,t] from fp16 g_v16 ----------------
__global__ void build_v_hl()
{
    __shared__ unsigned short tile[32][34];
    const int bh = blockIdx.z;
    const int b = bh / HH, h = bh % HH;
    const int t0 = blockIdx.x * 32;
    const int d0 = blockIdx.y * 32;
    const int tx = threadIdx.x, ty = threadIdx.y;

#pragma unroll
    for (int k = 0; k < 4; k++) {
        int t = t0 + ty + k*8;
        tile[ty + k*8][tx] =
            *(const unsigned short*)&g_v16[((size_t)(b*TT + t)*HH + h)*VDIM + d0 + tx];
    }
    __syncthreads();
#pragma unroll
    for (int k = 0; k < 4; k++) {
        int d = d0 + ty + k*8;
        *(unsigned short*)&g_vhl[((size_t)bh*VDIM + d)*TT + t0 + tx] = tile[tx][ty + k*8];
    }
}

// ---------------- HMMA flash attention (fp16, cp.async double-buffered K/V) ------
#define QS_STRIDE 200
#define VS_STRIDE 72
#define SM_Q_ELEMS (128*QS_STRIDE)
#define SM_K_ELEMS (64*QS_STRIDE)
#define SM_V_ELEMS (128*VS_STRIDE)
#define KV_STAGE_ELEMS (SM_K_ELEMS + SM_V_ELEMS)
#define ATT_SMEM_B ((SM_Q_ELEMS + 2*KV_STAGE_ELEMS) * 2)

__global__ __launch_bounds__(256, 1) void attn_hmma()
{
    extern __shared__ __half smb[];
    __half* qs = smb;

    const int b = blockIdx.z, h = blockIdx.y;
    const int qbase = blockIdx.x * 128;
    const int tid = threadIdx.x, lane = tid & 31, w = tid >> 5;
    const size_t bh = (size_t)b * HH + h;

    {
        const __half* qg = g_qhl + (bh*TT + qbase)*QKD;
        for (int i = tid; i < 128*24; i += 256) {
            int r = i / 24, c = i % 24;
            *(uint4*)&qs[r*QS_STRIDE + c*8] = *(const uint4*)&qg[(size_t)r*QKD + c*8];
        }
    }

    const int g  = lane >> 2;
    const int qc = (lane & 3) * 2;
    const int qr0 = qbase + w*16 + g;

    float m0 = -1e30f, m1 = -1e30f, l0 = 0.f, l1 = 0.f;
    float o[16][4];
#pragma unroll
    for (int nv = 0; nv < 16; nv++)
#pragma unroll
        for (int e = 0; e < 4; e++) o[nv][e] = 0.f;

    const uint32_t sQ  = smem_u32(qs);
    const uint32_t sKV = sQ + SM_Q_ELEMS * 2;   // two stages follow

    const int ntiles = qbase/64 + 2;

    auto stage = [&](int kb) {
        const int s = kb & 1;
        const uint32_t ksb = sKV + (uint32_t)s * KV_STAGE_ELEMS * 2;
        const uint32_t vsb = ksb + SM_K_ELEMS * 2;
        const __half* kg = g_khl + (bh*TT + kb*64)*QKD;
        const __half* vg = g_vhl + bh*VDIM*TT + kb*64;
        for (int i = tid; i < 64*24; i += 256) {
            int r = i / 24, c = i % 24;
            cp16(ksb + (r*QS_STRIDE + c*8)*2, kg + (size_t)r*QKD + c*8);
        }
        for (int i = tid; i < 128*8; i += 256) {
            int d = i / 8, c = i % 8;
            cp16(vsb + (d*VS_STRIDE + c*8)*2, vg + (size_t)d*TT + c*8);
        }
        cp_commit();
    };

    stage(0);

    for (int kb = 0; kb < ntiles; kb++) {
        const int kbase = kb * 64;
        if (kb + 1 < ntiles) { stage(kb + 1); cp_wait<1>(); }
        else                 { cp_wait<0>(); }
        __syncthreads();

        const uint32_t sK = sKV + (uint32_t)(kb & 1) * KV_STAGE_ELEMS * 2;
        const uint32_t sV = sK + SM_K_ELEMS * 2;

        float s[8][4];
#pragma unroll
        for (int ni = 0; ni < 8; ni++)
#pragma unroll
            for (int e = 0; e < 4; e++) s[ni][e] = 0.f;

#pragma unroll
        for (int kp = 0; kp < 6; kp++) {
            uint32_t ah0[4], ah1[4];
            uint32_t ab = sQ + ((w*16 + (lane & 15))*QS_STRIDE + kp*32 + (lane >> 4)*8) * 2;
            ldsm4(ah0, ab);
            ldsm4(ah1, ab + 32);
#pragma unroll
            for (int ni = 0; ni < 8; ni++) {
                uint32_t bb = sK + ((ni*8 + (lane & 7))*QS_STRIDE + kp*32 + (lane >> 3)*8) * 2;
                uint32_t bh4[4];
                ldsm4(bh4, bb);
                mma16816(s[ni], ah0, bh4);
                mma16816(s[ni], ah1, bh4 + 2);
            }
        }

        if (kbase + 63 > qr0) {
#pragma unroll
            for (int ni = 0; ni < 8; ni++) {
                int col = kbase + ni*8 + qc;
                if (col     > qr0)     s[ni][0] = -1e30f;
                if (col + 1 > qr0)     s[ni][1] = -1e30f;
                if (col     > qr0 + 8) s[ni][2] = -1e30f;
                if (col + 1 > qr0 + 8) s[ni][3] = -1e30f;
            }
        }

        float rm0 = -1e30f, rm1 = -1e30f;
#pragma unroll
        for (int ni = 0; ni < 8; ni++) {
            rm0 = fmaxf(rm0, fmaxf(s[ni][0], s[ni][1]));
            rm1 = fmaxf(rm1, fmaxf(s[ni][2], s[ni][3]));
        }
        rm0 = fmaxf(rm0, __shfl_xor_sync(0xffffffffu, rm0, 1));
        rm0 = fmaxf(rm0, __shfl_xor_sync(0xffffffffu, rm0, 2));
        rm1 = fmaxf(rm1, __shfl_xor_sync(0xffffffffu, rm1, 1));
        rm1 = fmaxf(rm1, __shfl_xor_sync(0xffffffffu, rm1, 2));
        float nm0 = fmaxf(m0, rm0), nm1 = fmaxf(m1, rm1);
        float c0 = __expf(m0 - nm0), c1 = __expf(m1 - nm1);

        float rs0 = 0.f, rs1 = 0.f;
#pragma unroll
        for (int ni = 0; ni < 8; ni++) {
            s[ni][0] = __expf(s[ni][0] - nm0); rs0 += s[ni][0];
            s[ni][1] = __expf(s[ni][1] - nm0); rs0 += s[ni][1];
            s[ni][2] = __expf(s[ni][2] - nm1); rs1 += s[ni][2];
            s[ni][3] = __expf(s[ni][3] - nm1); rs1 += s[ni][3];
        }
        rs0 += __shfl_xor_sync(0xffffffffu, rs0, 1);
        rs0 += __shfl_xor_sync(0xffffffffu, rs0, 2);
        rs1 += __shfl_xor_sync(0xffffffffu, rs1, 1);
        rs1 += __shfl_xor_sync(0xffffffffu, rs1, 2);
        l0 = l0 * c0 + rs0;
        l1 = l1 * c1 + rs1;
        m0 = nm0; m1 = nm1;
#pragma unroll
        for (int nv = 0; nv < 16; nv++) {
            o[nv][0] *= c0; o[nv][1] *= c0;
            o[nv][2] *= c1; o[nv][3] *= c1;
        }

#pragma unroll
        for (int kp = 0; kp < 2; kp++) {
            uint32_t ph[2][4];
#pragma unroll
            for (int ss2 = 0; ss2 < 2; ss2++) {
                int n0 = kp*4 + ss2*2;
#pragma unroll
                for (int half = 0; half < 2; half++) {
                    int nt = n0 + half;
                    ph[ss2][half*2 + 0] = pack_h2(__float2half_rn(s[nt][0]), __float2half_rn(s[nt][1]));
                    ph[ss2][half*2 + 1] = pack_h2(__float2half_rn(s[nt][2]), __float2half_rn(s[nt][3]));
                }
            }
#pragma unroll
            for (int nv = 0; nv < 16; nv++) {
                uint32_t vb = sV + ((nv*8 + (lane & 7))*VS_STRIDE + kp*32 + (lane >> 3)*8) * 2;
                uint32_t vh4[4];
                ldsm4(vh4, vb);
                mma16816(o[nv], ph[0], vh4);
                mma16816(o[nv], ph[1], vh4 + 2);
            }
        }
        __syncthreads();
    }

    // epilogue: write g_atth fp16 directly
    float inv0 = 1.f / l0, inv1 = 1.f / l1;
    __half* op0 = g_atth + (size_t)(b*TT + qr0) * (HH*VDIM) + h*VDIM;
    __half* op1 = op0 + (size_t)8 * (HH*VDIM);
#pragma unroll
    for (int nv = 0; nv < 16; nv++) {
        int d = nv*8 + qc;
        op0[d]     = __float2half_rn(o[nv][0] * inv0);
        op0[d + 1] = __float2half_rn(o[nv][1] * inv0);
        op1[d]     = __float2half_rn(o[nv][2] * inv1);
        op1[d + 1] = __float2half_rn(o[nv][3] * inv1);
    }
}

// ---------------- launch ----------------
extern "C" void kernel_launch(void* const* d_in, const int* in_sizes, int n_in,
                              void* d_out, int out_size)
{
    const float* x       = (const float*)d_in[0];
    const float* wq_w    = (const float*)d_in[1];
    const float* wq_b    = (const float*)d_in[2];
    const float* wkv_a_w = (const float*)d_in[3];
    const float* wkv_a_b = (const float*)d_in[4];
    const float* wkv_b_w = (const float*)d_in[5];
    const float* wkv_b_b = (const float*)d_in[6];
    const float* wo_w    = (const float*)d_in[7];
    const float* wo_b    = (const float*)d_in[8];
    const float* cosv    = (const float*)d_in[9];
    const float* sinv    = (const float*)d_in[10];
    float* out = (float*)d_out;

    float* KVAp;
    cudaGetSymbolAddress((void**)&KVAp, g_KVA);

    __half *xh, *wqh, *wkvah, *wkvbh, *woh, *kvnh, *atth;
    cudaGetSymbolAddress((void**)&xh,    g_xh);
    cudaGetSymbolAddress((void**)&wqh,   g_wqh);
    cudaGetSymbolAddress((void**)&wkvah, g_wkvah);
    cudaGetSymbolAddress((void**)&wkvbh, g_wkvbh);
    cudaGetSymbolAddress((void**)&woh,   g_woh);
    cudaGetSymbolAddress((void**)&kvnh,  g_kvnh);
    cudaGetSymbolAddress((void**)&atth,  g_atth);

    const size_t nX    = (size_t)MTOT * DIM;
    const size_t nWQ   = (size_t)(HH*QKD) * DIM;
    const size_t nWKVA = (size_t)(KVR+ROPE) * DIM;
    const size_t nWKVB = (size_t)(HH*(NOPE+VDIM)) * KVR;
    const size_t nWO   = (size_t)DIM * (HH*VDIM);

    cudaFuncSetAttribute(gemm_hmma<0>, cudaFuncAttributeMaxDynamicSharedMemorySize, G_SMEM_B);
    cudaFuncSetAttribute(gemm_hmma<1>, cudaFuncAttributeMaxDynamicSharedMemorySize, G_SMEM_B);
    cudaFuncSetAttribute(gemm_hmma<2>, cudaFuncAttributeMaxDynamicSharedMemorySize, G_SMEM_B);

    // conversions (all hi-only fp16)
    conv_hi<<<(unsigned)((nX + 255) / 256), 256>>>(x, xh, nX);
    conv_hi<<<(unsigned)((nWQ + 255) / 256), 256>>>(wq_w, wqh, nWQ);
    conv_hi<<<(unsigned)((nWKVA + 255) / 256), 256>>>(wkv_a_w, wkvah, nWKVA);
    conv_hi<<<(unsigned)((nWKVB + 255) / 256), 256>>>(wkv_b_w, wkvbh, nWKVB);
    conv_hi<<<(unsigned)((nWO + 255) / 256), 256>>>(wo_w, woh, nWO);

    // 1) q = x @ wq^T + b  (rope+scale fused, -> g_qhl fp16)
    gemm_hmma<1><<<dim3(3072/128, MTOT/128), 256, G_SMEM_B>>>(
        xh, wqh, wq_b, nullptr, MTOT, HH*QKD, DIM, cosv, sinv);
    // 2) kv_a = x @ wkv_a^T + b  (fp32 -> g_KVA)
    gemm_hmma<0><<<dim3((KVR+ROPE+127)/128, MTOT/128), 256, G_SMEM_B>>>(
        xh, wkvah, wkv_a_b, KVAp, MTOT, KVR+ROPE, DIM, nullptr, nullptr);
    // 3) rms norm (-> g_kvnh fp16) + k rope (-> g_khl rope section, all heads)
    kva_post_kernel<<<MTOT, 128>>>(cosv, sinv);
    // 4) kv = norm @ wkv_b^T + b  (split fused: k_nope -> g_khl, v -> g_v16)
    gemm_hmma<2><<<dim3(HH*(NOPE+VDIM)/128, MTOT/128), 256, G_SMEM_B>>>(
        kvnh, wkvbh, wkv_b_b, nullptr, MTOT, HH*(NOPE+VDIM), KVR, nullptr, nullptr);
    // 5) transpose V -> g_vhl [b,h,d,t]
    build_v_hl<<<dim3(TT/32, VDIM/32, BB*HH), dim3(32, 8)>>>();
    // 6) flash attention (fp16 HMMA, double-buffered staging) -> g_atth
    cudaFuncSetAttribute(attn_hmma, cudaFuncAttributeMaxDynamicSharedMemorySize, ATT_SMEM_B);
    attn_hmma<<<dim3(TT/128, HH, BB), 256, ATT_SMEM_B>>>();
    // 7) out = att @ wo^T + b
    gemm_hmma<0><<<dim3(DIM/128, MTOT/128), 256, G_SMEM_B>>>(
        atth, woh, wo_b, out, MTOT, DIM, HH*VDIM, nullptr, nullptr);
}